// round 10
// baseline (speedup 1.0000x reference)
#include <cuda_runtime.h>

#define HPX 512
#define WPX 512
#define HW  (HPX*WPX)           // 262144 = 2^18
#define HOB 518                 // r2 output side (512 + 2*4 - 2)
#define HW2 (HOB*HOB)           // 268324

typedef unsigned long long u64;

// ---------------- device scratch (no cudaMalloc allowed) ----------------
__device__ float g_t1raw[32*HW];
__device__ float g_t2raw[32*HW];
__device__ float g_graw [128*HW];
__device__ float g_r1raw[32*HW];
__device__ float g_r2raw[4*HW2];
// splatted weights for v9 convs: u64 {w,w}, layout [cin][k9][cout32]
__device__ __align__(16) float g_wt_e1[4*9*32*2];
__device__ __align__(16) float g_wt_e2[32*9*32*2];
__device__ __align__(16) float g_wt_g [4*64*9*32*2];
__device__ __align__(16) float g_wt_r1[32*9*32*2];
__device__ __align__(16) float g_wt_r2[32*9*4];      // v8 layout [cin][k][cout4]
__device__ float  g_stats[512];    // e1:[0,64) e2:[64,128) gates:[128,384) r1:[384,448) r2:[448,456)
__device__ float2 g_params[256];   // e1:0 e2:32 gates:64 r1:192 r2:224   (scale, bias)

// ---------------- f32x2 / cp.async helpers ----------------
__device__ __forceinline__ u64 pack2(float x) {
    unsigned u = __float_as_uint(x);
    u64 r;
    asm("mov.b64 %0, {%1, %2};" : "=l"(r) : "r"(u), "r"(u));
    return r;
}
__device__ __forceinline__ u64 ffma2(u64 a, u64 b, u64 c) {
    u64 d;
    asm("fma.rn.f32x2 %0, %1, %2, %3;" : "=l"(d) : "l"(a), "l"(b), "l"(c));
    return d;
}
__device__ __forceinline__ void unpack2(u64 v, float& lo, float& hi) {
    unsigned a, b;
    asm("mov.b64 {%0, %1}, %2;" : "=r"(a), "=r"(b) : "l"(v));
    lo = __uint_as_float(a); hi = __uint_as_float(b);
}
__device__ __forceinline__ float sigmoidf_(float x) { return 1.f / (1.f + expf(-x)); }

__device__ __forceinline__ void cp_async4(unsigned dst, const void* src, bool pred) {
    int bytes = pred ? 4 : 0;
    asm volatile("cp.async.ca.shared.global [%0], [%1], 4, %2;"
                 :: "r"(dst), "l"(src), "r"(bytes));
}
__device__ __forceinline__ void cp_async16(unsigned dst, const void* src) {
    asm volatile("cp.async.cg.shared.global [%0], [%1], 16;" :: "r"(dst), "l"(src));
}
__device__ __forceinline__ void cp_commit() {
    asm volatile("cp.async.commit_group;");
}
template<int N>
__device__ __forceinline__ void cp_wait() {
    asm volatile("cp.async.wait_group %0;" :: "n"(N));
}

// ---- weight prep: splat {w,w} u64 [cin][k][cout] for v9 convs; r2 plain; stats zero ----
__global__ void prep_weights(const float* __restrict__ we1, const float* __restrict__ we2,
                             const float* __restrict__ wf,  const float* __restrict__ wi,
                             const float* __restrict__ wc,  const float* __restrict__ wo,
                             const float* __restrict__ wr1, const float* __restrict__ wr2)
{
    int idx = blockIdx.x * 256 + threadIdx.x;
    if (idx < 512) g_stats[idx] = 0.f;
    // e1: 1152 u64
    if (idx < 1152) {
        int cout = idx % 32, k = (idx / 32) % 9, cin = idx / 288;
        float w = we1[cout*36 + cin*9 + k];
        g_wt_e1[2*idx] = w; g_wt_e1[2*idx+1] = w;
        return;
    }
    idx -= 1152;
    // e2: 9216 u64
    if (idx < 9216) {
        int cout = idx % 32, k = (idx / 32) % 9, cin = idx / 288;
        float w = we2[cout*288 + cin*9 + k];
        g_wt_e2[2*idx] = w; g_wt_e2[2*idx+1] = w;
        return;
    }
    idx -= 9216;
    // gates: 4*18432 u64
    if (idx < 73728) {
        int cout = idx % 32, k = (idx / 32) % 9, cin = (idx / 288) % 64, z = idx / 18432;
        const float* src = (z == 0) ? wf : (z == 1) ? wi : (z == 2) ? wc : wo;
        float w = src[cout*576 + cin*9 + k];
        g_wt_g[2*idx] = w; g_wt_g[2*idx+1] = w;
        return;
    }
    idx -= 73728;
    // r1: 9216 u64
    if (idx < 9216) {
        int cout = idx % 32, k = (idx / 32) % 9, cin = idx / 288;
        float w = wr1[cout*288 + cin*9 + k];
        g_wt_r1[2*idx] = w; g_wt_r1[2*idx+1] = w;
        return;
    }
    idx -= 9216;
    // r2: 1152 floats, [cin][k][cout4] (v8 layout), couts padded to 4
    if (idx < 1152) {
        int cout = idx % 4, t = idx / 4, k = t % 9, cin = t / 9;
        g_wt_r2[idx] = (cout < 3) ? wr2[cout*288 + cin*9 + k] : 0.f;
        return;
    }
}

// stats (sum, sumsq) -> params (scale, bias)
__global__ void make_params(const float* __restrict__ stats, float2* __restrict__ params,
                            int nch, float invn)
{
    int c = threadIdx.x;
    if (c >= nch) return;
    float m   = stats[2*c] * invn;
    float var = stats[2*c+1] * invn - m * m;
    float sc  = rsqrtf(var + 1e-5f);
    params[c] = make_float2(sc, -m * sc);
}

// ---------------- 3x3 conv v9: interleaved pixel pairs + splatted weights (COUT=32) ----------
// 256 threads = 4 groups x 64 (tx 0..15, ty 0..3). Group g computes couts [8g, 8g+8).
// Thread covers 2 pixel-pairs {px(tx), px(tx+16)} at rows (gy+ty) and (gy+ty+4).
// Tile smem: rows 10 x 18 u64 pairs; pair p = {col p, col p+16} (cols 16,17 duplicated).
// Weights: splatted u64 {w,w}, [cin][k][cout32]; per (k, group): 4 LDS.128 = 8 couts.
template<int CIN, int CHUNK>
__global__ void __launch_bounds__(256, 4)
conv3x3_v9(const float* __restrict__ inA, const float* __restrict__ inB, int csplit,
           const float2* __restrict__ prmA, const float2* __restrict__ prmB,
           int reluA, int reluB,
           const float* __restrict__ wt, float* __restrict__ out, float* __restrict__ statsOut,
           int H, int W, int pad, int HO, int WO)
{
    constexpr int TW = 32;
    constexpr int ROWP = 18;                      // u64 pairs per row
    constexpr int TSZF = 10 * 36;                 // 360 floats per tile
    constexpr int NCH = CIN / CHUNK;
    constexpr int WCHF = CHUNK * 9 * 32 * 2;      // splatted weight floats per chunk
    extern __shared__ float smem[];
    float* ws   = smem;                           // 2 * WCHF
    float* tile = smem + 2*WCHF;                  // 2 * CHUNK*TSZF
    __shared__ float sstat[64];

    const int tid   = threadIdx.x;
    const int group = tid >> 6;
    const int gtid  = tid & 63;
    const int tx    = gtid & 15;
    const int ty    = gtid >> 4;                  // 0..3
    if (tid < 64) sstat[tid] = 0.f;

    const int gx = blockIdx.x * TW, gy = blockIdx.y * 8;
    const int oy0 = gy + ty, oy1 = gy + ty + 4;
    const int ox0 = gx + tx, ox1 = ox0 + 16;
    const float* wsrc = wt + (size_t)blockIdx.z * (CIN*9*32*2);

    const unsigned ws_s   = (unsigned)__cvta_generic_to_shared(ws);
    const unsigned tile_s = (unsigned)__cvta_generic_to_shared(tile);
    const bool needT = (prmA != nullptr && csplit > 0) || (prmB != nullptr && csplit < CIN);

    u64 acc0[8], acc1[8];
#pragma unroll
    for (int c = 0; c < 8; c++) { acc0[c] = 0ull; acc1[c] = 0ull; }

    auto prefetch = [&](int ci, int buf) {
        const float* wc = wsrc + (size_t)ci * WCHF;
        unsigned wd = ws_s + buf * WCHF * 4;
        for (int i = tid; i < WCHF/4; i += 256)
            cp_async16(wd + i*16, wc + i*4);
        unsigned td = tile_s + buf * CHUNK*TSZF*4;
        for (int cc = 0; cc < CHUNK; ++cc) {
            int cin = ci*CHUNK + cc;
            bool isA = cin < csplit;
            const float* ip = isA ? (inA + (size_t)cin * H * W)
                                  : (inB + (size_t)(cin - csplit) * H * W);
            for (int i = tid; i < TSZF; i += 256) {
                int r = i / 36, rem = i % 36;
                int p = rem >> 1, h = rem & 1;
                int iy = gy - pad + r, ix = gx - pad + p + 16*h;
                bool inb = iy >= 0 && iy < H && ix >= 0 && ix < W;
                cp_async4(td + (cc*TSZF + i)*4, inb ? (ip + (size_t)iy*W + ix) : ip, inb);
            }
        }
        cp_commit();
    };

    auto transform = [&](int ci, int buf) {
        float* tb = tile + buf * CHUNK*TSZF;
        for (int i = tid; i < CHUNK*TSZF; i += 256) {
            int cc = i / TSZF, e = i % TSZF;
            int cin = ci*CHUNK + cc;
            bool isA = cin < csplit;
            const float2* prm = isA ? prmA : prmB;
            if (!prm) continue;
            int rl = isA ? reluA : reluB;
            int r = e / 36, rem = e % 36;
            int p = rem >> 1, h = rem & 1;
            int iy = gy - pad + r, ix = gx - pad + p + 16*h;
            bool inb = iy >= 0 && iy < H && ix >= 0 && ix < W;
            float2 pr = __ldg(&prm[isA ? cin : (cin - csplit)]);
            float v = inb ? (tb[i] * pr.x + pr.y) : 0.f;
            if (rl) v = fmaxf(v, 0.f);
            tb[i] = v;
        }
    };

    auto compute = [&](int buf) {
        const float* tb0 = tile + buf * CHUNK*TSZF;
        const u64* wb = (const u64*)(ws + buf * WCHF);
#pragma unroll
        for (int cc = 0; cc < CHUNK; ++cc) {
            const u64* tbu = (const u64*)(tb0 + cc * TSZF);
            const u64* wk  = wb + cc * 288 + group * 8;
#pragma unroll
            for (int ky = 0; ky < 3; ky++) {
#pragma unroll
                for (int kx = 0; kx < 3; kx++) {
                    u64 pa = tbu[(ty + ky) * ROWP + tx + kx];
                    u64 pb = tbu[(ty + 4 + ky) * ROWP + tx + kx];
                    const ulonglong2* w4 = (const ulonglong2*)(wk + (ky*3 + kx) * 32);
#pragma unroll
                    for (int j = 0; j < 4; j++) {
                        ulonglong2 w = w4[j];
                        acc0[2*j  ] = ffma2(pa, w.x, acc0[2*j  ]);
                        acc1[2*j  ] = ffma2(pb, w.x, acc1[2*j  ]);
                        acc0[2*j+1] = ffma2(pa, w.y, acc0[2*j+1]);
                        acc1[2*j+1] = ffma2(pb, w.y, acc1[2*j+1]);
                    }
                }
            }
        }
    };

    prefetch(0, 0);
    for (int ci = 0; ci < NCH; ++ci) {
        int cur = ci & 1;
        if (ci + 1 < NCH) {
            prefetch(ci + 1, 1 - cur);
            cp_wait<1>();
        } else {
            cp_wait<0>();
        }
        __syncthreads();
        if (needT) { transform(ci, cur); __syncthreads(); }
        compute(cur);
        __syncthreads();
    }

    // ---- epilogue: store + fused per-channel (sum, sumsq) ----
    float* ob = out + (size_t)blockIdx.z * 32 * HO * WO;
    float* so = statsOut + blockIdx.z * 64;
    const bool vy0 = oy0 < HO, vy1 = oy1 < HO;
    const bool vx0 = ox0 < WO, vx1 = ox1 < WO;
#pragma unroll
    for (int c = 0; c < 8; c++) {
        int co = group * 8 + c;
        float a0, a1, b0, b1;
        unpack2(acc0[c], a0, a1);   // row oy0: px ox0, ox1
        unpack2(acc1[c], b0, b1);   // row oy1
        float* pc = ob + (size_t)co * HO * WO;
        if (vy0) {
            if (vx0) pc[(size_t)oy0 * WO + ox0] = a0;
            if (vx1) pc[(size_t)oy0 * WO + ox1] = a1;
        }
        if (vy1) {
            if (vx0) pc[(size_t)oy1 * WO + ox0] = b0;
            if (vx1) pc[(size_t)oy1 * WO + ox1] = b1;
        }
        float z0 = (vy0 && vx0) ? a0 : 0.f;
        float z1 = (vy0 && vx1) ? a1 : 0.f;
        float z2 = (vy1 && vx0) ? b0 : 0.f;
        float z3 = (vy1 && vx1) ? b1 : 0.f;
        float s = z0 + z1 + z2 + z3;
        float q = z0*z0 + z1*z1 + z2*z2 + z3*z3;
#pragma unroll
        for (int o = 16; o; o >>= 1) {
            s += __shfl_down_sync(0xFFFFFFFFu, s, o);
            q += __shfl_down_sync(0xFFFFFFFFu, q, o);
        }
        if ((tid & 31) == 0) {
            atomicAdd(&sstat[2*co  ], s);
            atomicAdd(&sstat[2*co+1], q);
        }
    }
    __syncthreads();
    if (tid < 64) atomicAdd(&so[tid], sstat[tid]);
}

// ---------------- 3x3 conv v8 (kept for r2: COUT=4) ------------------------------------------
template<int CIN, int COUT, int CHUNK>
__global__ void __launch_bounds__(256, 4)
conv3x3_v8(const float* __restrict__ inA, const float* __restrict__ inB, int csplit,
           const float2* __restrict__ prmA, const float2* __restrict__ prmB,
           int reluA, int reluB,
           const float* __restrict__ wt, float* __restrict__ out, float* __restrict__ statsOut,
           int H, int W, int pad, int HO, int WO)
{
    constexpr int TW = 32, TPW = 36, TPH = 10;
    constexpr int TSZ = TPW * TPH;
    constexpr int NCH = CIN / CHUNK;
    constexpr int WCH = CHUNK * 9 * COUT;
    constexpr int COUTG = COUT / 2;
    constexpr int C2G = COUTG / 2;
    constexpr int C2  = COUT / 2;
    extern __shared__ float smem[];
    float* ws   = smem;
    float* tile = smem + 2*WCH;
    __shared__ float sstat[2*COUT];

    const int tid   = threadIdx.x;
    const int group = tid >> 7;
    const int tx    = tid & 15;
    const int ty    = (tid >> 4) & 7;
    if (tid < 2*COUT) sstat[tid] = 0.f;

    const int gx = blockIdx.x * TW, gy = blockIdx.y * 8;
    const int oy = gy + ty;
    const int ox0 = gx + tx, ox1 = ox0 + 16;
    const float* wsrc = wt + (size_t)blockIdx.z * (CIN*9*COUT);

    const unsigned ws_s   = (unsigned)__cvta_generic_to_shared(ws);
    const unsigned tile_s = (unsigned)__cvta_generic_to_shared(tile);
    const bool needT = (prmA != nullptr && csplit > 0) || (prmB != nullptr && csplit < CIN);

    u64 accA[C2G], accB[C2G];
#pragma unroll
    for (int p = 0; p < C2G; p++) { accA[p] = 0ull; accB[p] = 0ull; }

    auto prefetch = [&](int ci, int buf) {
        const float* wc = wsrc + (size_t)ci * WCH;
        unsigned wd = ws_s + buf * WCH * 4;
        for (int i = tid; i < WCH/4; i += 256)
            cp_async16(wd + i*16, wc + i*4);
        unsigned td = tile_s + buf * CHUNK*TSZ*4;
        for (int cc = 0; cc < CHUNK; ++cc) {
            int cin = ci*CHUNK + cc;
            bool isA = cin < csplit;
            const float* ip = isA ? (inA + (size_t)cin * H * W)
                                  : (inB + (size_t)(cin - csplit) * H * W);
            for (int i = tid; i < TSZ; i += 256) {
                int r = i / TPW, c = i % TPW;
                int iy = gy - pad + r, ix = gx - pad + c;
                bool inb = (c < TW+2) && iy >= 0 && iy < H && ix >= 0 && ix < W;
                cp_async4(td + (cc*TSZ + i)*4, inb ? (ip + (size_t)iy*W + ix) : ip, inb);
            }
        }
        cp_commit();
    };

    auto transform = [&](int ci, int buf) {
        float* tb = tile + buf * CHUNK*TSZ;
        for (int i = tid; i < CHUNK*TSZ; i += 256) {
            int cc = i / TSZ, e = i % TSZ;
            int cin = ci*CHUNK + cc;
            bool isA = cin < csplit;
            const float2* prm = isA ? prmA : prmB;
            if (!prm) continue;
            int rl = isA ? reluA : reluB;
            int r = e / TPW, c = e % TPW;
            int iy = gy - pad + r, ix = gx - pad + c;
            bool inb = (c < TW+2) && iy >= 0 && iy < H && ix >= 0 && ix < W;
            float2 p = __ldg(&prm[isA ? cin : (cin - csplit)]);
            float v = inb ? (tb[i] * p.x + p.y) : 0.f;
            if (rl) v = fmaxf(v, 0.f);
            tb[i] = v;
        }
    };

    auto compute = [&](int buf) {
        const float* tb0 = tile + buf * CHUNK*TSZ + ty * TPW + tx;
        const float* wsb = ws + buf * WCH;
#pragma unroll
        for (int cc = 0; cc < CHUNK; ++cc) {
            const float* tb = tb0 + cc * TSZ;
            const u64* wrow = (const u64*)(wsb + cc * 9 * COUT) + group * C2G;
#pragma unroll
            for (int ky = 0; ky < 3; ky++) {
#pragma unroll
                for (int kx = 0; kx < 3; kx++) {
                    u64 va = pack2(tb[ky*TPW + kx]);
                    u64 vb = pack2(tb[ky*TPW + kx + 16]);
                    if constexpr (C2G >= 2) {
                        const ulonglong2* w4 = (const ulonglong2*)(wrow + (ky*3+kx) * C2);
#pragma unroll
                        for (int p2 = 0; p2 < C2G/2; p2++) {
                            ulonglong2 w = w4[p2];
                            accA[2*p2  ] = ffma2(va, w.x, accA[2*p2  ]);
                            accB[2*p2  ] = ffma2(vb, w.x, accB[2*p2  ]);
                            accA[2*p2+1] = ffma2(va, w.y, accA[2*p2+1]);
                            accB[2*p2+1] = ffma2(vb, w.y, accB[2*p2+1]);
                        }
                    } else {
                        u64 w = wrow[(ky*3+kx) * C2];
                        accA[0] = ffma2(va, w, accA[0]);
                        accB[0] = ffma2(vb, w, accB[0]);
                    }
                }
            }
        }
    };

    prefetch(0, 0);
    for (int ci = 0; ci < NCH; ++ci) {
        int cur = ci & 1;
        if (ci + 1 < NCH) {
            prefetch(ci + 1, 1 - cur);
            cp_wait<1>();
        } else {
            cp_wait<0>();
        }
        __syncthreads();
        if (needT) { transform(ci, cur); __syncthreads(); }
        compute(cur);
        __syncthreads();
    }

    float* ob = out + (size_t)blockIdx.z * COUT * HO * WO;
    float* so = statsOut + blockIdx.z * 2 * COUT;
    const bool vA = (oy < HO) && (ox0 < WO);
    const bool vB = (oy < HO) && (ox1 < WO);
    const size_t row = (size_t)oy * WO;
#pragma unroll
    for (int p = 0; p < C2G; p++) {
        int c0 = group * COUTG + 2*p;
        float a0, a1, b0, b1;
        unpack2(accA[p], a0, a1);
        unpack2(accB[p], b0, b1);
        if (vA) {
            ob[(size_t)(c0  ) * HO * WO + row + ox0] = a0;
            ob[(size_t)(c0+1) * HO * WO + row + ox0] = a1;
        }
        if (vB) {
            ob[(size_t)(c0  ) * HO * WO + row + ox1] = b0;
            ob[(size_t)(c0+1) * HO * WO + row + ox1] = b1;
        }
        float s0 = (vA ? a0 : 0.f) + (vB ? b0 : 0.f);
        float q0 = (vA ? a0*a0 : 0.f) + (vB ? b0*b0 : 0.f);
        float s1 = (vA ? a1 : 0.f) + (vB ? b1 : 0.f);
        float q1 = (vA ? a1*a1 : 0.f) + (vB ? b1*b1 : 0.f);
#pragma unroll
        for (int o = 16; o; o >>= 1) {
            s0 += __shfl_down_sync(0xFFFFFFFFu, s0, o);
            q0 += __shfl_down_sync(0xFFFFFFFFu, q0, o);
            s1 += __shfl_down_sync(0xFFFFFFFFu, s1, o);
            q1 += __shfl_down_sync(0xFFFFFFFFu, q1, o);
        }
        if ((tid & 31) == 0) {
            atomicAdd(&sstat[2*c0  ], s0);
            atomicAdd(&sstat[2*c0+1], q0);
            atomicAdd(&sstat[2*c0+2], s1);
            atomicAdd(&sstat[2*c0+3], q1);
        }
    }
    __syncthreads();
    if (tid < 2*COUT) atomicAdd(&so[tid], sstat[tid]);
}

// ---------------- LSTM elementwise ----------------
__global__ void lstm_kernel(const float* __restrict__ prev_c, const float2* __restrict__ prm,
                            float* __restrict__ out_c, float* __restrict__ out_h)
{
    int idx = blockIdx.x * 256 + threadIdx.x;   // over 32*HW
    int c = idx >> 18;                          // HW = 2^18
    const int CHW = 32 * HW;

    float g[4];
#pragma unroll
    for (int gi = 0; gi < 4; gi++) {
        float2 p = prm[gi*32 + c];
        g[gi] = g_graw[(size_t)gi * CHW + idx] * p.x + p.y;
    }
    float f  = sigmoidf_(g[0]);
    float it = sigmoidf_(g[1]);
    float ct = tanhf(g[2]);
    float ot = sigmoidf_(g[3]);
    float nc = prev_c[idx] * f + it * ct;
    out_c[idx] = nc;
    out_h[idx] = tanhf(nc) * ot;
}

// ---------------- patch gather + per-channel dot ----------------
__global__ void gather_kernel(const int* __restrict__ holes,
                              const float* __restrict__ woil, const float* __restrict__ boil,
                              const float* __restrict__ wwat, const float* __restrict__ bwat,
                              const float* __restrict__ wgas, const float* __restrict__ bgas,
                              const float2* __restrict__ prm,
                              float* __restrict__ res)
{
    int nidx = threadIdx.x;
    if (nidx >= 256) return;
    int hx = holes[2*nidx], hy = holes[2*nidx+1];
    const float* wv[3] = { woil, wwat, wgas };
    float bv[3] = { boil[0], bwat[0], bgas[0] };
    for (int c = 0; c < 3; c++) {
        float2 p = prm[c];
        float s = bv[c];
        for (int i = 0; i < 3; i++)
            for (int j = 0; j < 3; j++) {
                float v = g_r2raw[(size_t)c * HW2 + (size_t)(hx + 3 + i) * HOB + (hy + 3 + j)];
                s += wv[c][i*3+j] * (v * p.x + p.y);
            }
        res[nidx*3 + c] = s;
    }
}

// ---------------- launch ----------------
extern "C" void kernel_launch(void* const* d_in, const int* in_sizes, int n_in,
                              void* d_out, int out_size)
{
    const float* x      = (const float*)d_in[0];
    const float* prev_c = (const float*)d_in[1];
    const float* prev_h = (const float*)d_in[2];
    const int*   holes  = (const int*)d_in[3];
    const float* w_e1   = (const float*)d_in[4];
    const float* w_e2   = (const float*)d_in[5];
    const float* w_f    = (const float*)d_in[6];
    const float* w_i    = (const float*)d_in[7];
    const float* w_c    = (const float*)d_in[8];
    const float* w_o    = (const float*)d_in[9];
    const float* w_r1   = (const float*)d_in[10];
    const float* w_r2   = (const float*)d_in[11];
    const float* w_oil  = (const float*)d_in[12];
    const float* b_oil  = (const float*)d_in[13];
    const float* w_wat  = (const float*)d_in[14];
    const float* b_wat  = (const float*)d_in[15];
    const float* w_gas  = (const float*)d_in[16];
    const float* b_gas  = (const float*)d_in[17];
    float* out = (float*)d_out;

    float *t1raw, *t2raw, *graw, *r1raw, *r2raw;
    float *wt_e1, *wt_e2, *wt_g, *wt_r1, *wt_r2, *stats;
    float2 *params;
    cudaGetSymbolAddress((void**)&t1raw, g_t1raw);
    cudaGetSymbolAddress((void**)&t2raw, g_t2raw);
    cudaGetSymbolAddress((void**)&graw,  g_graw);
    cudaGetSymbolAddress((void**)&r1raw, g_r1raw);
    cudaGetSymbolAddress((void**)&r2raw, g_r2raw);
    cudaGetSymbolAddress((void**)&wt_e1, g_wt_e1);
    cudaGetSymbolAddress((void**)&wt_e2, g_wt_e2);
    cudaGetSymbolAddress((void**)&wt_g,  g_wt_g);
    cudaGetSymbolAddress((void**)&wt_r1, g_wt_r1);
    cudaGetSymbolAddress((void**)&wt_r2, g_wt_r2);
    cudaGetSymbolAddress((void**)&stats, g_stats);
    cudaGetSymbolAddress((void**)&params, g_params);

    // v9 smem: 2*(CHUNK*9*32*2) + 2*(CHUNK*360) floats, CHUNK=4 -> 29952 bytes
    const int SM_V9 = (2*4*9*32*2 + 2*4*360) * 4;
    const int SM_R2 = (2*8*9*4 + 2*8*360) * 4;       // 25344
    cudaFuncSetAttribute((const void*)conv3x3_v9<4,4>,   cudaFuncAttributeMaxDynamicSharedMemorySize, SM_V9);
    cudaFuncSetAttribute((const void*)conv3x3_v9<32,4>,  cudaFuncAttributeMaxDynamicSharedMemorySize, SM_V9);
    cudaFuncSetAttribute((const void*)conv3x3_v9<64,4>,  cudaFuncAttributeMaxDynamicSharedMemorySize, SM_V9);
    cudaFuncSetAttribute((const void*)conv3x3_v8<32,4,8>, cudaFuncAttributeMaxDynamicSharedMemorySize, SM_R2);

    dim3 thr(256);
    dim3 grid512(512/32, 512/8, 1);        // 16 x 64
    dim3 gridG  (512/32, 512/8, 4);
    dim3 gridR2 ((HOB + 31)/32, (HOB + 7)/8, 1);   // 17 x 65

    // launch order arranged so the 6th launch (ncu -s 5 -c 1) is the gates conv
    prep_weights<<<(94464 + 255)/256, 256>>>(w_e1, w_e2, w_f, w_i, w_c, w_o, w_r1, w_r2);

    // e1: x (4ch, raw) -> t1raw (+stats)
    conv3x3_v9<4,4><<<grid512, thr, SM_V9>>>(x, x, 4, nullptr, nullptr, 0, 0,
                                             wt_e1, t1raw, stats + 0, 512, 512, 1, 512, 512);
    make_params<<<1, 32>>>(stats + 0, params + 0, 32, 1.f / (float)HW);

    // e2: relu(BN(t1raw)) -> t2raw (+stats)
    conv3x3_v9<32,4><<<grid512, thr, SM_V9>>>(t1raw, t1raw, 32, params + 0, params + 0, 1, 1,
                                              wt_e2, t2raw, stats + 64, 512, 512, 1, 512, 512);
    make_params<<<1, 32>>>(stats + 64, params + 32, 32, 1.f / (float)HW);

    // gates: [prev_h (raw) ; BN(t2raw)] -> graw (4 x 32ch over z) (+stats)  [profiled launch]
    conv3x3_v9<64,4><<<gridG, thr, SM_V9>>>(prev_h, t2raw, 32, nullptr, params + 32, 0, 0,
                                            wt_g, graw, stats + 128, 512, 512, 1, 512, 512);
    make_params<<<1, 128>>>(stats + 128, params + 64, 128, 1.f / (float)HW);

    // LSTM -> out[0:32HW]=next_c, out[32HW:64HW]=next_h
    lstm_kernel<<<32*HW/256, 256>>>(prev_c, params + 64, out, out + 32*HW);

    // r1: next_h (raw) -> r1raw (+stats)
    conv3x3_v9<32,4><<<grid512, thr, SM_V9>>>(out + 32*HW, out + 32*HW, 32, nullptr, nullptr, 0, 0,
                                              wt_r1, r1raw, stats + 384, 512, 512, 1, 512, 512);
    make_params<<<1, 32>>>(stats + 384, params + 192, 32, 1.f / (float)HW);

    // r2: relu(BN(r1raw)) -> r2raw (3+1 ch @ 518x518, pad 4) (+stats)  [v8 path]
    conv3x3_v8<32,4,8><<<gridR2, thr, SM_R2>>>(r1raw, r1raw, 32, params + 192, params + 192, 1, 1,
                                               wt_r2, r2raw, stats + 448, 512, 512, 4, HOB, HOB);
    make_params<<<1, 32>>>(stats + 448, params + 224, 4, 1.f / (float)HW2);

    // gather + dot -> out tail
    gather_kernel<<<1, 256>>>(holes, w_oil, b_oil, w_wat, b_wat, w_gas, b_gas, params + 224, out + 64*HW);
}

// round 11
// speedup vs baseline: 1.3204x; 1.3204x over previous
#include <cuda_runtime.h>

#define HPX 512
#define WPX 512
#define HW  (HPX*WPX)           // 262144 = 2^18
#define HOB 518                 // r2 output side (512 + 2*4 - 2)
#define HW2 (HOB*HOB)           // 268324

typedef unsigned long long u64;

// ---------------- device scratch (no cudaMalloc allowed) ----------------
__device__ float g_t1raw[32*HW];
__device__ float g_t2raw[32*HW];
__device__ float g_graw [128*HW];
__device__ float g_r1raw[32*HW];
__device__ float g_r2raw[4*HW2];
__device__ __align__(16) float g_wt_e1[4*9*32];
__device__ __align__(16) float g_wt_e2[32*9*32];
__device__ __align__(16) float g_wt_g [4*64*9*32];   // [z4][cin64][k9][cout32]
__device__ __align__(16) float g_wt_r1[32*9*32];
__device__ __align__(16) float g_wt_r2[32*9*4];
__device__ float  g_stats[512];    // e1:[0,64) e2:[64,128) gates:[128,384) r1:[384,448) r2:[448,456)
__device__ float2 g_params[256];   // e1:0 e2:32 gates:64 r1:192 r2:224   (scale, bias)

// ---------------- f32x2 / cp.async helpers ----------------
__device__ __forceinline__ u64 pack2(float x) {
    unsigned u = __float_as_uint(x);
    u64 r;
    asm("mov.b64 %0, {%1, %2};" : "=l"(r) : "r"(u), "r"(u));
    return r;
}
__device__ __forceinline__ u64 ffma2(u64 a, u64 b, u64 c) {
    u64 d;
    asm("fma.rn.f32x2 %0, %1, %2, %3;" : "=l"(d) : "l"(a), "l"(b), "l"(c));
    return d;
}
__device__ __forceinline__ void unpack2(u64 v, float& lo, float& hi) {
    unsigned a, b;
    asm("mov.b64 {%0, %1}, %2;" : "=r"(a), "=r"(b) : "l"(v));
    lo = __uint_as_float(a); hi = __uint_as_float(b);
}
__device__ __forceinline__ float sigmoidf_(float x) { return 1.f / (1.f + expf(-x)); }

__device__ __forceinline__ void cp_async4(unsigned dst, const void* src, bool pred) {
    int bytes = pred ? 4 : 0;
    asm volatile("cp.async.ca.shared.global [%0], [%1], 4, %2;"
                 :: "r"(dst), "l"(src), "r"(bytes));
}
__device__ __forceinline__ void cp_async16(unsigned dst, const void* src) {
    asm volatile("cp.async.cg.shared.global [%0], [%1], 16;" :: "r"(dst), "l"(src));
}
__device__ __forceinline__ void cp_commit() {
    asm volatile("cp.async.commit_group;");
}
template<int N>
__device__ __forceinline__ void cp_wait() {
    asm volatile("cp.async.wait_group %0;" :: "n"(N));
}
__device__ __forceinline__ unsigned to_tf32(float v) {
    unsigned u;
    asm("cvt.rna.tf32.f32 %0, %1;" : "=r"(u) : "f"(v));
    return u;
}
__device__ __forceinline__ void mma_tf32(float* c, unsigned a0, unsigned a1, unsigned a2,
                                         unsigned a3, unsigned b0, unsigned b1) {
    asm volatile("mma.sync.aligned.m16n8k8.row.col.f32.tf32.tf32.f32 "
                 "{%0,%1,%2,%3}, {%4,%5,%6,%7}, {%8,%9}, {%0,%1,%2,%3};"
                 : "+f"(c[0]), "+f"(c[1]), "+f"(c[2]), "+f"(c[3])
                 : "r"(a0), "r"(a1), "r"(a2), "r"(a3), "r"(b0), "r"(b1));
}

// ---------------- weight transpose/prep (+ stats zeroing): [cout][cin][k] -> [cin*9+k][cout] --
__global__ void prep_weights(const float* __restrict__ we1, const float* __restrict__ we2,
                             const float* __restrict__ wf,  const float* __restrict__ wi,
                             const float* __restrict__ wc,  const float* __restrict__ wo,
                             const float* __restrict__ wr1, const float* __restrict__ wr2)
{
    int idx = blockIdx.x * 256 + threadIdx.x;
    if (idx < 512) g_stats[idx] = 0.f;
    if (idx < 1152) {
        int cout = idx % 32, t = idx / 32, k = t % 9, cin = t / 9;
        g_wt_e1[idx] = we1[cout*4*9 + cin*9 + k];
        return;
    }
    idx -= 1152;
    if (idx < 9216) {
        int cout = idx % 32, t = idx / 32, k = t % 9, cin = t / 9;
        g_wt_e2[idx] = we2[cout*32*9 + cin*9 + k];
        return;
    }
    idx -= 9216;
    if (idx < 4*18432) {
        int g = idx / 18432, d = idx % 18432;
        int cout = d % 32, t = d / 32, k = t % 9, cin = t / 9;
        const float* src = (g == 0) ? wf : (g == 1) ? wi : (g == 2) ? wc : wo;
        g_wt_g[idx] = src[cout*64*9 + cin*9 + k];
        return;
    }
    idx -= 4*18432;
    if (idx < 9216) {
        int cout = idx % 32, t = idx / 32, k = t % 9, cin = t / 9;
        g_wt_r1[idx] = wr1[cout*32*9 + cin*9 + k];
        return;
    }
    idx -= 9216;
    if (idx < 1152) {
        int cout = idx % 4, t = idx / 4, k = t % 9, cin = t / 9;
        g_wt_r2[idx] = (cout < 3) ? wr2[cout*32*9 + cin*9 + k] : 0.f;
        return;
    }
}

// stats (sum, sumsq) -> params (scale, bias)
__global__ void make_params(const float* __restrict__ stats, float2* __restrict__ params,
                            int nch, float invn)
{
    int c = threadIdx.x;
    if (c >= nch) return;
    float m   = stats[2*c] * invn;
    float var = stats[2*c+1] * invn - m * m;
    float sc  = rsqrtf(var + 1e-5f);
    params[c] = make_float2(sc, -m * sc);
}

// ---------------- gates conv via tf32 mma.m16n8k8 (implicit GEMM) ----------------------------
// Block: 32x4 output pixels x 32 couts, blockIdx.z = gate. 8 warps, warp w = 16-pixel mtile.
// K = (cin group of 8) x (9 taps). Weights (all 64 cin) staged once in smem, stride 296.
// Tiles double-buffered via cp.async; transform applies BN (xemb half) + cvt.rna.tf32.
__global__ void __launch_bounds__(256, 2)
conv_gates_mma(const float* __restrict__ ph, const float* __restrict__ t2,
               const float2* __restrict__ prm,
               const float* __restrict__ wt, float* __restrict__ out,
               float* __restrict__ statsOut)
{
    constexpr int PS = 232;     // tile plane stride floats (232 % 32 == 8 -> conflict-free A)
    constexpr int WS = 296;     // weight cin stride floats (296 % 32 == 8 -> conflict-free B)
    constexpr int TEL = 204;    // live elems per plane (34 x 6)
    extern __shared__ float smem[];
    float* wsh  = smem;                     // 64 * WS
    float* tile = smem + 64*WS;             // 2 * 8 * PS
    __shared__ float sstat[64];

    const int tid  = threadIdx.x;
    const int warp = tid >> 5, lane = tid & 31;
    const int gid  = lane >> 2, tig = lane & 3;
    if (tid < 64) sstat[tid] = 0.f;

    const int gx = blockIdx.x * 32, gy = blockIdx.y * 4;
    const float* wsrc = wt + blockIdx.z * (64*9*32);
    const unsigned wsh_s  = (unsigned)__cvta_generic_to_shared(wsh);
    const unsigned tile_s = (unsigned)__cvta_generic_to_shared(tile);

    float acc[4][4];
#pragma unroll
    for (int j = 0; j < 4; j++)
#pragma unroll
        for (int e = 0; e < 4; e++) acc[j][e] = 0.f;

    // stage all weights (64 cin x 288 floats -> padded stride WS)
    for (int i = tid; i < 64*72; i += 256) {
        int cin = i / 72, off = i % 72;
        cp_async16(wsh_s + (cin*WS + off*4)*4, wsrc + cin*288 + off*4);
    }
    cp_commit();

    auto prefetch = [&](int g, int buf) {
        unsigned td = tile_s + buf * 8*PS*4;
        for (int i = tid; i < 8*TEL; i += 256) {
            int pl = i / TEL, rem = i % TEL;
            int r = rem / 34, c = rem % 34;
            int cin = g*8 + pl;
            const float* ip = (cin < 32) ? (ph + (size_t)cin * HW)
                                         : (t2 + (size_t)(cin - 32) * HW);
            int iy = gy - 1 + r, ix = gx - 1 + c;
            bool inb = iy >= 0 && iy < 512 && ix >= 0 && ix < 512;
            cp_async4(td + (pl*PS + r*34 + c)*4, inb ? (ip + (size_t)iy*512 + ix) : ip, inb);
        }
        cp_commit();
    };

    auto transform = [&](int g, int buf) {
        float* tb = tile + buf * 8*PS;
        for (int i = tid; i < 8*TEL; i += 256) {
            int pl = i / TEL, rem = i % TEL;
            int r = rem / 34, c = rem % 34;
            int cin = g*8 + pl;
            int iy = gy - 1 + r, ix = gx - 1 + c;
            bool inb = iy >= 0 && iy < 512 && ix >= 0 && ix < 512;
            int o = pl*PS + r*34 + c;
            float v = tb[o];
            if (cin >= 32) {
                float2 p = __ldg(&prm[cin - 32]);
                v = inb ? (v * p.x + p.y) : 0.f;
            }
            ((unsigned*)tb)[o] = to_tf32(v);
        }
    };

    auto compute = [&](int g, int buf) {
        const unsigned* tb = (const unsigned*)(tile + buf * 8*PS);
        const unsigned* wb = (const unsigned*)wsh + g*8*WS;
        const int py = warp >> 1, pxb = (warp & 1) * 16;
#pragma unroll
        for (int ky = 0; ky < 3; ky++) {
#pragma unroll
            for (int kx = 0; kx < 3; kx++) {
                int ro = (py + ky) * 34 + pxb + kx;
                unsigned a0 = tb[ tig    * PS + ro + gid    ];
                unsigned a1 = tb[ tig    * PS + ro + gid + 8];
                unsigned a2 = tb[(tig+4) * PS + ro + gid    ];
                unsigned a3 = tb[(tig+4) * PS + ro + gid + 8];
                const unsigned* wk0 = wb + tig    *WS + (ky*3+kx)*32 + gid;
                const unsigned* wk4 = wb + (tig+4)*WS + (ky*3+kx)*32 + gid;
#pragma unroll
                for (int j = 0; j < 4; j++)
                    mma_tf32(acc[j], a0, a1, a2, a3, wk0[8*j], wk4[8*j]);
            }
        }
    };

    prefetch(0, 0);
    for (int g = 0; g < 8; ++g) {
        int cur = g & 1;
        if (g + 1 < 8) {
            prefetch(g + 1, 1 - cur);
            cp_wait<1>();
        } else {
            cp_wait<0>();
        }
        __syncthreads();
        transform(g, cur);
        __syncthreads();
        compute(g, cur);
        __syncthreads();
    }

    // ---- epilogue: store + fused stats (all pixels valid: 512 divides exactly) ----
    float* ob = out + (size_t)blockIdx.z * 32 * HW;
    const int py = warp >> 1, pxb = (warp & 1) * 16;
    const int oy = gy + py;
    const size_t row = (size_t)oy * 512 + gx + pxb;
#pragma unroll
    for (int j = 0; j < 4; j++) {
        int n0 = 8*j + 2*tig;
        ob[(size_t)(n0  ) * HW + row + gid    ] = acc[j][0];
        ob[(size_t)(n0+1) * HW + row + gid    ] = acc[j][1];
        ob[(size_t)(n0  ) * HW + row + gid + 8] = acc[j][2];
        ob[(size_t)(n0+1) * HW + row + gid + 8] = acc[j][3];
        float s0 = acc[j][0] + acc[j][2];
        float q0 = acc[j][0]*acc[j][0] + acc[j][2]*acc[j][2];
        float s1 = acc[j][1] + acc[j][3];
        float q1 = acc[j][1]*acc[j][1] + acc[j][3]*acc[j][3];
#pragma unroll
        for (int o = 16; o >= 4; o >>= 1) {
            s0 += __shfl_down_sync(0xFFFFFFFFu, s0, o);
            q0 += __shfl_down_sync(0xFFFFFFFFu, q0, o);
            s1 += __shfl_down_sync(0xFFFFFFFFu, s1, o);
            q1 += __shfl_down_sync(0xFFFFFFFFu, q1, o);
        }
        if (gid == 0) {
            atomicAdd(&sstat[2*n0    ], s0);
            atomicAdd(&sstat[2*n0 + 1], q0);
            atomicAdd(&sstat[2*n0 + 2], s1);
            atomicAdd(&sstat[2*n0 + 3], q1);
        }
    }
    __syncthreads();
    if (tid < 64) atomicAdd(&statsOut[blockIdx.z*64 + tid], sstat[tid]);
}

// ---------------- 3x3 conv v8 (e1 / e2 / r1 / r2) ---------------------------------------------
template<int CIN, int COUT, int CHUNK>
__global__ void __launch_bounds__(256, 4)
conv3x3_v8(const float* __restrict__ inA, const float* __restrict__ inB, int csplit,
           const float2* __restrict__ prmA, const float2* __restrict__ prmB,
           int reluA, int reluB,
           const float* __restrict__ wt, float* __restrict__ out, float* __restrict__ statsOut,
           int H, int W, int pad, int HO, int WO)
{
    constexpr int TW = 32, TPW = 36, TPH = 10;
    constexpr int TSZ = TPW * TPH;
    constexpr int NCH = CIN / CHUNK;
    constexpr int WCH = CHUNK * 9 * COUT;
    constexpr int COUTG = COUT / 2;
    constexpr int C2G = COUTG / 2;
    constexpr int C2  = COUT / 2;
    extern __shared__ float smem[];
    float* ws   = smem;
    float* tile = smem + 2*WCH;
    __shared__ float sstat[2*COUT];

    const int tid   = threadIdx.x;
    const int group = tid >> 7;
    const int tx    = tid & 15;
    const int ty    = (tid >> 4) & 7;
    if (tid < 2*COUT) sstat[tid] = 0.f;

    const int gx = blockIdx.x * TW, gy = blockIdx.y * 8;
    const int oy = gy + ty;
    const int ox0 = gx + tx, ox1 = ox0 + 16;
    const float* wsrc = wt + (size_t)blockIdx.z * (CIN*9*COUT);

    const unsigned ws_s   = (unsigned)__cvta_generic_to_shared(ws);
    const unsigned tile_s = (unsigned)__cvta_generic_to_shared(tile);
    const bool needT = (prmA != nullptr && csplit > 0) || (prmB != nullptr && csplit < CIN);

    u64 accA[C2G], accB[C2G];
#pragma unroll
    for (int p = 0; p < C2G; p++) { accA[p] = 0ull; accB[p] = 0ull; }

    auto prefetch = [&](int ci, int buf) {
        const float* wc = wsrc + (size_t)ci * WCH;
        unsigned wd = ws_s + buf * WCH * 4;
        for (int i = tid; i < WCH/4; i += 256)
            cp_async16(wd + i*16, wc + i*4);
        unsigned td = tile_s + buf * CHUNK*TSZ*4;
        for (int cc = 0; cc < CHUNK; ++cc) {
            int cin = ci*CHUNK + cc;
            bool isA = cin < csplit;
            const float* ip = isA ? (inA + (size_t)cin * H * W)
                                  : (inB + (size_t)(cin - csplit) * H * W);
            for (int i = tid; i < TSZ; i += 256) {
                int r = i / TPW, c = i % TPW;
                int iy = gy - pad + r, ix = gx - pad + c;
                bool inb = (c < TW+2) && iy >= 0 && iy < H && ix >= 0 && ix < W;
                cp_async4(td + (cc*TSZ + i)*4, inb ? (ip + (size_t)iy*W + ix) : ip, inb);
            }
        }
        cp_commit();
    };

    auto transform = [&](int ci, int buf) {
        float* tb = tile + buf * CHUNK*TSZ;
        for (int i = tid; i < CHUNK*TSZ; i += 256) {
            int cc = i / TSZ, e = i % TSZ;
            int cin = ci*CHUNK + cc;
            bool isA = cin < csplit;
            const float2* prm = isA ? prmA : prmB;
            if (!prm) continue;
            int rl = isA ? reluA : reluB;
            int r = e / TPW, c = e % TPW;
            int iy = gy - pad + r, ix = gx - pad + c;
            bool inb = (c < TW+2) && iy >= 0 && iy < H && ix >= 0 && ix < W;
            float2 p = __ldg(&prm[isA ? cin : (cin - csplit)]);
            float v = inb ? (tb[i] * p.x + p.y) : 0.f;
            if (rl) v = fmaxf(v, 0.f);
            tb[i] = v;
        }
    };

    auto compute = [&](int buf) {
        const float* tb0 = tile + buf * CHUNK*TSZ + ty * TPW + tx;
        const float* wsb = ws + buf * WCH;
#pragma unroll
        for (int cc = 0; cc < CHUNK; ++cc) {
            const float* tb = tb0 + cc * TSZ;
            const u64* wrow = (const u64*)(wsb + cc * 9 * COUT) + group * C2G;
#pragma unroll
            for (int ky = 0; ky < 3; ky++) {
#pragma unroll
                for (int kx = 0; kx < 3; kx++) {
                    u64 va = pack2(tb[ky*TPW + kx]);
                    u64 vb = pack2(tb[ky*TPW + kx + 16]);
                    if constexpr (C2G >= 2) {
                        const ulonglong2* w4 = (const ulonglong2*)(wrow + (ky*3+kx) * C2);
#pragma unroll
                        for (int p2 = 0; p2 < C2G/2; p2++) {
                            ulonglong2 w = w4[p2];
                            accA[2*p2  ] = ffma2(va, w.x, accA[2*p2  ]);
                            accB[2*p2  ] = ffma2(vb, w.x, accB[2*p2  ]);
                            accA[2*p2+1] = ffma2(va, w.y, accA[2*p2+1]);
                            accB[2*p2+1] = ffma2(vb, w.y, accB[2*p2+1]);
                        }
                    } else {
                        u64 w = wrow[(ky*3+kx) * C2];
                        accA[0] = ffma2(va, w, accA[0]);
                        accB[0] = ffma2(vb, w, accB[0]);
                    }
                }
            }
        }
    };

    prefetch(0, 0);
    for (int ci = 0; ci < NCH; ++ci) {
        int cur = ci & 1;
        if (ci + 1 < NCH) {
            prefetch(ci + 1, 1 - cur);
            cp_wait<1>();
        } else {
            cp_wait<0>();
        }
        __syncthreads();
        if (needT) { transform(ci, cur); __syncthreads(); }
        compute(cur);
        __syncthreads();
    }

    float* ob = out + (size_t)blockIdx.z * COUT * HO * WO;
    float* so = statsOut + blockIdx.z * 2 * COUT;
    const bool vA = (oy < HO) && (ox0 < WO);
    const bool vB = (oy < HO) && (ox1 < WO);
    const size_t row = (size_t)oy * WO;
#pragma unroll
    for (int p = 0; p < C2G; p++) {
        int c0 = group * COUTG + 2*p;
        float a0, a1, b0, b1;
        unpack2(accA[p], a0, a1);
        unpack2(accB[p], b0, b1);
        if (vA) {
            ob[(size_t)(c0  ) * HO * WO + row + ox0] = a0;
            ob[(size_t)(c0+1) * HO * WO + row + ox0] = a1;
        }
        if (vB) {
            ob[(size_t)(c0  ) * HO * WO + row + ox1] = b0;
            ob[(size_t)(c0+1) * HO * WO + row + ox1] = b1;
        }
        float s0 = (vA ? a0 : 0.f) + (vB ? b0 : 0.f);
        float q0 = (vA ? a0*a0 : 0.f) + (vB ? b0*b0 : 0.f);
        float s1 = (vA ? a1 : 0.f) + (vB ? b1 : 0.f);
        float q1 = (vA ? a1*a1 : 0.f) + (vB ? b1*b1 : 0.f);
#pragma unroll
        for (int o = 16; o; o >>= 1) {
            s0 += __shfl_down_sync(0xFFFFFFFFu, s0, o);
            q0 += __shfl_down_sync(0xFFFFFFFFu, q0, o);
            s1 += __shfl_down_sync(0xFFFFFFFFu, s1, o);
            q1 += __shfl_down_sync(0xFFFFFFFFu, q1, o);
        }
        if ((tid & 31) == 0) {
            atomicAdd(&sstat[2*c0  ], s0);
            atomicAdd(&sstat[2*c0+1], q0);
            atomicAdd(&sstat[2*c0+2], s1);
            atomicAdd(&sstat[2*c0+3], q1);
        }
    }
    __syncthreads();
    if (tid < 2*COUT) atomicAdd(&so[tid], sstat[tid]);
}

// ---------------- LSTM elementwise ----------------
__global__ void lstm_kernel(const float* __restrict__ prev_c, const float2* __restrict__ prm,
                            float* __restrict__ out_c, float* __restrict__ out_h)
{
    int idx = blockIdx.x * 256 + threadIdx.x;   // over 32*HW
    int c = idx >> 18;                          // HW = 2^18
    const int CHW = 32 * HW;

    float g[4];
#pragma unroll
    for (int gi = 0; gi < 4; gi++) {
        float2 p = prm[gi*32 + c];
        g[gi] = g_graw[(size_t)gi * CHW + idx] * p.x + p.y;
    }
    float f  = sigmoidf_(g[0]);
    float it = sigmoidf_(g[1]);
    float ct = tanhf(g[2]);
    float ot = sigmoidf_(g[3]);
    float nc = prev_c[idx] * f + it * ct;
    out_c[idx] = nc;
    out_h[idx] = tanhf(nc) * ot;
}

// ---------------- patch gather + per-channel dot ----------------
__global__ void gather_kernel(const int* __restrict__ holes,
                              const float* __restrict__ woil, const float* __restrict__ boil,
                              const float* __restrict__ wwat, const float* __restrict__ bwat,
                              const float* __restrict__ wgas, const float* __restrict__ bgas,
                              const float2* __restrict__ prm,
                              float* __restrict__ res)
{
    int nidx = threadIdx.x;
    if (nidx >= 256) return;
    int hx = holes[2*nidx], hy = holes[2*nidx+1];
    const float* wv[3] = { woil, wwat, wgas };
    float bv[3] = { boil[0], bwat[0], bgas[0] };
    for (int c = 0; c < 3; c++) {
        float2 p = prm[c];
        float s = bv[c];
        for (int i = 0; i < 3; i++)
            for (int j = 0; j < 3; j++) {
                float v = g_r2raw[(size_t)c * HW2 + (size_t)(hx + 3 + i) * HOB + (hy + 3 + j)];
                s += wv[c][i*3+j] * (v * p.x + p.y);
            }
        res[nidx*3 + c] = s;
    }
}

// ---------------- launch ----------------
extern "C" void kernel_launch(void* const* d_in, const int* in_sizes, int n_in,
                              void* d_out, int out_size)
{
    const float* x      = (const float*)d_in[0];
    const float* prev_c = (const float*)d_in[1];
    const float* prev_h = (const float*)d_in[2];
    const int*   holes  = (const int*)d_in[3];
    const float* w_e1   = (const float*)d_in[4];
    const float* w_e2   = (const float*)d_in[5];
    const float* w_f    = (const float*)d_in[6];
    const float* w_i    = (const float*)d_in[7];
    const float* w_c    = (const float*)d_in[8];
    const float* w_o    = (const float*)d_in[9];
    const float* w_r1   = (const float*)d_in[10];
    const float* w_r2   = (const float*)d_in[11];
    const float* w_oil  = (const float*)d_in[12];
    const float* b_oil  = (const float*)d_in[13];
    const float* w_wat  = (const float*)d_in[14];
    const float* b_wat  = (const float*)d_in[15];
    const float* w_gas  = (const float*)d_in[16];
    const float* b_gas  = (const float*)d_in[17];
    float* out = (float*)d_out;

    float *t1raw, *t2raw, *graw, *r1raw, *r2raw;
    float *wt_e1, *wt_e2, *wt_g, *wt_r1, *wt_r2, *stats;
    float2 *params;
    cudaGetSymbolAddress((void**)&t1raw, g_t1raw);
    cudaGetSymbolAddress((void**)&t2raw, g_t2raw);
    cudaGetSymbolAddress((void**)&graw,  g_graw);
    cudaGetSymbolAddress((void**)&r1raw, g_r1raw);
    cudaGetSymbolAddress((void**)&r2raw, g_r2raw);
    cudaGetSymbolAddress((void**)&wt_e1, g_wt_e1);
    cudaGetSymbolAddress((void**)&wt_e2, g_wt_e2);
    cudaGetSymbolAddress((void**)&wt_g,  g_wt_g);
    cudaGetSymbolAddress((void**)&wt_r1, g_wt_r1);
    cudaGetSymbolAddress((void**)&wt_r2, g_wt_r2);
    cudaGetSymbolAddress((void**)&stats, g_stats);
    cudaGetSymbolAddress((void**)&params, g_params);

    constexpr int TSZ = 36 * 10;
    const int SM_E1 = (2*4*9*32  + 2*4*TSZ) * 4;    // 20736
    const int SM_32 = (2*8*9*32  + 2*8*TSZ) * 4;    // 41472
    const int SM_R2 = (2*8*9*4   + 2*8*TSZ) * 4;    // 25344
    const int SM_G  = (64*296 + 2*8*232) * 4;        // 90624
    cudaFuncSetAttribute((const void*)conv3x3_v8<4,32,4>,  cudaFuncAttributeMaxDynamicSharedMemorySize, SM_E1);
    cudaFuncSetAttribute((const void*)conv3x3_v8<32,32,8>, cudaFuncAttributeMaxDynamicSharedMemorySize, SM_32);
    cudaFuncSetAttribute((const void*)conv3x3_v8<32,4,8>,  cudaFuncAttributeMaxDynamicSharedMemorySize, SM_R2);
    cudaFuncSetAttribute((const void*)conv_gates_mma,      cudaFuncAttributeMaxDynamicSharedMemorySize, SM_G);

    dim3 thr(256);
    dim3 grid512(512/32, 512/8, 1);        // 16 x 64
    dim3 gridGM (512/32, 512/4, 4);        // 16 x 128 x 4  (mma gates)
    dim3 gridR2 ((HOB + 31)/32, (HOB + 7)/8, 1);   // 17 x 65

    // launch order arranged so the 6th launch (ncu -s 5 -c 1) is the gates mma conv
    prep_weights<<<(94464 + 255)/256, 256>>>(w_e1, w_e2, w_f, w_i, w_c, w_o, w_r1, w_r2);

    // e1: x (4ch, raw) -> t1raw (+stats)
    conv3x3_v8<4,32,4><<<grid512, thr, SM_E1>>>(x, x, 4, nullptr, nullptr, 0, 0,
                                                wt_e1, t1raw, stats + 0, 512, 512, 1, 512, 512);
    make_params<<<1, 32>>>(stats + 0, params + 0, 32, 1.f / (float)HW);

    // e2: relu(BN(t1raw)) -> t2raw (+stats)
    conv3x3_v8<32,32,8><<<grid512, thr, SM_32>>>(t1raw, t1raw, 32, params + 0, params + 0, 1, 1,
                                                 wt_e2, t2raw, stats + 64, 512, 512, 1, 512, 512);
    make_params<<<1, 32>>>(stats + 64, params + 32, 32, 1.f / (float)HW);

    // gates: [prev_h (raw) ; BN(t2raw)] via tf32 mma -> graw (+stats)  [profiled launch]
    conv_gates_mma<<<gridGM, thr, SM_G>>>(prev_h, t2raw, params + 32, wt_g, graw, stats + 128);
    make_params<<<1, 128>>>(stats + 128, params + 64, 128, 1.f / (float)HW);

    // LSTM -> out[0:32HW]=next_c, out[32HW:64HW]=next_h
    lstm_kernel<<<32*HW/256, 256>>>(prev_c, params + 64, out, out + 32*HW);

    // r1: next_h (raw) -> r1raw (+stats)
    conv3x3_v8<32,32,8><<<grid512, thr, SM_32>>>(out + 32*HW, out + 32*HW, 32, nullptr, nullptr, 0, 0,
                                                 wt_r1, r1raw, stats + 384, 512, 512, 1, 512, 512);
    make_params<<<1, 32>>>(stats + 384, params + 192, 32, 1.f / (float)HW);

    // r2: relu(BN(r1raw)) -> r2raw (3+1 ch @ 518x518, pad 4) (+stats)
    conv3x3_v8<32,4,8><<<gridR2, thr, SM_R2>>>(r1raw, r1raw, 32, params + 192, params + 192, 1, 1,
                                               wt_r2, r2raw, stats + 448, 512, 512, 4, HOB, HOB);
    make_params<<<1, 32>>>(stats + 448, params + 224, 4, 1.f / (float)HW2);

    // gather + dot -> out tail
    gather_kernel<<<1, 256>>>(holes, w_oil, b_oil, w_wat, b_wat, w_gas, b_gas, params + 224, out + 64*HW);
}

// round 12
// speedup vs baseline: 1.3525x; 1.0243x over previous
#include <cuda_runtime.h>

#define HPX 512
#define WPX 512
#define HW  (HPX*WPX)           // 262144 = 2^18
#define HOB 518                 // r2 output side (512 + 2*4 - 2)
#define HW2 (HOB*HOB)           // 268324

typedef unsigned long long u64;

// ---------------- device scratch (no cudaMalloc allowed) ----------------
__device__ float g_t1raw[32*HW];
__device__ float g_t2raw[32*HW];
__device__ float g_graw [128*HW];
__device__ float g_r1raw[32*HW];
__device__ float g_r2raw[4*HW2];
__device__ __align__(16) float g_wt_e1[4*9*32];
__device__ __align__(16) float g_wt_e2[32*9*32];     // [cin32][k9][cout32]
__device__ __align__(16) float g_wt_g [4*64*9*32];   // [z4][cin64][k9][cout32]
__device__ __align__(16) float g_wt_r1[32*9*32];     // [cin32][k9][cout32]
__device__ __align__(16) float g_wt_r2[32*9*4];
__device__ float  g_stats[512];    // e1:[0,64) e2:[64,128) gates:[128,384) r1:[384,448) r2:[448,456)
__device__ float2 g_params[256];   // e1:0 e2:32 gates:64 r1:192 r2:224   (scale, bias)

// ---------------- f32x2 / cp.async helpers ----------------
__device__ __forceinline__ u64 pack2(float x) {
    unsigned u = __float_as_uint(x);
    u64 r;
    asm("mov.b64 %0, {%1, %2};" : "=l"(r) : "r"(u), "r"(u));
    return r;
}
__device__ __forceinline__ u64 ffma2(u64 a, u64 b, u64 c) {
    u64 d;
    asm("fma.rn.f32x2 %0, %1, %2, %3;" : "=l"(d) : "l"(a), "l"(b), "l"(c));
    return d;
}
__device__ __forceinline__ void unpack2(u64 v, float& lo, float& hi) {
    unsigned a, b;
    asm("mov.b64 {%0, %1}, %2;" : "=r"(a), "=r"(b) : "l"(v));
    lo = __uint_as_float(a); hi = __uint_as_float(b);
}
__device__ __forceinline__ float sigmoidf_(float x) { return 1.f / (1.f + expf(-x)); }

__device__ __forceinline__ void cp_async4(unsigned dst, const void* src, bool pred) {
    int bytes = pred ? 4 : 0;
    asm volatile("cp.async.ca.shared.global [%0], [%1], 4, %2;"
                 :: "r"(dst), "l"(src), "r"(bytes));
}
__device__ __forceinline__ void cp_async16(unsigned dst, const void* src) {
    asm volatile("cp.async.cg.shared.global [%0], [%1], 16;" :: "r"(dst), "l"(src));
}
__device__ __forceinline__ void cp_commit() {
    asm volatile("cp.async.commit_group;");
}
template<int N>
__device__ __forceinline__ void cp_wait() {
    asm volatile("cp.async.wait_group %0;" :: "n"(N));
}
__device__ __forceinline__ unsigned to_tf32(float v) {
    unsigned u;
    asm("cvt.rna.tf32.f32 %0, %1;" : "=r"(u) : "f"(v));
    return u;
}
__device__ __forceinline__ void mma_tf32(float* c, unsigned a0, unsigned a1, unsigned a2,
                                         unsigned a3, unsigned b0, unsigned b1) {
    asm volatile("mma.sync.aligned.m16n8k8.row.col.f32.tf32.tf32.f32 "
                 "{%0,%1,%2,%3}, {%4,%5,%6,%7}, {%8,%9}, {%0,%1,%2,%3};"
                 : "+f"(c[0]), "+f"(c[1]), "+f"(c[2]), "+f"(c[3])
                 : "r"(a0), "r"(a1), "r"(a2), "r"(a3), "r"(b0), "r"(b1));
}

// ---------------- weight transpose/prep (+ stats zeroing): [cout][cin][k] -> [cin*9+k][cout] --
__global__ void prep_weights(const float* __restrict__ we1, const float* __restrict__ we2,
                             const float* __restrict__ wf,  const float* __restrict__ wi,
                             const float* __restrict__ wc,  const float* __restrict__ wo,
                             const float* __restrict__ wr1, const float* __restrict__ wr2)
{
    int idx = blockIdx.x * 256 + threadIdx.x;
    if (idx < 512) g_stats[idx] = 0.f;
    if (idx < 1152) {
        int cout = idx % 32, t = idx / 32, k = t % 9, cin = t / 9;
        g_wt_e1[idx] = we1[cout*4*9 + cin*9 + k];
        return;
    }
    idx -= 1152;
    if (idx < 9216) {
        int cout = idx % 32, t = idx / 32, k = t % 9, cin = t / 9;
        g_wt_e2[idx] = we2[cout*32*9 + cin*9 + k];
        return;
    }
    idx -= 9216;
    if (idx < 4*18432) {
        int g = idx / 18432, d = idx % 18432;
        int cout = d % 32, t = d / 32, k = t % 9, cin = t / 9;
        const float* src = (g == 0) ? wf : (g == 1) ? wi : (g == 2) ? wc : wo;
        g_wt_g[idx] = src[cout*64*9 + cin*9 + k];
        return;
    }
    idx -= 4*18432;
    if (idx < 9216) {
        int cout = idx % 32, t = idx / 32, k = t % 9, cin = t / 9;
        g_wt_r1[idx] = wr1[cout*32*9 + cin*9 + k];
        return;
    }
    idx -= 9216;
    if (idx < 1152) {
        int cout = idx % 4, t = idx / 4, k = t % 9, cin = t / 9;
        g_wt_r2[idx] = (cout < 3) ? wr2[cout*32*9 + cin*9 + k] : 0.f;
        return;
    }
}

// stats (sum, sumsq) -> params (scale, bias)
__global__ void make_params(const float* __restrict__ stats, float2* __restrict__ params,
                            int nch, float invn)
{
    int c = threadIdx.x;
    if (c >= nch) return;
    float m   = stats[2*c] * invn;
    float var = stats[2*c+1] * invn - m * m;
    float sc  = rsqrtf(var + 1e-5f);
    params[c] = make_float2(sc, -m * sc);
}

// ---------------- generic 3x3 conv via tf32 mma.m16n8k8 (512x512, pad 1, 32 couts) -----------
// Block: 32x4 output pixels x 32 couts; blockIdx.z = weight slice (gate).
// 8 warps, warp w -> 16-pixel mtile. K = (cin group of 8) x (9 taps).
// All CIN weights staged once in smem (stride 296); tiles double-buffered via cp.async;
// transform applies optional BN(+relu) and always cvt.rna.tf32.
template<int CIN>
__global__ void __launch_bounds__(256, 2)
conv_mma(const float* __restrict__ inA, const float* __restrict__ inB, int csplit,
         const float2* __restrict__ prmA, const float2* __restrict__ prmB,
         int reluA, int reluB,
         const float* __restrict__ wt, float* __restrict__ out, float* __restrict__ statsOut)
{
    constexpr int PS = 232;     // tile plane stride floats (232 % 32 == 8 -> conflict-free A)
    constexpr int WS = 296;     // weight cin stride floats (296 % 32 == 8 -> conflict-free B)
    constexpr int TEL = 204;    // live elems per plane (34 x 6)
    constexpr int NG = CIN / 8;
    extern __shared__ float smem[];
    float* wsh  = smem;                     // CIN * WS
    float* tile = smem + CIN*WS;            // 2 * 8 * PS
    __shared__ float sstat[64];

    const int tid  = threadIdx.x;
    const int warp = tid >> 5, lane = tid & 31;
    const int gid  = lane >> 2, tig = lane & 3;
    if (tid < 64) sstat[tid] = 0.f;

    const int gx = blockIdx.x * 32, gy = blockIdx.y * 4;
    const float* wsrc = wt + (size_t)blockIdx.z * (CIN*9*32);
    const unsigned wsh_s  = (unsigned)__cvta_generic_to_shared(wsh);
    const unsigned tile_s = (unsigned)__cvta_generic_to_shared(tile);

    float acc[4][4];
#pragma unroll
    for (int j = 0; j < 4; j++)
#pragma unroll
        for (int e = 0; e < 4; e++) acc[j][e] = 0.f;

    // stage all weights (CIN cin x 288 floats -> padded stride WS)
    for (int i = tid; i < CIN*72; i += 256) {
        int cin = i / 72, off = i % 72;
        cp_async16(wsh_s + (cin*WS + off*4)*4, wsrc + cin*288 + off*4);
    }
    cp_commit();

    auto prefetch = [&](int g, int buf) {
        unsigned td = tile_s + buf * 8*PS*4;
        for (int i = tid; i < 8*TEL; i += 256) {
            int pl = i / TEL, rem = i % TEL;
            int r = rem / 34, c = rem % 34;
            int cin = g*8 + pl;
            const float* ip = (cin < csplit) ? (inA + (size_t)cin * HW)
                                             : (inB + (size_t)(cin - csplit) * HW);
            int iy = gy - 1 + r, ix = gx - 1 + c;
            bool inb = iy >= 0 && iy < 512 && ix >= 0 && ix < 512;
            cp_async4(td + (pl*PS + r*34 + c)*4, inb ? (ip + (size_t)iy*512 + ix) : ip, inb);
        }
        cp_commit();
    };

    auto transform = [&](int g, int buf) {
        float* tb = tile + buf * 8*PS;
        for (int i = tid; i < 8*TEL; i += 256) {
            int pl = i / TEL, rem = i % TEL;
            int r = rem / 34, c = rem % 34;
            int cin = g*8 + pl;
            bool isA = cin < csplit;
            const float2* prm = isA ? prmA : prmB;
            int rl = isA ? reluA : reluB;
            int iy = gy - 1 + r, ix = gx - 1 + c;
            bool inb = iy >= 0 && iy < 512 && ix >= 0 && ix < 512;
            int o = pl*PS + r*34 + c;
            float v = tb[o];
            if (prm) {
                float2 p = __ldg(&prm[isA ? cin : (cin - csplit)]);
                v = inb ? (v * p.x + p.y) : 0.f;
                if (rl) v = fmaxf(v, 0.f);
            }
            ((unsigned*)tb)[o] = to_tf32(v);
        }
    };

    auto compute = [&](int g, int buf) {
        const unsigned* tb = (const unsigned*)(tile + buf * 8*PS);
        const unsigned* wb = (const unsigned*)wsh + g*8*WS;
        const int py = warp >> 1, pxb = (warp & 1) * 16;
#pragma unroll
        for (int ky = 0; ky < 3; ky++) {
#pragma unroll
            for (int kx = 0; kx < 3; kx++) {
                int ro = (py + ky) * 34 + pxb + kx;
                unsigned a0 = tb[ tig    * PS + ro + gid    ];
                unsigned a1 = tb[ tig    * PS + ro + gid + 8];
                unsigned a2 = tb[(tig+4) * PS + ro + gid    ];
                unsigned a3 = tb[(tig+4) * PS + ro + gid + 8];
                const unsigned* wk0 = wb + tig    *WS + (ky*3+kx)*32 + gid;
                const unsigned* wk4 = wb + (tig+4)*WS + (ky*3+kx)*32 + gid;
#pragma unroll
                for (int j = 0; j < 4; j++)
                    mma_tf32(acc[j], a0, a1, a2, a3, wk0[8*j], wk4[8*j]);
            }
        }
    };

    prefetch(0, 0);
    for (int g = 0; g < NG; ++g) {
        int cur = g & 1;
        if (g + 1 < NG) {
            prefetch(g + 1, 1 - cur);
            cp_wait<1>();
        } else {
            cp_wait<0>();
        }
        __syncthreads();
        transform(g, cur);
        __syncthreads();
        compute(g, cur);
        __syncthreads();
    }

    // ---- epilogue: store + fused stats (all pixels valid: 512 divides exactly) ----
    float* ob = out + (size_t)blockIdx.z * 32 * HW;
    const int py = warp >> 1, pxb = (warp & 1) * 16;
    const int oy = gy + py;
    const size_t row = (size_t)oy * 512 + gx + pxb;
#pragma unroll
    for (int j = 0; j < 4; j++) {
        int n0 = 8*j + 2*tig;
        ob[(size_t)(n0  ) * HW + row + gid    ] = acc[j][0];
        ob[(size_t)(n0+1) * HW + row + gid    ] = acc[j][1];
        ob[(size_t)(n0  ) * HW + row + gid + 8] = acc[j][2];
        ob[(size_t)(n0+1) * HW + row + gid + 8] = acc[j][3];
        float s0 = acc[j][0] + acc[j][2];
        float q0 = acc[j][0]*acc[j][0] + acc[j][2]*acc[j][2];
        float s1 = acc[j][1] + acc[j][3];
        float q1 = acc[j][1]*acc[j][1] + acc[j][3]*acc[j][3];
#pragma unroll
        for (int o = 16; o >= 4; o >>= 1) {
            s0 += __shfl_down_sync(0xFFFFFFFFu, s0, o);
            q0 += __shfl_down_sync(0xFFFFFFFFu, q0, o);
            s1 += __shfl_down_sync(0xFFFFFFFFu, s1, o);
            q1 += __shfl_down_sync(0xFFFFFFFFu, q1, o);
        }
        if (gid == 0) {
            atomicAdd(&sstat[2*n0    ], s0);
            atomicAdd(&sstat[2*n0 + 1], q0);
            atomicAdd(&sstat[2*n0 + 2], s1);
            atomicAdd(&sstat[2*n0 + 3], q1);
        }
    }
    __syncthreads();
    if (tid < 64) atomicAdd(&statsOut[blockIdx.z*64 + tid], sstat[tid]);
}

// ---------------- 3x3 conv v8 (e1, r2) --------------------------------------------------------
template<int CIN, int COUT, int CHUNK>
__global__ void __launch_bounds__(256, 4)
conv3x3_v8(const float* __restrict__ inA, const float* __restrict__ inB, int csplit,
           const float2* __restrict__ prmA, const float2* __restrict__ prmB,
           int reluA, int reluB,
           const float* __restrict__ wt, float* __restrict__ out, float* __restrict__ statsOut,
           int H, int W, int pad, int HO, int WO)
{
    constexpr int TW = 32, TPW = 36, TPH = 10;
    constexpr int TSZ = TPW * TPH;
    constexpr int NCH = CIN / CHUNK;
    constexpr int WCH = CHUNK * 9 * COUT;
    constexpr int COUTG = COUT / 2;
    constexpr int C2G = COUTG / 2;
    constexpr int C2  = COUT / 2;
    extern __shared__ float smem[];
    float* ws   = smem;
    float* tile = smem + 2*WCH;
    __shared__ float sstat[2*COUT];

    const int tid   = threadIdx.x;
    const int group = tid >> 7;
    const int tx    = tid & 15;
    const int ty    = (tid >> 4) & 7;
    if (tid < 2*COUT) sstat[tid] = 0.f;

    const int gx = blockIdx.x * TW, gy = blockIdx.y * 8;
    const int oy = gy + ty;
    const int ox0 = gx + tx, ox1 = ox0 + 16;
    const float* wsrc = wt + (size_t)blockIdx.z * (CIN*9*COUT);

    const unsigned ws_s   = (unsigned)__cvta_generic_to_shared(ws);
    const unsigned tile_s = (unsigned)__cvta_generic_to_shared(tile);
    const bool needT = (prmA != nullptr && csplit > 0) || (prmB != nullptr && csplit < CIN);

    u64 accA[C2G], accB[C2G];
#pragma unroll
    for (int p = 0; p < C2G; p++) { accA[p] = 0ull; accB[p] = 0ull; }

    auto prefetch = [&](int ci, int buf) {
        const float* wc = wsrc + (size_t)ci * WCH;
        unsigned wd = ws_s + buf * WCH * 4;
        for (int i = tid; i < WCH/4; i += 256)
            cp_async16(wd + i*16, wc + i*4);
        unsigned td = tile_s + buf * CHUNK*TSZ*4;
        for (int cc = 0; cc < CHUNK; ++cc) {
            int cin = ci*CHUNK + cc;
            bool isA = cin < csplit;
            const float* ip = isA ? (inA + (size_t)cin * H * W)
                                  : (inB + (size_t)(cin - csplit) * H * W);
            for (int i = tid; i < TSZ; i += 256) {
                int r = i / TPW, c = i % TPW;
                int iy = gy - pad + r, ix = gx - pad + c;
                bool inb = (c < TW+2) && iy >= 0 && iy < H && ix >= 0 && ix < W;
                cp_async4(td + (cc*TSZ + i)*4, inb ? (ip + (size_t)iy*W + ix) : ip, inb);
            }
        }
        cp_commit();
    };

    auto transform = [&](int ci, int buf) {
        float* tb = tile + buf * CHUNK*TSZ;
        for (int i = tid; i < CHUNK*TSZ; i += 256) {
            int cc = i / TSZ, e = i % TSZ;
            int cin = ci*CHUNK + cc;
            bool isA = cin < csplit;
            const float2* prm = isA ? prmA : prmB;
            if (!prm) continue;
            int rl = isA ? reluA : reluB;
            int r = e / TPW, c = e % TPW;
            int iy = gy - pad + r, ix = gx - pad + c;
            bool inb = (c < TW+2) && iy >= 0 && iy < H && ix >= 0 && ix < W;
            float2 p = __ldg(&prm[isA ? cin : (cin - csplit)]);
            float v = inb ? (tb[i] * p.x + p.y) : 0.f;
            if (rl) v = fmaxf(v, 0.f);
            tb[i] = v;
        }
    };

    auto compute = [&](int buf) {
        const float* tb0 = tile + buf * CHUNK*TSZ + ty * TPW + tx;
        const float* wsb = ws + buf * WCH;
#pragma unroll
        for (int cc = 0; cc < CHUNK; ++cc) {
            const float* tb = tb0 + cc * TSZ;
            const u64* wrow = (const u64*)(wsb + cc * 9 * COUT) + group * C2G;
#pragma unroll
            for (int ky = 0; ky < 3; ky++) {
#pragma unroll
                for (int kx = 0; kx < 3; kx++) {
                    u64 va = pack2(tb[ky*TPW + kx]);
                    u64 vb = pack2(tb[ky*TPW + kx + 16]);
                    if constexpr (C2G >= 2) {
                        const ulonglong2* w4 = (const ulonglong2*)(wrow + (ky*3+kx) * C2);
#pragma unroll
                        for (int p2 = 0; p2 < C2G/2; p2++) {
                            ulonglong2 w = w4[p2];
                            accA[2*p2  ] = ffma2(va, w.x, accA[2*p2  ]);
                            accB[2*p2  ] = ffma2(vb, w.x, accB[2*p2  ]);
                            accA[2*p2+1] = ffma2(va, w.y, accA[2*p2+1]);
                            accB[2*p2+1] = ffma2(vb, w.y, accB[2*p2+1]);
                        }
                    } else {
                        u64 w = wrow[(ky*3+kx) * C2];
                        accA[0] = ffma2(va, w, accA[0]);
                        accB[0] = ffma2(vb, w, accB[0]);
                    }
                }
            }
        }
    };

    prefetch(0, 0);
    for (int ci = 0; ci < NCH; ++ci) {
        int cur = ci & 1;
        if (ci + 1 < NCH) {
            prefetch(ci + 1, 1 - cur);
            cp_wait<1>();
        } else {
            cp_wait<0>();
        }
        __syncthreads();
        if (needT) { transform(ci, cur); __syncthreads(); }
        compute(cur);
        __syncthreads();
    }

    float* ob = out + (size_t)blockIdx.z * COUT * HO * WO;
    float* so = statsOut + blockIdx.z * 2 * COUT;
    const bool vA = (oy < HO) && (ox0 < WO);
    const bool vB = (oy < HO) && (ox1 < WO);
    const size_t row = (size_t)oy * WO;
#pragma unroll
    for (int p = 0; p < C2G; p++) {
        int c0 = group * COUTG + 2*p;
        float a0, a1, b0, b1;
        unpack2(accA[p], a0, a1);
        unpack2(accB[p], b0, b1);
        if (vA) {
            ob[(size_t)(c0  ) * HO * WO + row + ox0] = a0;
            ob[(size_t)(c0+1) * HO * WO + row + ox0] = a1;
        }
        if (vB) {
            ob[(size_t)(c0  ) * HO * WO + row + ox1] = b0;
            ob[(size_t)(c0+1) * HO * WO + row + ox1] = b1;
        }
        float s0 = (vA ? a0 : 0.f) + (vB ? b0 : 0.f);
        float q0 = (vA ? a0*a0 : 0.f) + (vB ? b0*b0 : 0.f);
        float s1 = (vA ? a1 : 0.f) + (vB ? b1 : 0.f);
        float q1 = (vA ? a1*a1 : 0.f) + (vB ? b1*b1 : 0.f);
#pragma unroll
        for (int o = 16; o; o >>= 1) {
            s0 += __shfl_down_sync(0xFFFFFFFFu, s0, o);
            q0 += __shfl_down_sync(0xFFFFFFFFu, q0, o);
            s1 += __shfl_down_sync(0xFFFFFFFFu, s1, o);
            q1 += __shfl_down_sync(0xFFFFFFFFu, q1, o);
        }
        if ((tid & 31) == 0) {
            atomicAdd(&sstat[2*c0  ], s0);
            atomicAdd(&sstat[2*c0+1], q0);
            atomicAdd(&sstat[2*c0+2], s1);
            atomicAdd(&sstat[2*c0+3], q1);
        }
    }
    __syncthreads();
    if (tid < 2*COUT) atomicAdd(&so[tid], sstat[tid]);
}

// ---------------- LSTM elementwise ----------------
__global__ void lstm_kernel(const float* __restrict__ prev_c, const float2* __restrict__ prm,
                            float* __restrict__ out_c, float* __restrict__ out_h)
{
    int idx = blockIdx.x * 256 + threadIdx.x;   // over 32*HW
    int c = idx >> 18;                          // HW = 2^18
    const int CHW = 32 * HW;

    float g[4];
#pragma unroll
    for (int gi = 0; gi < 4; gi++) {
        float2 p = prm[gi*32 + c];
        g[gi] = g_graw[(size_t)gi * CHW + idx] * p.x + p.y;
    }
    float f  = sigmoidf_(g[0]);
    float it = sigmoidf_(g[1]);
    float ct = tanhf(g[2]);
    float ot = sigmoidf_(g[3]);
    float nc = prev_c[idx] * f + it * ct;
    out_c[idx] = nc;
    out_h[idx] = tanhf(nc) * ot;
}

// ---------------- patch gather + per-channel dot ----------------
__global__ void gather_kernel(const int* __restrict__ holes,
                              const float* __restrict__ woil, const float* __restrict__ boil,
                              const float* __restrict__ wwat, const float* __restrict__ bwat,
                              const float* __restrict__ wgas, const float* __restrict__ bgas,
                              const float2* __restrict__ prm,
                              float* __restrict__ res)
{
    int nidx = threadIdx.x;
    if (nidx >= 256) return;
    int hx = holes[2*nidx], hy = holes[2*nidx+1];
    const float* wv[3] = { woil, wwat, wgas };
    float bv[3] = { boil[0], bwat[0], bgas[0] };
    for (int c = 0; c < 3; c++) {
        float2 p = prm[c];
        float s = bv[c];
        for (int i = 0; i < 3; i++)
            for (int j = 0; j < 3; j++) {
                float v = g_r2raw[(size_t)c * HW2 + (size_t)(hx + 3 + i) * HOB + (hy + 3 + j)];
                s += wv[c][i*3+j] * (v * p.x + p.y);
            }
        res[nidx*3 + c] = s;
    }
}

// ---------------- launch ----------------
extern "C" void kernel_launch(void* const* d_in, const int* in_sizes, int n_in,
                              void* d_out, int out_size)
{
    const float* x      = (const float*)d_in[0];
    const float* prev_c = (const float*)d_in[1];
    const float* prev_h = (const float*)d_in[2];
    const int*   holes  = (const int*)d_in[3];
    const float* w_e1   = (const float*)d_in[4];
    const float* w_e2   = (const float*)d_in[5];
    const float* w_f    = (const float*)d_in[6];
    const float* w_i    = (const float*)d_in[7];
    const float* w_c    = (const float*)d_in[8];
    const float* w_o    = (const float*)d_in[9];
    const float* w_r1   = (const float*)d_in[10];
    const float* w_r2   = (const float*)d_in[11];
    const float* w_oil  = (const float*)d_in[12];
    const float* b_oil  = (const float*)d_in[13];
    const float* w_wat  = (const float*)d_in[14];
    const float* b_wat  = (const float*)d_in[15];
    const float* w_gas  = (const float*)d_in[16];
    const float* b_gas  = (const float*)d_in[17];
    float* out = (float*)d_out;

    float *t1raw, *t2raw, *graw, *r1raw, *r2raw;
    float *wt_e1, *wt_e2, *wt_g, *wt_r1, *wt_r2, *stats;
    float2 *params;
    cudaGetSymbolAddress((void**)&t1raw, g_t1raw);
    cudaGetSymbolAddress((void**)&t2raw, g_t2raw);
    cudaGetSymbolAddress((void**)&graw,  g_graw);
    cudaGetSymbolAddress((void**)&r1raw, g_r1raw);
    cudaGetSymbolAddress((void**)&r2raw, g_r2raw);
    cudaGetSymbolAddress((void**)&wt_e1, g_wt_e1);
    cudaGetSymbolAddress((void**)&wt_e2, g_wt_e2);
    cudaGetSymbolAddress((void**)&wt_g,  g_wt_g);
    cudaGetSymbolAddress((void**)&wt_r1, g_wt_r1);
    cudaGetSymbolAddress((void**)&wt_r2, g_wt_r2);
    cudaGetSymbolAddress((void**)&stats, g_stats);
    cudaGetSymbolAddress((void**)&params, g_params);

    constexpr int TSZ = 36 * 10;
    const int SM_E1 = (2*4*9*32  + 2*4*TSZ) * 4;    // 20736
    const int SM_R2 = (2*8*9*4   + 2*8*TSZ) * 4;    // 25344
    const int SM_M32 = (32*296 + 2*8*232) * 4;       // 52736
    const int SM_M64 = (64*296 + 2*8*232) * 4;       // 90624
    cudaFuncSetAttribute((const void*)conv3x3_v8<4,32,4>,  cudaFuncAttributeMaxDynamicSharedMemorySize, SM_E1);
    cudaFuncSetAttribute((const void*)conv3x3_v8<32,4,8>,  cudaFuncAttributeMaxDynamicSharedMemorySize, SM_R2);
    cudaFuncSetAttribute((const void*)conv_mma<32>,        cudaFuncAttributeMaxDynamicSharedMemorySize, SM_M32);
    cudaFuncSetAttribute((const void*)conv_mma<64>,        cudaFuncAttributeMaxDynamicSharedMemorySize, SM_M64);

    dim3 thr(256);
    dim3 grid512(512/32, 512/8, 1);        // 16 x 64  (v8)
    dim3 gridM  (512/32, 512/4, 1);        // 16 x 128 (mma)
    dim3 gridGM (512/32, 512/4, 4);
    dim3 gridR2 ((HOB + 31)/32, (HOB + 7)/8, 1);   // 17 x 65

    // launch order: prep(1), e1(2), mp(3), e2_mma(4), mp(5), gates_mma(6 = profiled)
    prep_weights<<<(94464 + 255)/256, 256>>>(w_e1, w_e2, w_f, w_i, w_c, w_o, w_r1, w_r2);

    // e1: x (4ch, raw) -> t1raw (+stats)  [fp32 v8]
    conv3x3_v8<4,32,4><<<grid512, thr, SM_E1>>>(x, x, 4, nullptr, nullptr, 0, 0,
                                                wt_e1, t1raw, stats + 0, 512, 512, 1, 512, 512);
    make_params<<<1, 32>>>(stats + 0, params + 0, 32, 1.f / (float)HW);

    // e2: relu(BN(t1raw)) -> t2raw (+stats)  [tf32 mma]
    conv_mma<32><<<gridM, thr, SM_M32>>>(t1raw, t1raw, 32, params + 0, params + 0, 1, 1,
                                         wt_e2, t2raw, stats + 64);
    make_params<<<1, 32>>>(stats + 64, params + 32, 32, 1.f / (float)HW);

    // gates: [prev_h (raw) ; BN(t2raw)] -> graw (+stats)  [tf32 mma, profiled launch]
    conv_mma<64><<<gridGM, thr, SM_M64>>>(prev_h, t2raw, 32, nullptr, params + 32, 0, 0,
                                          wt_g, graw, stats + 128);
    make_params<<<1, 128>>>(stats + 128, params + 64, 128, 1.f / (float)HW);

    // LSTM -> out[0:32HW]=next_c, out[32HW:64HW]=next_h
    lstm_kernel<<<32*HW/256, 256>>>(prev_c, params + 64, out, out + 32*HW);

    // r1: next_h (raw) -> r1raw (+stats)  [tf32 mma]
    conv_mma<32><<<gridM, thr, SM_M32>>>(out + 32*HW, out + 32*HW, 32, nullptr, nullptr, 0, 0,
                                         wt_r1, r1raw, stats + 384);
    make_params<<<1, 32>>>(stats + 384, params + 192, 32, 1.f / (float)HW);

    // r2: relu(BN(r1raw)) -> r2raw (3+1 ch @ 518x518, pad 4) (+stats)  [fp32 v8]
    conv3x3_v8<32,4,8><<<gridR2, thr, SM_R2>>>(r1raw, r1raw, 32, params + 192, params + 192, 1, 1,
                                               wt_r2, r2raw, stats + 448, 512, 512, 4, HOB, HOB);
    make_params<<<1, 32>>>(stats + 448, params + 224, 4, 1.f / (float)HW2);

    // gather + dot -> out tail
    gather_kernel<<<1, 256>>>(holes, w_oil, b_oil, w_wat, b_wat, w_gas, b_gas, params + 224, out + 64*HW);
}

// round 13
// speedup vs baseline: 2.0055x; 1.4828x over previous
#include <cuda_runtime.h>

#define HPX 512
#define WPX 512
#define HW  (HPX*WPX)           // 262144 = 2^18
#define HOB 518                 // r2 output side (512 + 2*4 - 2)
#define HW2 (HOB*HOB)           // 268324

typedef unsigned long long u64;

// ---------------- device scratch (no cudaMalloc allowed) ----------------
__device__ float g_t1raw[32*HW];
__device__ float g_t2raw[32*HW];
__device__ float g_graw [128*HW];
__device__ float g_r1raw[32*HW];
__device__ float g_r2raw[4*HW2];
__device__ __align__(16) float g_wt_e1[4*9*32];
__device__ __align__(16) float g_wt_e2[32*9*32];     // [cin32][k9][cout32], tf32-rounded
__device__ __align__(16) float g_wt_g [4*64*9*32];   // [z4][cin64][k9][cout32], tf32-rounded
__device__ __align__(16) float g_wt_r1[32*9*32];     // [cin32][k9][cout32], tf32-rounded
__device__ __align__(16) float g_wt_r2[32*9*4];
__device__ float  g_stats[512];    // e1:[0,64) e2:[64,128) gates:[128,384) r1:[384,448) r2:[448,456)
__device__ float2 g_params[256];   // e1:0 e2:32 gates:64 r1:192 r2:224   (scale, bias)

// ---------------- f32x2 / cp.async helpers ----------------
__device__ __forceinline__ u64 pack2(float x) {
    unsigned u = __float_as_uint(x);
    u64 r;
    asm("mov.b64 %0, {%1, %2};" : "=l"(r) : "r"(u), "r"(u));
    return r;
}
__device__ __forceinline__ u64 ffma2(u64 a, u64 b, u64 c) {
    u64 d;
    asm("fma.rn.f32x2 %0, %1, %2, %3;" : "=l"(d) : "l"(a), "l"(b), "l"(c));
    return d;
}
__device__ __forceinline__ void unpack2(u64 v, float& lo, float& hi) {
    unsigned a, b;
    asm("mov.b64 {%0, %1}, %2;" : "=r"(a), "=r"(b) : "l"(v));
    lo = __uint_as_float(a); hi = __uint_as_float(b);
}
__device__ __forceinline__ float sigmoidf_(float x) { return 1.f / (1.f + expf(-x)); }

__device__ __forceinline__ void cp_async4(unsigned dst, const void* src, bool pred) {
    int bytes = pred ? 4 : 0;
    asm volatile("cp.async.ca.shared.global [%0], [%1], 4, %2;"
                 :: "r"(dst), "l"(src), "r"(bytes));
}
__device__ __forceinline__ void cp_async16(unsigned dst, const void* src) {
    asm volatile("cp.async.cg.shared.global [%0], [%1], 16;" :: "r"(dst), "l"(src));
}
__device__ __forceinline__ void cp_commit() {
    asm volatile("cp.async.commit_group;");
}
template<int N>
__device__ __forceinline__ void cp_wait() {
    asm volatile("cp.async.wait_group %0;" :: "n"(N));
}
__device__ __forceinline__ unsigned to_tf32(float v) {
    unsigned u;
    asm("cvt.rna.tf32.f32 %0, %1;" : "=r"(u) : "f"(v));
    return u;
}
__device__ __forceinline__ void mma_tf32(float* c, unsigned a0, unsigned a1, unsigned a2,
                                         unsigned a3, unsigned b0, unsigned b1) {
    asm volatile("mma.sync.aligned.m16n8k8.row.col.f32.tf32.tf32.f32 "
                 "{%0,%1,%2,%3}, {%4,%5,%6,%7}, {%8,%9}, {%0,%1,%2,%3};"
                 : "+f"(c[0]), "+f"(c[1]), "+f"(c[2]), "+f"(c[3])
                 : "r"(a0), "r"(a1), "r"(a2), "r"(a3), "r"(b0), "r"(b1));
}

// ------ weight prep (+ stats zeroing); mma weights pre-rounded to tf32 (rna) ------
__global__ void prep_weights(const float* __restrict__ we1, const float* __restrict__ we2,
                             const float* __restrict__ wf,  const float* __restrict__ wi,
                             const float* __restrict__ wc,  const float* __restrict__ wo,
                             const float* __restrict__ wr1, const float* __restrict__ wr2)
{
    int idx = blockIdx.x * 256 + threadIdx.x;
    if (idx < 512) g_stats[idx] = 0.f;
    if (idx < 1152) {
        int cout = idx % 32, t = idx / 32, k = t % 9, cin = t / 9;
        g_wt_e1[idx] = we1[cout*4*9 + cin*9 + k];
        return;
    }
    idx -= 1152;
    if (idx < 9216) {
        int cout = idx % 32, t = idx / 32, k = t % 9, cin = t / 9;
        g_wt_e2[idx] = __uint_as_float(to_tf32(we2[cout*32*9 + cin*9 + k]));
        return;
    }
    idx -= 9216;
    if (idx < 4*18432) {
        int g = idx / 18432, d = idx % 18432;
        int cout = d % 32, t = d / 32, k = t % 9, cin = t / 9;
        const float* src = (g == 0) ? wf : (g == 1) ? wi : (g == 2) ? wc : wo;
        g_wt_g[idx] = __uint_as_float(to_tf32(src[cout*64*9 + cin*9 + k]));
        return;
    }
    idx -= 4*18432;
    if (idx < 9216) {
        int cout = idx % 32, t = idx / 32, k = t % 9, cin = t / 9;
        g_wt_r1[idx] = __uint_as_float(to_tf32(wr1[cout*32*9 + cin*9 + k]));
        return;
    }
    idx -= 9216;
    if (idx < 1152) {
        int cout = idx % 4, t = idx / 4, k = t % 9, cin = t / 9;
        g_wt_r2[idx] = (cout < 3) ? wr2[cout*32*9 + cin*9 + k] : 0.f;
        return;
    }
}

// stats (sum, sumsq) -> params (scale, bias)
__global__ void make_params(const float* __restrict__ stats, float2* __restrict__ params,
                            int nch, float invn)
{
    int c = threadIdx.x;
    if (c >= nch) return;
    float m   = stats[2*c] * invn;
    float var = stats[2*c+1] * invn - m * m;
    float sc  = rsqrtf(var + 1e-5f);
    params[c] = make_float2(sc, -m * sc);
}

// ---------------- generic 3x3 conv via tf32 mma (register-pipelined, single tile buffer) ------
// Block: 32x4 output pixels x 32 couts; blockIdx.z = weight slice. 8 warps, warp -> 16-px mtile.
// Per group g (8 cins): STS (regs -> tile, BN+cvt fused) -> LDG group g+1 into regs -> compute.
// Slot state (smem off, gmem off, inb, plane) precomputed once in the prologue.
template<int CIN>
__global__ void __launch_bounds__(256, 2)
conv_mma(const float* __restrict__ inA, const float* __restrict__ inB, int csplit,
         const float2* __restrict__ prmA, const float2* __restrict__ prmB,
         int reluA, int reluB,
         const float* __restrict__ wt, float* __restrict__ out, float* __restrict__ statsOut)
{
    constexpr int PS = 232;     // tile plane stride floats (232 % 32 == 8 -> conflict-free A)
    constexpr int WS = 296;     // weight cin stride floats (296 % 32 == 8 -> conflict-free B)
    constexpr int TEL = 204;    // live elems per plane (34 x 6)
    constexpr int NG = CIN / 8;
    constexpr int NEL = 8 * TEL;            // 1632 elements per group
    constexpr int NSLOT = (NEL + 255) / 256; // 7
    extern __shared__ float smem[];
    float* wsh  = smem;                     // CIN * WS
    float* tile = smem + CIN*WS;            // 8 * PS (single buffer)
    __shared__ float2 spar[CIN];
    __shared__ float sstat[64];

    const int tid  = threadIdx.x;
    const int warp = tid >> 5, lane = tid & 31;
    const int gid  = lane >> 2, tig = lane & 3;
    if (tid < 64) sstat[tid] = 0.f;
    if (tid < CIN) {
        bool isA = tid < csplit;
        const float2* pr = isA ? prmA : prmB;
        spar[tid] = pr ? __ldg(&pr[isA ? tid : tid - csplit]) : make_float2(1.f, 0.f);
    }

    const int gx = blockIdx.x * 32, gy = blockIdx.y * 4;
    const float* wsrc = wt + (size_t)blockIdx.z * (CIN*9*32);
    const unsigned wsh_s = (unsigned)__cvta_generic_to_shared(wsh);

    float acc[4][4];
#pragma unroll
    for (int j = 0; j < 4; j++)
#pragma unroll
        for (int e = 0; e < 4; e++) acc[j][e] = 0.f;

    // stage all weights (already tf32-rounded) once
    for (int i = tid; i < CIN*72; i += 256) {
        int cin = i / 72, off = i % 72;
        cp_async16(wsh_s + (cin*WS + off*4)*4, wsrc + cin*288 + off*4);
    }
    cp_commit();

    // ---- precompute per-slot state (loop-invariant across groups) ----
    const int nslot = (tid < (NEL & 255)) ? NSLOT : NSLOT - 1;
    int so_[NSLOT];     // smem offset within tile
    int go_[NSLOT];     // global offset: pl*HW + iy*512 + ix
    int pl_[NSLOT];     // plane (cin within group)
    bool ib_[NSLOT];
#pragma unroll
    for (int j = 0; j < NSLOT; j++) {
        int i = tid + j*256;
        if (j < nslot) {
            int pl = i / TEL, rem = i % TEL;
            int r = rem / 34, c = rem % 34;
            int iy = gy - 1 + r, ix = gx - 1 + c;
            so_[j] = pl*PS + r*34 + c;
            go_[j] = pl*HW + iy*512 + ix;
            pl_[j] = pl;
            ib_[j] = iy >= 0 && iy < 512 && ix >= 0 && ix < 512;
        }
    }

    float vreg[NSLOT];
    auto loadg = [&](int g) {
        int cin0 = g*8;
        bool isA = cin0 < csplit;
        const float* bp = isA ? (inA + (size_t)cin0 * HW)
                              : (inB + (size_t)(cin0 - csplit) * HW);
#pragma unroll
        for (int j = 0; j < NSLOT; j++)
            if (j < nslot) vreg[j] = ib_[j] ? __ldg(bp + go_[j]) : 0.f;
    };

    auto stores = [&](int g) {
        int cin0 = g*8;
        bool isA = cin0 < csplit;
        int rl = isA ? reluA : reluB;
#pragma unroll
        for (int j = 0; j < NSLOT; j++) {
            if (j < nslot) {
                float2 p = spar[cin0 + pl_[j]];
                float v = ib_[j] ? (vreg[j] * p.x + p.y) : 0.f;
                if (rl) v = fmaxf(v, 0.f);
                ((unsigned*)tile)[so_[j]] = to_tf32(v);
            }
        }
    };

    auto compute = [&](int g) {
        const unsigned* tb = (const unsigned*)tile;
        const unsigned* wb = (const unsigned*)wsh + g*8*WS;
        const int py = warp >> 1, pxb = (warp & 1) * 16;
#pragma unroll
        for (int ky = 0; ky < 3; ky++) {
#pragma unroll
            for (int kx = 0; kx < 3; kx++) {
                int ro = (py + ky) * 34 + pxb + kx;
                unsigned a0 = tb[ tig    * PS + ro + gid    ];
                unsigned a1 = tb[ tig    * PS + ro + gid + 8];
                unsigned a2 = tb[(tig+4) * PS + ro + gid    ];
                unsigned a3 = tb[(tig+4) * PS + ro + gid + 8];
                const unsigned* wk0 = wb + tig    *WS + (ky*3+kx)*32 + gid;
                const unsigned* wk4 = wb + (tig+4)*WS + (ky*3+kx)*32 + gid;
#pragma unroll
                for (int j = 0; j < 4; j++)
                    mma_tf32(acc[j], a0, a1, a2, a3, wk0[8*j], wk4[8*j]);
            }
        }
    };

    loadg(0);
    cp_wait<0>();          // weights landed
    __syncthreads();       // weights + spar visible
    for (int g = 0; g < NG; ++g) {
        stores(g);
        if (g + 1 < NG) loadg(g + 1);
        __syncthreads();   // tile(g) visible
        compute(g);
        if (g + 1 < NG) __syncthreads();   // readers done before next stores
    }

    // ---- epilogue: store + fused stats (all pixels valid: 512 divides exactly) ----
    float* ob = out + (size_t)blockIdx.z * 32 * HW;
    const int py = warp >> 1, pxb = (warp & 1) * 16;
    const int oy = gy + py;
    const size_t row = (size_t)oy * 512 + gx + pxb;
#pragma unroll
    for (int j = 0; j < 4; j++) {
        int n0 = 8*j + 2*tig;
        ob[(size_t)(n0  ) * HW + row + gid    ] = acc[j][0];
        ob[(size_t)(n0+1) * HW + row + gid    ] = acc[j][1];
        ob[(size_t)(n0  ) * HW + row + gid + 8] = acc[j][2];
        ob[(size_t)(n0+1) * HW + row + gid + 8] = acc[j][3];
        float s0 = acc[j][0] + acc[j][2];
        float q0 = acc[j][0]*acc[j][0] + acc[j][2]*acc[j][2];
        float s1 = acc[j][1] + acc[j][3];
        float q1 = acc[j][1]*acc[j][1] + acc[j][3]*acc[j][3];
#pragma unroll
        for (int o = 16; o >= 4; o >>= 1) {
            s0 += __shfl_down_sync(0xFFFFFFFFu, s0, o);
            q0 += __shfl_down_sync(0xFFFFFFFFu, q0, o);
            s1 += __shfl_down_sync(0xFFFFFFFFu, s1, o);
            q1 += __shfl_down_sync(0xFFFFFFFFu, q1, o);
        }
        if (gid == 0) {
            atomicAdd(&sstat[2*n0    ], s0);
            atomicAdd(&sstat[2*n0 + 1], q0);
            atomicAdd(&sstat[2*n0 + 2], s1);
            atomicAdd(&sstat[2*n0 + 3], q1);
        }
    }
    __syncthreads();
    if (tid < 64) atomicAdd(&statsOut[blockIdx.z*64 + tid], sstat[tid]);
}

// ---------------- 3x3 conv v8 (e1, r2) --------------------------------------------------------
template<int CIN, int COUT, int CHUNK>
__global__ void __launch_bounds__(256, 4)
conv3x3_v8(const float* __restrict__ inA, const float* __restrict__ inB, int csplit,
           const float2* __restrict__ prmA, const float2* __restrict__ prmB,
           int reluA, int reluB,
           const float* __restrict__ wt, float* __restrict__ out, float* __restrict__ statsOut,
           int H, int W, int pad, int HO, int WO)
{
    constexpr int TW = 32, TPW = 36, TPH = 10;
    constexpr int TSZ = TPW * TPH;
    constexpr int NCH = CIN / CHUNK;
    constexpr int WCH = CHUNK * 9 * COUT;
    constexpr int COUTG = COUT / 2;
    constexpr int C2G = COUTG / 2;
    constexpr int C2  = COUT / 2;
    extern __shared__ float smem[];
    float* ws   = smem;
    float* tile = smem + 2*WCH;
    __shared__ float sstat[2*COUT];

    const int tid   = threadIdx.x;
    const int group = tid >> 7;
    const int tx    = tid & 15;
    const int ty    = (tid >> 4) & 7;
    if (tid < 2*COUT) sstat[tid] = 0.f;

    const int gx = blockIdx.x * TW, gy = blockIdx.y * 8;
    const int oy = gy + ty;
    const int ox0 = gx + tx, ox1 = ox0 + 16;
    const float* wsrc = wt + (size_t)blockIdx.z * (CIN*9*COUT);

    const unsigned ws_s   = (unsigned)__cvta_generic_to_shared(ws);
    const unsigned tile_s = (unsigned)__cvta_generic_to_shared(tile);
    const bool needT = (prmA != nullptr && csplit > 0) || (prmB != nullptr && csplit < CIN);

    u64 accA[C2G], accB[C2G];
#pragma unroll
    for (int p = 0; p < C2G; p++) { accA[p] = 0ull; accB[p] = 0ull; }

    auto prefetch = [&](int ci, int buf) {
        const float* wc = wsrc + (size_t)ci * WCH;
        unsigned wd = ws_s + buf * WCH * 4;
        for (int i = tid; i < WCH/4; i += 256)
            cp_async16(wd + i*16, wc + i*4);
        unsigned td = tile_s + buf * CHUNK*TSZ*4;
        for (int cc = 0; cc < CHUNK; ++cc) {
            int cin = ci*CHUNK + cc;
            bool isA = cin < csplit;
            const float* ip = isA ? (inA + (size_t)cin * H * W)
                                  : (inB + (size_t)(cin - csplit) * H * W);
            for (int i = tid; i < TSZ; i += 256) {
                int r = i / TPW, c = i % TPW;
                int iy = gy - pad + r, ix = gx - pad + c;
                bool inb = (c < TW+2) && iy >= 0 && iy < H && ix >= 0 && ix < W;
                cp_async4(td + (cc*TSZ + i)*4, inb ? (ip + (size_t)iy*W + ix) : ip, inb);
            }
        }
        cp_commit();
    };

    auto transform = [&](int ci, int buf) {
        float* tb = tile + buf * CHUNK*TSZ;
        for (int i = tid; i < CHUNK*TSZ; i += 256) {
            int cc = i / TSZ, e = i % TSZ;
            int cin = ci*CHUNK + cc;
            bool isA = cin < csplit;
            const float2* prm = isA ? prmA : prmB;
            if (!prm) continue;
            int rl = isA ? reluA : reluB;
            int r = e / TPW, c = e % TPW;
            int iy = gy - pad + r, ix = gx - pad + c;
            bool inb = (c < TW+2) && iy >= 0 && iy < H && ix >= 0 && ix < W;
            float2 p = __ldg(&prm[isA ? cin : (cin - csplit)]);
            float v = inb ? (tb[i] * p.x + p.y) : 0.f;
            if (rl) v = fmaxf(v, 0.f);
            tb[i] = v;
        }
    };

    auto compute = [&](int buf) {
        const float* tb0 = tile + buf * CHUNK*TSZ + ty * TPW + tx;
        const float* wsb = ws + buf * WCH;
#pragma unroll
        for (int cc = 0; cc < CHUNK; ++cc) {
            const float* tb = tb0 + cc * TSZ;
            const u64* wrow = (const u64*)(wsb + cc * 9 * COUT) + group * C2G;
#pragma unroll
            for (int ky = 0; ky < 3; ky++) {
#pragma unroll
                for (int kx = 0; kx < 3; kx++) {
                    u64 va = pack2(tb[ky*TPW + kx]);
                    u64 vb = pack2(tb[ky*TPW + kx + 16]);
                    if constexpr (C2G >= 2) {
                        const ulonglong2* w4 = (const ulonglong2*)(wrow + (ky*3+kx) * C2);
#pragma unroll
                        for (int p2 = 0; p2 < C2G/2; p2++) {
                            ulonglong2 w = w4[p2];
                            accA[2*p2  ] = ffma2(va, w.x, accA[2*p2  ]);
                            accB[2*p2  ] = ffma2(vb, w.x, accB[2*p2  ]);
                            accA[2*p2+1] = ffma2(va, w.y, accA[2*p2+1]);
                            accB[2*p2+1] = ffma2(vb, w.y, accB[2*p2+1]);
                        }
                    } else {
                        u64 w = wrow[(ky*3+kx) * C2];
                        accA[0] = ffma2(va, w, accA[0]);
                        accB[0] = ffma2(vb, w, accB[0]);
                    }
                }
            }
        }
    };

    prefetch(0, 0);
    for (int ci = 0; ci < NCH; ++ci) {
        int cur = ci & 1;
        if (ci + 1 < NCH) {
            prefetch(ci + 1, 1 - cur);
            cp_wait<1>();
        } else {
            cp_wait<0>();
        }
        __syncthreads();
        if (needT) { transform(ci, cur); __syncthreads(); }
        compute(cur);
        __syncthreads();
    }

    float* ob = out + (size_t)blockIdx.z * COUT * HO * WO;
    float* so = statsOut + blockIdx.z * 2 * COUT;
    const bool vA = (oy < HO) && (ox0 < WO);
    const bool vB = (oy < HO) && (ox1 < WO);
    const size_t row = (size_t)oy * WO;
#pragma unroll
    for (int p = 0; p < C2G; p++) {
        int c0 = group * COUTG + 2*p;
        float a0, a1, b0, b1;
        unpack2(accA[p], a0, a1);
        unpack2(accB[p], b0, b1);
        if (vA) {
            ob[(size_t)(c0  ) * HO * WO + row + ox0] = a0;
            ob[(size_t)(c0+1) * HO * WO + row + ox0] = a1;
        }
        if (vB) {
            ob[(size_t)(c0  ) * HO * WO + row + ox1] = b0;
            ob[(size_t)(c0+1) * HO * WO + row + ox1] = b1;
        }
        float s0 = (vA ? a0 : 0.f) + (vB ? b0 : 0.f);
        float q0 = (vA ? a0*a0 : 0.f) + (vB ? b0*b0 : 0.f);
        float s1 = (vA ? a1 : 0.f) + (vB ? b1 : 0.f);
        float q1 = (vA ? a1*a1 : 0.f) + (vB ? b1*b1 : 0.f);
#pragma unroll
        for (int o = 16; o; o >>= 1) {
            s0 += __shfl_down_sync(0xFFFFFFFFu, s0, o);
            q0 += __shfl_down_sync(0xFFFFFFFFu, q0, o);
            s1 += __shfl_down_sync(0xFFFFFFFFu, s1, o);
            q1 += __shfl_down_sync(0xFFFFFFFFu, q1, o);
        }
        if ((tid & 31) == 0) {
            atomicAdd(&sstat[2*c0  ], s0);
            atomicAdd(&sstat[2*c0+1], q0);
            atomicAdd(&sstat[2*c0+2], s1);
            atomicAdd(&sstat[2*c0+3], q1);
        }
    }
    __syncthreads();
    if (tid < 2*COUT) atomicAdd(&so[tid], sstat[tid]);
}

// ---------------- LSTM elementwise ----------------
__global__ void lstm_kernel(const float* __restrict__ prev_c, const float2* __restrict__ prm,
                            float* __restrict__ out_c, float* __restrict__ out_h)
{
    int idx = blockIdx.x * 256 + threadIdx.x;   // over 32*HW
    int c = idx >> 18;                          // HW = 2^18
    const int CHW = 32 * HW;

    float g[4];
#pragma unroll
    for (int gi = 0; gi < 4; gi++) {
        float2 p = prm[gi*32 + c];
        g[gi] = g_graw[(size_t)gi * CHW + idx] * p.x + p.y;
    }
    float f  = sigmoidf_(g[0]);
    float it = sigmoidf_(g[1]);
    float ct = tanhf(g[2]);
    float ot = sigmoidf_(g[3]);
    float nc = prev_c[idx] * f + it * ct;
    out_c[idx] = nc;
    out_h[idx] = tanhf(nc) * ot;
}

// ---------------- patch gather + per-channel dot ----------------
__global__ void gather_kernel(const int* __restrict__ holes,
                              const float* __restrict__ woil, const float* __restrict__ boil,
                              const float* __restrict__ wwat, const float* __restrict__ bwat,
                              const float* __restrict__ wgas, const float* __restrict__ bgas,
                              const float2* __restrict__ prm,
                              float* __restrict__ res)
{
    int nidx = threadIdx.x;
    if (nidx >= 256) return;
    int hx = holes[2*nidx], hy = holes[2*nidx+1];
    const float* wv[3] = { woil, wwat, wgas };
    float bv[3] = { boil[0], bwat[0], bgas[0] };
    for (int c = 0; c < 3; c++) {
        float2 p = prm[c];
        float s = bv[c];
        for (int i = 0; i < 3; i++)
            for (int j = 0; j < 3; j++) {
                float v = g_r2raw[(size_t)c * HW2 + (size_t)(hx + 3 + i) * HOB + (hy + 3 + j)];
                s += wv[c][i*3+j] * (v * p.x + p.y);
            }
        res[nidx*3 + c] = s;
    }
}

// ---------------- launch ----------------
extern "C" void kernel_launch(void* const* d_in, const int* in_sizes, int n_in,
                              void* d_out, int out_size)
{
    const float* x      = (const float*)d_in[0];
    const float* prev_c = (const float*)d_in[1];
    const float* prev_h = (const float*)d_in[2];
    const int*   holes  = (const int*)d_in[3];
    const float* w_e1   = (const float*)d_in[4];
    const float* w_e2   = (const float*)d_in[5];
    const float* w_f    = (const float*)d_in[6];
    const float* w_i    = (const float*)d_in[7];
    const float* w_c    = (const float*)d_in[8];
    const float* w_o    = (const float*)d_in[9];
    const float* w_r1   = (const float*)d_in[10];
    const float* w_r2   = (const float*)d_in[11];
    const float* w_oil  = (const float*)d_in[12];
    const float* b_oil  = (const float*)d_in[13];
    const float* w_wat  = (const float*)d_in[14];
    const float* b_wat  = (const float*)d_in[15];
    const float* w_gas  = (const float*)d_in[16];
    const float* b_gas  = (const float*)d_in[17];
    float* out = (float*)d_out;

    float *t1raw, *t2raw, *graw, *r1raw, *r2raw;
    float *wt_e1, *wt_e2, *wt_g, *wt_r1, *wt_r2, *stats;
    float2 *params;
    cudaGetSymbolAddress((void**)&t1raw, g_t1raw);
    cudaGetSymbolAddress((void**)&t2raw, g_t2raw);
    cudaGetSymbolAddress((void**)&graw,  g_graw);
    cudaGetSymbolAddress((void**)&r1raw, g_r1raw);
    cudaGetSymbolAddress((void**)&r2raw, g_r2raw);
    cudaGetSymbolAddress((void**)&wt_e1, g_wt_e1);
    cudaGetSymbolAddress((void**)&wt_e2, g_wt_e2);
    cudaGetSymbolAddress((void**)&wt_g,  g_wt_g);
    cudaGetSymbolAddress((void**)&wt_r1, g_wt_r1);
    cudaGetSymbolAddress((void**)&wt_r2, g_wt_r2);
    cudaGetSymbolAddress((void**)&stats, g_stats);
    cudaGetSymbolAddress((void**)&params, g_params);

    constexpr int TSZ = 36 * 10;
    const int SM_E1 = (2*4*9*32  + 2*4*TSZ) * 4;    // 20736
    const int SM_R2 = (2*8*9*4   + 2*8*TSZ) * 4;    // 25344
    const int SM_M32 = (32*296 + 8*232) * 4;         // 45312
    const int SM_M64 = (64*296 + 8*232) * 4;         // 83200
    cudaFuncSetAttribute((const void*)conv3x3_v8<4,32,4>,  cudaFuncAttributeMaxDynamicSharedMemorySize, SM_E1);
    cudaFuncSetAttribute((const void*)conv3x3_v8<32,4,8>,  cudaFuncAttributeMaxDynamicSharedMemorySize, SM_R2);
    cudaFuncSetAttribute((const void*)conv_mma<32>,        cudaFuncAttributeMaxDynamicSharedMemorySize, SM_M32);
    cudaFuncSetAttribute((const void*)conv_mma<64>,        cudaFuncAttributeMaxDynamicSharedMemorySize, SM_M64);

    dim3 thr(256);
    dim3 grid512(512/32, 512/8, 1);        // 16 x 64  (v8)
    dim3 gridM  (512/32, 512/4, 1);        // 16 x 128 (mma)
    dim3 gridGM (512/32, 512/4, 4);
    dim3 gridR2 ((HOB + 31)/32, (HOB + 7)/8, 1);   // 17 x 65

    // launch order: prep(1), e1(2), mp(3), e2_mma(4), mp(5), gates_mma(6 = profiled)
    prep_weights<<<(94464 + 255)/256, 256>>>(w_e1, w_e2, w_f, w_i, w_c, w_o, w_r1, w_r2);

    // e1: x (4ch, raw) -> t1raw (+stats)  [fp32 v8]
    conv3x3_v8<4,32,4><<<grid512, thr, SM_E1>>>(x, x, 4, nullptr, nullptr, 0, 0,
                                                wt_e1, t1raw, stats + 0, 512, 512, 1, 512, 512);
    make_params<<<1, 32>>>(stats + 0, params + 0, 32, 1.f / (float)HW);

    // e2: relu(BN(t1raw)) -> t2raw (+stats)  [tf32 mma]
    conv_mma<32><<<gridM, thr, SM_M32>>>(t1raw, t1raw, 32, params + 0, params + 0, 1, 1,
                                         wt_e2, t2raw, stats + 64);
    make_params<<<1, 32>>>(stats + 64, params + 32, 32, 1.f / (float)HW);

    // gates: [prev_h (raw) ; BN(t2raw)] -> graw (+stats)  [tf32 mma, profiled launch]
    conv_mma<64><<<gridGM, thr, SM_M64>>>(prev_h, t2raw, 32, nullptr, params + 32, 0, 0,
                                          wt_g, graw, stats + 128);
    make_params<<<1, 128>>>(stats + 128, params + 64, 128, 1.f / (float)HW);

    // LSTM -> out[0:32HW]=next_c, out[32HW:64HW]=next_h
    lstm_kernel<<<32*HW/256, 256>>>(prev_c, params + 64, out, out + 32*HW);

    // r1: next_h (raw) -> r1raw (+stats)  [tf32 mma]
    conv_mma<32><<<gridM, thr, SM_M32>>>(out + 32*HW, out + 32*HW, 32, nullptr, nullptr, 0, 0,
                                         wt_r1, r1raw, stats + 384);
    make_params<<<1, 32>>>(stats + 384, params + 192, 32, 1.f / (float)HW);

    // r2: relu(BN(r1raw)) -> r2raw (3+1 ch @ 518x518, pad 4) (+stats)  [fp32 v8]
    conv3x3_v8<32,4,8><<<gridR2, thr, SM_R2>>>(r1raw, r1raw, 32, params + 192, params + 192, 1, 1,
                                               wt_r2, r2raw, stats + 448, 512, 512, 4, HOB, HOB);
    make_params<<<1, 32>>>(stats + 448, params + 224, 4, 1.f / (float)HW2);

    // gather + dot -> out tail
    gather_kernel<<<1, 256>>>(holes, w_oil, b_oil, w_wat, b_wat, w_gas, b_gas, params + 224, out + 64*HW);
}

// round 14
// speedup vs baseline: 2.0291x; 1.0117x over previous
#include <cuda_runtime.h>

#define HPX 512
#define WPX 512
#define HW  (HPX*WPX)           // 262144 = 2^18
#define HOB 518                 // r2 output side (512 + 2*4 - 2)
#define HW2 (HOB*HOB)           // 268324

typedef unsigned long long u64;

// ---------------- device scratch (no cudaMalloc allowed) ----------------
__device__ float g_t1raw[32*HW];
__device__ float g_t2raw[32*HW];
__device__ float g_graw [128*HW];
__device__ float g_r1raw[32*HW];
__device__ float g_r2raw[4*HW2];
__device__ __align__(16) float g_wt_e1[4*9*32];
__device__ __align__(16) float g_wt_e2[32*9*32];     // [cin32][k9][cout32], tf32-rounded
__device__ __align__(16) float g_wt_g [4*64*9*32];   // [z4][cin64][k9][cout32], tf32-rounded
__device__ __align__(16) float g_wt_r1[32*9*32];     // [cin32][k9][cout32], tf32-rounded
__device__ __align__(16) float g_wt_r2[32*9*4];
__device__ float  g_stats[512];    // e1:[0,64) e2:[64,128) gates:[128,384) r1:[384,448) r2:[448,456)
__device__ float2 g_params[256];   // e1:0 e2:32 gates:64 r1:192 r2:224   (scale, bias)

// ---------------- f32x2 / cp.async helpers ----------------
__device__ __forceinline__ u64 pack2(float x) {
    unsigned u = __float_as_uint(x);
    u64 r;
    asm("mov.b64 %0, {%1, %2};" : "=l"(r) : "r"(u), "r"(u));
    return r;
}
__device__ __forceinline__ u64 ffma2(u64 a, u64 b, u64 c) {
    u64 d;
    asm("fma.rn.f32x2 %0, %1, %2, %3;" : "=l"(d) : "l"(a), "l"(b), "l"(c));
    return d;
}
__device__ __forceinline__ void unpack2(u64 v, float& lo, float& hi) {
    unsigned a, b;
    asm("mov.b64 {%0, %1}, %2;" : "=r"(a), "=r"(b) : "l"(v));
    lo = __uint_as_float(a); hi = __uint_as_float(b);
}
__device__ __forceinline__ float sigmoidf_(float x) { return 1.f / (1.f + expf(-x)); }

__device__ __forceinline__ void cp_async4(unsigned dst, const void* src, bool pred) {
    int bytes = pred ? 4 : 0;
    asm volatile("cp.async.ca.shared.global [%0], [%1], 4, %2;"
                 :: "r"(dst), "l"(src), "r"(bytes));
}
__device__ __forceinline__ void cp_async16(unsigned dst, const void* src) {
    asm volatile("cp.async.cg.shared.global [%0], [%1], 16;" :: "r"(dst), "l"(src));
}
__device__ __forceinline__ void cp_commit() {
    asm volatile("cp.async.commit_group;");
}
template<int N>
__device__ __forceinline__ void cp_wait() {
    asm volatile("cp.async.wait_group %0;" :: "n"(N));
}
__device__ __forceinline__ unsigned to_tf32(float v) {
    unsigned u;
    asm("cvt.rna.tf32.f32 %0, %1;" : "=r"(u) : "f"(v));
    return u;
}
__device__ __forceinline__ void mma_tf32(float* c, unsigned a0, unsigned a1, unsigned a2,
                                         unsigned a3, unsigned b0, unsigned b1) {
    asm volatile("mma.sync.aligned.m16n8k8.row.col.f32.tf32.tf32.f32 "
                 "{%0,%1,%2,%3}, {%4,%5,%6,%7}, {%8,%9}, {%0,%1,%2,%3};"
                 : "+f"(c[0]), "+f"(c[1]), "+f"(c[2]), "+f"(c[3])
                 : "r"(a0), "r"(a1), "r"(a2), "r"(a3), "r"(b0), "r"(b1));
}

// ------ weight prep (+ stats zeroing); mma weights pre-rounded to tf32 (rna) ------
__global__ void prep_weights(const float* __restrict__ we1, const float* __restrict__ we2,
                             const float* __restrict__ wf,  const float* __restrict__ wi,
                             const float* __restrict__ wc,  const float* __restrict__ wo,
                             const float* __restrict__ wr1, const float* __restrict__ wr2)
{
    int idx = blockIdx.x * 256 + threadIdx.x;
    if (idx < 512) g_stats[idx] = 0.f;
    if (idx < 1152) {
        int cout = idx % 32, t = idx / 32, k = t % 9, cin = t / 9;
        g_wt_e1[idx] = we1[cout*4*9 + cin*9 + k];
        return;
    }
    idx -= 1152;
    if (idx < 9216) {
        int cout = idx % 32, t = idx / 32, k = t % 9, cin = t / 9;
        g_wt_e2[idx] = __uint_as_float(to_tf32(we2[cout*32*9 + cin*9 + k]));
        return;
    }
    idx -= 9216;
    if (idx < 4*18432) {
        int g = idx / 18432, d = idx % 18432;
        int cout = d % 32, t = d / 32, k = t % 9, cin = t / 9;
        const float* src = (g == 0) ? wf : (g == 1) ? wi : (g == 2) ? wc : wo;
        g_wt_g[idx] = __uint_as_float(to_tf32(src[cout*64*9 + cin*9 + k]));
        return;
    }
    idx -= 4*18432;
    if (idx < 9216) {
        int cout = idx % 32, t = idx / 32, k = t % 9, cin = t / 9;
        g_wt_r1[idx] = __uint_as_float(to_tf32(wr1[cout*32*9 + cin*9 + k]));
        return;
    }
    idx -= 9216;
    if (idx < 1152) {
        int cout = idx % 4, t = idx / 4, k = t % 9, cin = t / 9;
        g_wt_r2[idx] = (cout < 3) ? wr2[cout*32*9 + cin*9 + k] : 0.f;
        return;
    }
}

// stats (sum, sumsq) -> params (scale, bias)
__global__ void make_params(const float* __restrict__ stats, float2* __restrict__ params,
                            int nch, float invn)
{
    int c = threadIdx.x;
    if (c >= nch) return;
    float m   = stats[2*c] * invn;
    float var = stats[2*c+1] * invn - m * m;
    float sc  = rsqrtf(var + 1e-5f);
    params[c] = make_float2(sc, -m * sc);
}

// ------- generic 3x3 conv via tf32 mma (register pipeline + double-buffered tile) -------------
// Block: 32x4 output pixels x 32 couts; blockIdx.z = weight slice. 8 warps, warp -> 16-px mtile.
// One __syncthreads per 8-cin group: sync; LDG(g+1); compute(g, buf g&1); STS(g+1, buf (g+1)&1).
// Slot state packed in 2 arrays: so_ (smem off), go_ (gmem off, -1 = out of bounds; pl = go>>18).
template<int CIN>
__global__ void __launch_bounds__(256, 2)
conv_mma(const float* __restrict__ inA, const float* __restrict__ inB, int csplit,
         const float2* __restrict__ prmA, const float2* __restrict__ prmB,
         int reluA, int reluB,
         const float* __restrict__ wt, float* __restrict__ out, float* __restrict__ statsOut)
{
    constexpr int PS = 232;     // tile plane stride floats (232 % 32 == 8 -> conflict-free A)
    constexpr int WS = 296;     // weight cin stride floats (296 % 32 == 8 -> conflict-free B)
    constexpr int TEL = 204;    // live elems per plane (34 x 6)
    constexpr int NG = CIN / 8;
    constexpr int NEL = 8 * TEL;             // 1632 elements per group
    constexpr int NSLOT = (NEL + 255) / 256; // 7
    constexpr int TB = 8 * PS;               // floats per tile buffer
    extern __shared__ float smem[];
    float* wsh  = smem;                      // CIN * WS
    float* tile = smem + CIN*WS;             // 2 * TB
    __shared__ float2 spar[CIN];
    __shared__ float sstat[64];

    const int tid  = threadIdx.x;
    const int warp = tid >> 5, lane = tid & 31;
    const int gid  = lane >> 2, tig = lane & 3;
    if (tid < 64) sstat[tid] = 0.f;
    if (tid < CIN) {
        bool isA = tid < csplit;
        const float2* pr = isA ? prmA : prmB;
        spar[tid] = pr ? __ldg(&pr[isA ? tid : tid - csplit]) : make_float2(1.f, 0.f);
    }

    const int gx = blockIdx.x * 32, gy = blockIdx.y * 4;
    const float* wsrc = wt + (size_t)blockIdx.z * (CIN*9*32);
    const unsigned wsh_s = (unsigned)__cvta_generic_to_shared(wsh);

    float acc[4][4];
#pragma unroll
    for (int j = 0; j < 4; j++)
#pragma unroll
        for (int e = 0; e < 4; e++) acc[j][e] = 0.f;

    // stage all weights (already tf32-rounded) once
    for (int i = tid; i < CIN*72; i += 256) {
        int cin = i / 72, off = i % 72;
        cp_async16(wsh_s + (cin*WS + off*4)*4, wsrc + cin*288 + off*4);
    }
    cp_commit();

    // ---- precompute per-slot state (loop-invariant across groups) ----
    const int nslot = (tid < (NEL & 255)) ? NSLOT : NSLOT - 1;
    int so_[NSLOT];     // smem offset within a tile buffer
    int go_[NSLOT];     // global offset pl*HW + iy*512 + ix, or -1 if out of bounds
#pragma unroll
    for (int j = 0; j < NSLOT; j++) {
        int i = tid + j*256;
        if (j < nslot) {
            int pl = i / TEL, rem = i % TEL;
            int r = rem / 34, c = rem % 34;
            int iy = gy - 1 + r, ix = gx - 1 + c;
            so_[j] = pl*PS + r*34 + c;
            bool ib = iy >= 0 && iy < 512 && ix >= 0 && ix < 512;
            go_[j] = ib ? (pl*HW + iy*512 + ix) : -1;
        }
    }

    float vreg[NSLOT];
    auto loadg = [&](int g) {
        int cin0 = g*8;
        bool isA = cin0 < csplit;
        const float* bp = isA ? (inA + (size_t)cin0 * HW)
                              : (inB + (size_t)(cin0 - csplit) * HW);
#pragma unroll
        for (int j = 0; j < NSLOT; j++)
            if (j < nslot) vreg[j] = (go_[j] >= 0) ? __ldg(bp + go_[j]) : 0.f;
    };

    auto stores = [&](int g, int buf) {
        int cin0 = g*8;
        bool isA = cin0 < csplit;
        int rl = isA ? reluA : reluB;
        unsigned* tb = (unsigned*)(tile + buf * TB);
#pragma unroll
        for (int j = 0; j < NSLOT; j++) {
            if (j < nslot) {
                int g0 = go_[j];
                int pl = (g0 >= 0 ? g0 : 0) >> 18;
                float2 p = spar[cin0 + pl];
                float v = (g0 >= 0) ? (vreg[j] * p.x + p.y) : 0.f;
                if (rl) v = fmaxf(v, 0.f);
                tb[so_[j]] = to_tf32(v);
            }
        }
    };

    auto compute = [&](int g, int buf) {
        const unsigned* tb = (const unsigned*)(tile + buf * TB);
        const unsigned* wb = (const unsigned*)wsh + g*8*WS;
        const int py = warp >> 1, pxb = (warp & 1) * 16;
#pragma unroll
        for (int ky = 0; ky < 3; ky++) {
#pragma unroll
            for (int kx = 0; kx < 3; kx++) {
                int ro = (py + ky) * 34 + pxb + kx;
                unsigned a0 = tb[ tig    * PS + ro + gid    ];
                unsigned a1 = tb[ tig    * PS + ro + gid + 8];
                unsigned a2 = tb[(tig+4) * PS + ro + gid    ];
                unsigned a3 = tb[(tig+4) * PS + ro + gid + 8];
                const unsigned* wk0 = wb + tig    *WS + (ky*3+kx)*32 + gid;
                const unsigned* wk4 = wb + (tig+4)*WS + (ky*3+kx)*32 + gid;
#pragma unroll
                for (int j = 0; j < 4; j++)
                    mma_tf32(acc[j], a0, a1, a2, a3, wk0[8*j], wk4[8*j]);
            }
        }
    };

    loadg(0);
    cp_wait<0>();          // weights landed
    __syncthreads();       // weights + spar visible
    stores(0, 0);
    for (int g = 0; g < NG; ++g) {
        __syncthreads();   // tile(g) visible; all readers of buf (g+1)&1 (compute g-1) done
        if (g + 1 < NG) loadg(g + 1);
        compute(g, g & 1);
        if (g + 1 < NG) stores(g + 1, (g + 1) & 1);
    }

    // ---- epilogue: store + fused stats (all pixels valid: 512 divides exactly) ----
    float* ob = out + (size_t)blockIdx.z * 32 * HW;
    const int py = warp >> 1, pxb = (warp & 1) * 16;
    const int oy = gy + py;
    const size_t row = (size_t)oy * 512 + gx + pxb;
#pragma unroll
    for (int j = 0; j < 4; j++) {
        int n0 = 8*j + 2*tig;
        ob[(size_t)(n0  ) * HW + row + gid    ] = acc[j][0];
        ob[(size_t)(n0+1) * HW + row + gid    ] = acc[j][1];
        ob[(size_t)(n0  ) * HW + row + gid + 8] = acc[j][2];
        ob[(size_t)(n0+1) * HW + row + gid + 8] = acc[j][3];
        float s0 = acc[j][0] + acc[j][2];
        float q0 = acc[j][0]*acc[j][0] + acc[j][2]*acc[j][2];
        float s1 = acc[j][1] + acc[j][3];
        float q1 = acc[j][1]*acc[j][1] + acc[j][3]*acc[j][3];
#pragma unroll
        for (int o = 16; o >= 4; o >>= 1) {
            s0 += __shfl_down_sync(0xFFFFFFFFu, s0, o);
            q0 += __shfl_down_sync(0xFFFFFFFFu, q0, o);
            s1 += __shfl_down_sync(0xFFFFFFFFu, s1, o);
            q1 += __shfl_down_sync(0xFFFFFFFFu, q1, o);
        }
        if (gid == 0) {
            atomicAdd(&sstat[2*n0    ], s0);
            atomicAdd(&sstat[2*n0 + 1], q0);
            atomicAdd(&sstat[2*n0 + 2], s1);
            atomicAdd(&sstat[2*n0 + 3], q1);
        }
    }
    __syncthreads();
    if (tid < 64) atomicAdd(&statsOut[blockIdx.z*64 + tid], sstat[tid]);
}

// ---------------- 3x3 conv v8 (e1, r2) --------------------------------------------------------
template<int CIN, int COUT, int CHUNK>
__global__ void __launch_bounds__(256, 4)
conv3x3_v8(const float* __restrict__ inA, const float* __restrict__ inB, int csplit,
           const float2* __restrict__ prmA, const float2* __restrict__ prmB,
           int reluA, int reluB,
           const float* __restrict__ wt, float* __restrict__ out, float* __restrict__ statsOut,
           int H, int W, int pad, int HO, int WO)
{
    constexpr int TW = 32, TPW = 36, TPH = 10;
    constexpr int TSZ = TPW * TPH;
    constexpr int NCH = CIN / CHUNK;
    constexpr int WCH = CHUNK * 9 * COUT;
    constexpr int COUTG = COUT / 2;
    constexpr int C2G = COUTG / 2;
    constexpr int C2  = COUT / 2;
    extern __shared__ float smem[];
    float* ws   = smem;
    float* tile = smem + 2*WCH;
    __shared__ float sstat[2*COUT];

    const int tid   = threadIdx.x;
    const int group = tid >> 7;
    const int tx    = tid & 15;
    const int ty    = (tid >> 4) & 7;
    if (tid < 2*COUT) sstat[tid] = 0.f;

    const int gx = blockIdx.x * TW, gy = blockIdx.y * 8;
    const int oy = gy + ty;
    const int ox0 = gx + tx, ox1 = ox0 + 16;
    const float* wsrc = wt + (size_t)blockIdx.z * (CIN*9*COUT);

    const unsigned ws_s   = (unsigned)__cvta_generic_to_shared(ws);
    const unsigned tile_s = (unsigned)__cvta_generic_to_shared(tile);
    const bool needT = (prmA != nullptr && csplit > 0) || (prmB != nullptr && csplit < CIN);

    u64 accA[C2G], accB[C2G];
#pragma unroll
    for (int p = 0; p < C2G; p++) { accA[p] = 0ull; accB[p] = 0ull; }

    auto prefetch = [&](int ci, int buf) {
        const float* wc = wsrc + (size_t)ci * WCH;
        unsigned wd = ws_s + buf * WCH * 4;
        for (int i = tid; i < WCH/4; i += 256)
            cp_async16(wd + i*16, wc + i*4);
        unsigned td = tile_s + buf * CHUNK*TSZ*4;
        for (int cc = 0; cc < CHUNK; ++cc) {
            int cin = ci*CHUNK + cc;
            bool isA = cin < csplit;
            const float* ip = isA ? (inA + (size_t)cin * H * W)
                                  : (inB + (size_t)(cin - csplit) * H * W);
            for (int i = tid; i < TSZ; i += 256) {
                int r = i / TPW, c = i % TPW;
                int iy = gy - pad + r, ix = gx - pad + c;
                bool inb = (c < TW+2) && iy >= 0 && iy < H && ix >= 0 && ix < W;
                cp_async4(td + (cc*TSZ + i)*4, inb ? (ip + (size_t)iy*W + ix) : ip, inb);
            }
        }
        cp_commit();
    };

    auto transform = [&](int ci, int buf) {
        float* tb = tile + buf * CHUNK*TSZ;
        for (int i = tid; i < CHUNK*TSZ; i += 256) {
            int cc = i / TSZ, e = i % TSZ;
            int cin = ci*CHUNK + cc;
            bool isA = cin < csplit;
            const float2* prm = isA ? prmA : prmB;
            if (!prm) continue;
            int rl = isA ? reluA : reluB;
            int r = e / TPW, c = e % TPW;
            int iy = gy - pad + r, ix = gx - pad + c;
            bool inb = (c < TW+2) && iy >= 0 && iy < H && ix >= 0 && ix < W;
            float2 p = __ldg(&prm[isA ? cin : (cin - csplit)]);
            float v = inb ? (tb[i] * p.x + p.y) : 0.f;
            if (rl) v = fmaxf(v, 0.f);
            tb[i] = v;
        }
    };

    auto compute = [&](int buf) {
        const float* tb0 = tile + buf * CHUNK*TSZ + ty * TPW + tx;
        const float* wsb = ws + buf * WCH;
#pragma unroll
        for (int cc = 0; cc < CHUNK; ++cc) {
            const float* tb = tb0 + cc * TSZ;
            const u64* wrow = (const u64*)(wsb + cc * 9 * COUT) + group * C2G;
#pragma unroll
            for (int ky = 0; ky < 3; ky++) {
#pragma unroll
                for (int kx = 0; kx < 3; kx++) {
                    u64 va = pack2(tb[ky*TPW + kx]);
                    u64 vb = pack2(tb[ky*TPW + kx + 16]);
                    if constexpr (C2G >= 2) {
                        const ulonglong2* w4 = (const ulonglong2*)(wrow + (ky*3+kx) * C2);
#pragma unroll
                        for (int p2 = 0; p2 < C2G/2; p2++) {
                            ulonglong2 w = w4[p2];
                            accA[2*p2  ] = ffma2(va, w.x, accA[2*p2  ]);
                            accB[2*p2  ] = ffma2(vb, w.x, accB[2*p2  ]);
                            accA[2*p2+1] = ffma2(va, w.y, accA[2*p2+1]);
                            accB[2*p2+1] = ffma2(vb, w.y, accB[2*p2+1]);
                        }
                    } else {
                        u64 w = wrow[(ky*3+kx) * C2];
                        accA[0] = ffma2(va, w, accA[0]);
                        accB[0] = ffma2(vb, w, accB[0]);
                    }
                }
            }
        }
    };

    prefetch(0, 0);
    for (int ci = 0; ci < NCH; ++ci) {
        int cur = ci & 1;
        if (ci + 1 < NCH) {
            prefetch(ci + 1, 1 - cur);
            cp_wait<1>();
        } else {
            cp_wait<0>();
        }
        __syncthreads();
        if (needT) { transform(ci, cur); __syncthreads(); }
        compute(cur);
        __syncthreads();
    }

    float* ob = out + (size_t)blockIdx.z * COUT * HO * WO;
    float* so = statsOut + blockIdx.z * 2 * COUT;
    const bool vA = (oy < HO) && (ox0 < WO);
    const bool vB = (oy < HO) && (ox1 < WO);
    const size_t row = (size_t)oy * WO;
#pragma unroll
    for (int p = 0; p < C2G; p++) {
        int c0 = group * COUTG + 2*p;
        float a0, a1, b0, b1;
        unpack2(accA[p], a0, a1);
        unpack2(accB[p], b0, b1);
        if (vA) {
            ob[(size_t)(c0  ) * HO * WO + row + ox0] = a0;
            ob[(size_t)(c0+1) * HO * WO + row + ox0] = a1;
        }
        if (vB) {
            ob[(size_t)(c0  ) * HO * WO + row + ox1] = b0;
            ob[(size_t)(c0+1) * HO * WO + row + ox1] = b1;
        }
        float s0 = (vA ? a0 : 0.f) + (vB ? b0 : 0.f);
        float q0 = (vA ? a0*a0 : 0.f) + (vB ? b0*b0 : 0.f);
        float s1 = (vA ? a1 : 0.f) + (vB ? b1 : 0.f);
        float q1 = (vA ? a1*a1 : 0.f) + (vB ? b1*b1 : 0.f);
#pragma unroll
        for (int o = 16; o; o >>= 1) {
            s0 += __shfl_down_sync(0xFFFFFFFFu, s0, o);
            q0 += __shfl_down_sync(0xFFFFFFFFu, q0, o);
            s1 += __shfl_down_sync(0xFFFFFFFFu, s1, o);
            q1 += __shfl_down_sync(0xFFFFFFFFu, q1, o);
        }
        if ((tid & 31) == 0) {
            atomicAdd(&sstat[2*c0  ], s0);
            atomicAdd(&sstat[2*c0+1], q0);
            atomicAdd(&sstat[2*c0+2], s1);
            atomicAdd(&sstat[2*c0+3], q1);
        }
    }
    __syncthreads();
    if (tid < 2*COUT) atomicAdd(&so[tid], sstat[tid]);
}

// ---------------- LSTM elementwise ----------------
__global__ void lstm_kernel(const float* __restrict__ prev_c, const float2* __restrict__ prm,
                            float* __restrict__ out_c, float* __restrict__ out_h)
{
    int idx = blockIdx.x * 256 + threadIdx.x;   // over 32*HW
    int c = idx >> 18;                          // HW = 2^18
    const int CHW = 32 * HW;

    float g[4];
#pragma unroll
    for (int gi = 0; gi < 4; gi++) {
        float2 p = prm[gi*32 + c];
        g[gi] = g_graw[(size_t)gi * CHW + idx] * p.x + p.y;
    }
    float f  = sigmoidf_(g[0]);
    float it = sigmoidf_(g[1]);
    float ct = tanhf(g[2]);
    float ot = sigmoidf_(g[3]);
    float nc = prev_c[idx] * f + it * ct;
    out_c[idx] = nc;
    out_h[idx] = tanhf(nc) * ot;
}

// ---------------- patch gather + per-channel dot ----------------
__global__ void gather_kernel(const int* __restrict__ holes,
                              const float* __restrict__ woil, const float* __restrict__ boil,
                              const float* __restrict__ wwat, const float* __restrict__ bwat,
                              const float* __restrict__ wgas, const float* __restrict__ bgas,
                              const float2* __restrict__ prm,
                              float* __restrict__ res)
{
    int nidx = threadIdx.x;
    if (nidx >= 256) return;
    int hx = holes[2*nidx], hy = holes[2*nidx+1];
    const float* wv[3] = { woil, wwat, wgas };
    float bv[3] = { boil[0], bwat[0], bgas[0] };
    for (int c = 0; c < 3; c++) {
        float2 p = prm[c];
        float s = bv[c];
        for (int i = 0; i < 3; i++)
            for (int j = 0; j < 3; j++) {
                float v = g_r2raw[(size_t)c * HW2 + (size_t)(hx + 3 + i) * HOB + (hy + 3 + j)];
                s += wv[c][i*3+j] * (v * p.x + p.y);
            }
        res[nidx*3 + c] = s;
    }
}

// ---------------- launch ----------------
extern "C" void kernel_launch(void* const* d_in, const int* in_sizes, int n_in,
                              void* d_out, int out_size)
{
    const float* x      = (const float*)d_in[0];
    const float* prev_c = (const float*)d_in[1];
    const float* prev_h = (const float*)d_in[2];
    const int*   holes  = (const int*)d_in[3];
    const float* w_e1   = (const float*)d_in[4];
    const float* w_e2   = (const float*)d_in[5];
    const float* w_f    = (const float*)d_in[6];
    const float* w_i    = (const float*)d_in[7];
    const float* w_c    = (const float*)d_in[8];
    const float* w_o    = (const float*)d_in[9];
    const float* w_r1   = (const float*)d_in[10];
    const float* w_r2   = (const float*)d_in[11];
    const float* w_oil  = (const float*)d_in[12];
    const float* b_oil  = (const float*)d_in[13];
    const float* w_wat  = (const float*)d_in[14];
    const float* b_wat  = (const float*)d_in[15];
    const float* w_gas  = (const float*)d_in[16];
    const float* b_gas  = (const float*)d_in[17];
    float* out = (float*)d_out;

    float *t1raw, *t2raw, *graw, *r1raw, *r2raw;
    float *wt_e1, *wt_e2, *wt_g, *wt_r1, *wt_r2, *stats;
    float2 *params;
    cudaGetSymbolAddress((void**)&t1raw, g_t1raw);
    cudaGetSymbolAddress((void**)&t2raw, g_t2raw);
    cudaGetSymbolAddress((void**)&graw,  g_graw);
    cudaGetSymbolAddress((void**)&r1raw, g_r1raw);
    cudaGetSymbolAddress((void**)&r2raw, g_r2raw);
    cudaGetSymbolAddress((void**)&wt_e1, g_wt_e1);
    cudaGetSymbolAddress((void**)&wt_e2, g_wt_e2);
    cudaGetSymbolAddress((void**)&wt_g,  g_wt_g);
    cudaGetSymbolAddress((void**)&wt_r1, g_wt_r1);
    cudaGetSymbolAddress((void**)&wt_r2, g_wt_r2);
    cudaGetSymbolAddress((void**)&stats, g_stats);
    cudaGetSymbolAddress((void**)&params, g_params);

    constexpr int TSZ = 36 * 10;
    const int SM_E1 = (2*4*9*32  + 2*4*TSZ) * 4;    // 20736
    const int SM_R2 = (2*8*9*4   + 2*8*TSZ) * 4;    // 25344
    const int SM_M32 = (32*296 + 2*8*232) * 4;       // 52736
    const int SM_M64 = (64*296 + 2*8*232) * 4;       // 90624
    cudaFuncSetAttribute((const void*)conv3x3_v8<4,32,4>,  cudaFuncAttributeMaxDynamicSharedMemorySize, SM_E1);
    cudaFuncSetAttribute((const void*)conv3x3_v8<32,4,8>,  cudaFuncAttributeMaxDynamicSharedMemorySize, SM_R2);
    cudaFuncSetAttribute((const void*)conv_mma<32>,        cudaFuncAttributeMaxDynamicSharedMemorySize, SM_M32);
    cudaFuncSetAttribute((const void*)conv_mma<64>,        cudaFuncAttributeMaxDynamicSharedMemorySize, SM_M64);

    dim3 thr(256);
    dim3 grid512(512/32, 512/8, 1);        // 16 x 64  (v8)
    dim3 gridM  (512/32, 512/4, 1);        // 16 x 128 (mma)
    dim3 gridGM (512/32, 512/4, 4);
    dim3 gridR2 ((HOB + 31)/32, (HOB + 7)/8, 1);   // 17 x 65

    // launch order: prep(1), e1(2), mp(3), e2_mma(4), mp(5), gates_mma(6 = profiled)
    prep_weights<<<(94464 + 255)/256, 256>>>(w_e1, w_e2, w_f, w_i, w_c, w_o, w_r1, w_r2);

    // e1: x (4ch, raw) -> t1raw (+stats)  [fp32 v8]
    conv3x3_v8<4,32,4><<<grid512, thr, SM_E1>>>(x, x, 4, nullptr, nullptr, 0, 0,
                                                wt_e1, t1raw, stats + 0, 512, 512, 1, 512, 512);
    make_params<<<1, 32>>>(stats + 0, params + 0, 32, 1.f / (float)HW);

    // e2: relu(BN(t1raw)) -> t2raw (+stats)  [tf32 mma]
    conv_mma<32><<<gridM, thr, SM_M32>>>(t1raw, t1raw, 32, params + 0, params + 0, 1, 1,
                                         wt_e2, t2raw, stats + 64);
    make_params<<<1, 32>>>(stats + 64, params + 32, 32, 1.f / (float)HW);

    // gates: [prev_h (raw) ; BN(t2raw)] -> graw (+stats)  [tf32 mma, profiled launch]
    conv_mma<64><<<gridGM, thr, SM_M64>>>(prev_h, t2raw, 32, nullptr, params + 32, 0, 0,
                                          wt_g, graw, stats + 128);
    make_params<<<1, 128>>>(stats + 128, params + 64, 128, 1.f / (float)HW);

    // LSTM -> out[0:32HW]=next_c, out[32HW:64HW]=next_h
    lstm_kernel<<<32*HW/256, 256>>>(prev_c, params + 64, out, out + 32*HW);

    // r1: next_h (raw) -> r1raw (+stats)  [tf32 mma]
    conv_mma<32><<<gridM, thr, SM_M32>>>(out + 32*HW, out + 32*HW, 32, nullptr, nullptr, 0, 0,
                                         wt_r1, r1raw, stats + 384);
    make_params<<<1, 32>>>(stats + 384, params + 192, 32, 1.f / (float)HW);

    // r2: relu(BN(r1raw)) -> r2raw (3+1 ch @ 518x518, pad 4) (+stats)  [fp32 v8]
    conv3x3_v8<32,4,8><<<gridR2, thr, SM_R2>>>(r1raw, r1raw, 32, params + 192, params + 192, 1, 1,
                                               wt_r2, r2raw, stats + 448, 512, 512, 4, HOB, HOB);
    make_params<<<1, 32>>>(stats + 448, params + 224, 4, 1.f / (float)HW2);

    // gather + dot -> out tail
    gather_kernel<<<1, 256>>>(holes, w_oil, b_oil, w_wat, b_wat, w_gas, b_gas, params + 224, out + 64*HW);
}

// round 15
// speedup vs baseline: 2.2042x; 1.0863x over previous
#include <cuda_runtime.h>

#define HPX 512
#define WPX 512
#define HW  (HPX*WPX)           // 262144 = 2^18
#define HOB 518                 // r2 output side (512 + 2*4 - 2)
#define HW2 (HOB*HOB)           // 268324

typedef unsigned long long u64;

// ---------------- device scratch (no cudaMalloc allowed) ----------------
__device__ float g_t1raw[32*HW];
__device__ float g_t2raw[32*HW];
__device__ float g_graw [128*HW];
__device__ float g_r1raw[32*HW];
__device__ float g_r2raw[4*HW2];
__device__ __align__(16) float g_wt_e1[4*9*32];
// mma weights: [cin][k9][cl32], cl = (cout%8)*4 + cout/8 (B-fragment permuted), tf32-rounded
__device__ __align__(16) float g_wt_e2[32*9*32];
__device__ __align__(16) float g_wt_g [4*64*9*32];
__device__ __align__(16) float g_wt_r1[32*9*32];
__device__ __align__(16) float g_wt_r2[32*9*4];
__device__ float  g_stats[512];    // e1:[0,64) e2:[64,128) gates:[128,384) r1:[384,448) r2:[448,456)
__device__ float2 g_params[256];   // e1:0 e2:32 gates:64 r1:192 r2:224   (scale, bias)

// ---------------- f32x2 / cp.async helpers ----------------
__device__ __forceinline__ u64 pack2(float x) {
    unsigned u = __float_as_uint(x);
    u64 r;
    asm("mov.b64 %0, {%1, %2};" : "=l"(r) : "r"(u), "r"(u));
    return r;
}
__device__ __forceinline__ u64 ffma2(u64 a, u64 b, u64 c) {
    u64 d;
    asm("fma.rn.f32x2 %0, %1, %2, %3;" : "=l"(d) : "l"(a), "l"(b), "l"(c));
    return d;
}
__device__ __forceinline__ void unpack2(u64 v, float& lo, float& hi) {
    unsigned a, b;
    asm("mov.b64 {%0, %1}, %2;" : "=r"(a), "=r"(b) : "l"(v));
    lo = __uint_as_float(a); hi = __uint_as_float(b);
}
__device__ __forceinline__ float sigmoidf_(float x) { return 1.f / (1.f + expf(-x)); }

__device__ __forceinline__ void cp_async4(unsigned dst, const void* src, bool pred) {
    int bytes = pred ? 4 : 0;
    asm volatile("cp.async.ca.shared.global [%0], [%1], 4, %2;"
                 :: "r"(dst), "l"(src), "r"(bytes));
}
__device__ __forceinline__ void cp_async16(unsigned dst, const void* src) {
    asm volatile("cp.async.cg.shared.global [%0], [%1], 16;" :: "r"(dst), "l"(src));
}
__device__ __forceinline__ void cp_commit() {
    asm volatile("cp.async.commit_group;");
}
template<int N>
__device__ __forceinline__ void cp_wait() {
    asm volatile("cp.async.wait_group %0;" :: "n"(N));
}
__device__ __forceinline__ unsigned to_tf32(float v) {
    unsigned u;
    asm("cvt.rna.tf32.f32 %0, %1;" : "=r"(u) : "f"(v));
    return u;
}
__device__ __forceinline__ void mma_tf32(float* c, unsigned a0, unsigned a1, unsigned a2,
                                         unsigned a3, unsigned b0, unsigned b1) {
    asm volatile("mma.sync.aligned.m16n8k8.row.col.f32.tf32.tf32.f32 "
                 "{%0,%1,%2,%3}, {%4,%5,%6,%7}, {%8,%9}, {%0,%1,%2,%3};"
                 : "+f"(c[0]), "+f"(c[1]), "+f"(c[2]), "+f"(c[3])
                 : "r"(a0), "r"(a1), "r"(a2), "r"(a3), "r"(b0), "r"(b1));
}

// ------ weight prep (+ stats zeroing); mma weights tf32-rounded + cout-permuted ------
__global__ void prep_weights(const float* __restrict__ we1, const float* __restrict__ we2,
                             const float* __restrict__ wf,  const float* __restrict__ wi,
                             const float* __restrict__ wc,  const float* __restrict__ wo,
                             const float* __restrict__ wr1, const float* __restrict__ wr2)
{
    int idx = blockIdx.x * 256 + threadIdx.x;
    if (idx < 512) g_stats[idx] = 0.f;
    if (idx < 1152) {
        int cout = idx % 32, t = idx / 32, k = t % 9, cin = t / 9;
        g_wt_e1[idx] = we1[cout*4*9 + cin*9 + k];
        return;
    }
    idx -= 1152;
    if (idx < 9216) {
        int cl = idx % 32, t = idx / 32, k = t % 9, cin = t / 9;
        int cout = 8*(cl & 3) + (cl >> 2);
        g_wt_e2[idx] = __uint_as_float(to_tf32(we2[cout*32*9 + cin*9 + k]));
        return;
    }
    idx -= 9216;
    if (idx < 4*18432) {
        int g = idx / 18432, d = idx % 18432;
        int cl = d % 32, t = d / 32, k = t % 9, cin = t / 9;
        int cout = 8*(cl & 3) + (cl >> 2);
        const float* src = (g == 0) ? wf : (g == 1) ? wi : (g == 2) ? wc : wo;
        g_wt_g[idx] = __uint_as_float(to_tf32(src[cout*64*9 + cin*9 + k]));
        return;
    }
    idx -= 4*18432;
    if (idx < 9216) {
        int cl = idx % 32, t = idx / 32, k = t % 9, cin = t / 9;
        int cout = 8*(cl & 3) + (cl >> 2);
        g_wt_r1[idx] = __uint_as_float(to_tf32(wr1[cout*32*9 + cin*9 + k]));
        return;
    }
    idx -= 9216;
    if (idx < 1152) {
        int cout = idx % 4, t = idx / 4, k = t % 9, cin = t / 9;
        g_wt_r2[idx] = (cout < 3) ? wr2[cout*32*9 + cin*9 + k] : 0.f;
        return;
    }
}

// stats (sum, sumsq) -> params (scale, bias)
__global__ void make_params(const float* __restrict__ stats, float2* __restrict__ params,
                            int nch, float invn)
{
    int c = threadIdx.x;
    if (c >= nch) return;
    float m   = stats[2*c] * invn;
    float var = stats[2*c+1] * invn - m * m;
    float sc  = rsqrtf(var + 1e-5f);
    params[c] = make_float2(sc, -m * sc);
}

// ------- generic 3x3 conv via tf32 mma: reg pipeline, double-buffer tile, staged weights ------
// Block: 32x4 output pixels x 32 couts; blockIdx.z = weight slice. 8 warps, warp -> 16-px mtile.
// Weights staged 32 cins at a time (restage at g=4 for CIN=64) -> 52.7 KB smem, 3 CTAs/SM.
// B fragments contiguous via cout permutation -> one LDS.128 per (tig, k) pair.
template<int CIN>
__global__ void __launch_bounds__(256, 3)
conv_mma(const float* __restrict__ inA, const float* __restrict__ inB, int csplit,
         const float2* __restrict__ prmA, const float2* __restrict__ prmB,
         int reluA, int reluB,
         const float* __restrict__ wt, float* __restrict__ out, float* __restrict__ statsOut)
{
    constexpr int PS = 232;     // tile plane stride floats (232 % 32 == 8 -> conflict-free A)
    constexpr int WS = 296;     // weight cin stride floats
    constexpr int TEL = 204;    // live elems per plane (34 x 6)
    constexpr int NG = CIN / 8;
    constexpr int NEL = 8 * TEL;             // 1632 elements per group
    constexpr int NSLOT = (NEL + 255) / 256; // 7
    constexpr int TB = 8 * PS;               // floats per tile buffer
    constexpr int WCIN = (CIN < 32) ? CIN : 32;   // cins staged at once
    extern __shared__ float smem[];
    float* wsh  = smem;                      // WCIN * WS
    float* tile = smem + WCIN*WS;            // 2 * TB
    __shared__ float2 spar[CIN];
    __shared__ float sstat[64];

    const int tid  = threadIdx.x;
    const int warp = tid >> 5, lane = tid & 31;
    const int gid  = lane >> 2, tig = lane & 3;
    if (tid < 64) sstat[tid] = 0.f;
    if (tid < CIN) {
        bool isA = tid < csplit;
        const float2* pr = isA ? prmA : prmB;
        spar[tid] = pr ? __ldg(&pr[isA ? tid : tid - csplit]) : make_float2(1.f, 0.f);
    }

    const int gx = blockIdx.x * 32, gy = blockIdx.y * 4;
    const float* wsrc = wt + (size_t)blockIdx.z * (CIN*9*32);
    const unsigned wsh_s = (unsigned)__cvta_generic_to_shared(wsh);

    float acc[4][4];
#pragma unroll
    for (int j = 0; j < 4; j++)
#pragma unroll
        for (int e = 0; e < 4; e++) acc[j][e] = 0.f;

    auto stage_w = [&](int half) {
        const float* wc = wsrc + half * 32 * 288;
        for (int i = tid; i < WCIN*72; i += 256) {
            int cin = i / 72, off = i % 72;
            cp_async16(wsh_s + (cin*WS + off*4)*4, wc + cin*288 + off*4);
        }
        cp_commit();
    };
    stage_w(0);

    // ---- precompute per-slot state (loop-invariant across groups) ----
    const int nslot = (tid < (NEL & 255)) ? NSLOT : NSLOT - 1;
    int so_[NSLOT];     // smem offset within a tile buffer
    int go_[NSLOT];     // global offset pl*HW + iy*512 + ix, or -1 if out of bounds
#pragma unroll
    for (int j = 0; j < NSLOT; j++) {
        int i = tid + j*256;
        if (j < nslot) {
            int pl = i / TEL, rem = i % TEL;
            int r = rem / 34, c = rem % 34;
            int iy = gy - 1 + r, ix = gx - 1 + c;
            so_[j] = pl*PS + r*34 + c;
            bool ib = iy >= 0 && iy < 512 && ix >= 0 && ix < 512;
            go_[j] = ib ? (pl*HW + iy*512 + ix) : -1;
        }
    }

    float vreg[NSLOT];
    auto loadg = [&](int g) {
        int cin0 = g*8;
        bool isA = cin0 < csplit;
        const float* bp = isA ? (inA + (size_t)cin0 * HW)
                              : (inB + (size_t)(cin0 - csplit) * HW);
#pragma unroll
        for (int j = 0; j < NSLOT; j++)
            if (j < nslot) vreg[j] = (go_[j] >= 0) ? __ldg(bp + go_[j]) : 0.f;
    };

    auto stores = [&](int g, int buf) {
        int cin0 = g*8;
        bool isA = cin0 < csplit;
        int rl = isA ? reluA : reluB;
        unsigned* tb = (unsigned*)(tile + buf * TB);
#pragma unroll
        for (int j = 0; j < NSLOT; j++) {
            if (j < nslot) {
                int g0 = go_[j];
                int pl = (g0 >= 0 ? g0 : 0) >> 18;
                float2 p = spar[cin0 + pl];
                float v = (g0 >= 0) ? (vreg[j] * p.x + p.y) : 0.f;
                if (rl) v = fmaxf(v, 0.f);
                tb[so_[j]] = to_tf32(v);
            }
        }
    };

    auto compute = [&](int gs, int buf) {     // gs = group slot within staged weights
        const unsigned* tb = (const unsigned*)(tile + buf * TB);
        const unsigned* wb = (const unsigned*)wsh + gs*8*WS;
        const int py = warp >> 1, pxb = (warp & 1) * 16;
#pragma unroll
        for (int ky = 0; ky < 3; ky++) {
#pragma unroll
            for (int kx = 0; kx < 3; kx++) {
                int ro = (py + ky) * 34 + pxb + kx;
                unsigned a0 = tb[ tig    * PS + ro + gid    ];
                unsigned a1 = tb[ tig    * PS + ro + gid + 8];
                unsigned a2 = tb[(tig+4) * PS + ro + gid    ];
                unsigned a3 = tb[(tig+4) * PS + ro + gid + 8];
                uint4 b0v = *(const uint4*)(wb + tig    *WS + (ky*3+kx)*32 + gid*4);
                uint4 b4v = *(const uint4*)(wb + (tig+4)*WS + (ky*3+kx)*32 + gid*4);
                mma_tf32(acc[0], a0, a1, a2, a3, b0v.x, b4v.x);
                mma_tf32(acc[1], a0, a1, a2, a3, b0v.y, b4v.y);
                mma_tf32(acc[2], a0, a1, a2, a3, b0v.z, b4v.z);
                mma_tf32(acc[3], a0, a1, a2, a3, b0v.w, b4v.w);
            }
        }
    };

    loadg(0);
    cp_wait<0>();          // weights (half 0) landed
    __syncthreads();       // weights + spar visible
    stores(0, 0);
    for (int g = 0; g < NG; ++g) {
        __syncthreads();   // tile(g) visible; prior readers of the other buffer done
        if (CIN > 32 && g == 4) {
            stage_w(1);    // safe: compute(3) readers passed the barrier above
            if (g + 1 < NG) loadg(g + 1);
            cp_wait<0>();
            __syncthreads();
        } else {
            if (g + 1 < NG) loadg(g + 1);
        }
        compute((CIN > 32) ? (g & 3) : g, g & 1);
        if (g + 1 < NG) stores(g + 1, (g + 1) & 1);
    }

    // ---- epilogue: store + fused stats (all pixels valid: 512 divides exactly) ----
    float* ob = out + (size_t)blockIdx.z * 32 * HW;
    const int py = warp >> 1, pxb = (warp & 1) * 16;
    const int oy = gy + py;
    const size_t row = (size_t)oy * 512 + gx + pxb;
#pragma unroll
    for (int j = 0; j < 4; j++) {
        int n0 = 8*j + 2*tig;
        ob[(size_t)(n0  ) * HW + row + gid    ] = acc[j][0];
        ob[(size_t)(n0+1) * HW + row + gid    ] = acc[j][1];
        ob[(size_t)(n0  ) * HW + row + gid + 8] = acc[j][2];
        ob[(size_t)(n0+1) * HW + row + gid + 8] = acc[j][3];
        float s0 = acc[j][0] + acc[j][2];
        float q0 = acc[j][0]*acc[j][0] + acc[j][2]*acc[j][2];
        float s1 = acc[j][1] + acc[j][3];
        float q1 = acc[j][1]*acc[j][1] + acc[j][3]*acc[j][3];
#pragma unroll
        for (int o = 16; o >= 4; o >>= 1) {
            s0 += __shfl_down_sync(0xFFFFFFFFu, s0, o);
            q0 += __shfl_down_sync(0xFFFFFFFFu, q0, o);
            s1 += __shfl_down_sync(0xFFFFFFFFu, s1, o);
            q1 += __shfl_down_sync(0xFFFFFFFFu, q1, o);
        }
        if (gid == 0) {
            atomicAdd(&sstat[2*n0    ], s0);
            atomicAdd(&sstat[2*n0 + 1], q0);
            atomicAdd(&sstat[2*n0 + 2], s1);
            atomicAdd(&sstat[2*n0 + 3], q1);
        }
    }
    __syncthreads();
    if (tid < 64) atomicAdd(&statsOut[blockIdx.z*64 + tid], sstat[tid]);
}

// ---------------- 3x3 conv v8 (e1, r2) --------------------------------------------------------
template<int CIN, int COUT, int CHUNK>
__global__ void __launch_bounds__(256, 4)
conv3x3_v8(const float* __restrict__ inA, const float* __restrict__ inB, int csplit,
           const float2* __restrict__ prmA, const float2* __restrict__ prmB,
           int reluA, int reluB,
           const float* __restrict__ wt, float* __restrict__ out, float* __restrict__ statsOut,
           int H, int W, int pad, int HO, int WO)
{
    constexpr int TW = 32, TPW = 36, TPH = 10;
    constexpr int TSZ = TPW * TPH;
    constexpr int NCH = CIN / CHUNK;
    constexpr int WCH = CHUNK * 9 * COUT;
    constexpr int COUTG = COUT / 2;
    constexpr int C2G = COUTG / 2;
    constexpr int C2  = COUT / 2;
    extern __shared__ float smem[];
    float* ws   = smem;
    float* tile = smem + 2*WCH;
    __shared__ float sstat[2*COUT];

    const int tid   = threadIdx.x;
    const int group = tid >> 7;
    const int tx    = tid & 15;
    const int ty    = (tid >> 4) & 7;
    if (tid < 2*COUT) sstat[tid] = 0.f;

    const int gx = blockIdx.x * TW, gy = blockIdx.y * 8;
    const int oy = gy + ty;
    const int ox0 = gx + tx, ox1 = ox0 + 16;
    const float* wsrc = wt + (size_t)blockIdx.z * (CIN*9*COUT);

    const unsigned ws_s   = (unsigned)__cvta_generic_to_shared(ws);
    const unsigned tile_s = (unsigned)__cvta_generic_to_shared(tile);
    const bool needT = (prmA != nullptr && csplit > 0) || (prmB != nullptr && csplit < CIN);

    u64 accA[C2G], accB[C2G];
#pragma unroll
    for (int p = 0; p < C2G; p++) { accA[p] = 0ull; accB[p] = 0ull; }

    auto prefetch = [&](int ci, int buf) {
        const float* wc = wsrc + (size_t)ci * WCH;
        unsigned wd = ws_s + buf * WCH * 4;
        for (int i = tid; i < WCH/4; i += 256)
            cp_async16(wd + i*16, wc + i*4);
        unsigned td = tile_s + buf * CHUNK*TSZ*4;
        for (int cc = 0; cc < CHUNK; ++cc) {
            int cin = ci*CHUNK + cc;
            bool isA = cin < csplit;
            const float* ip = isA ? (inA + (size_t)cin * H * W)
                                  : (inB + (size_t)(cin - csplit) * H * W);
            for (int i = tid; i < TSZ; i += 256) {
                int r = i / TPW, c = i % TPW;
                int iy = gy - pad + r, ix = gx - pad + c;
                bool inb = (c < TW+2) && iy >= 0 && iy < H && ix >= 0 && ix < W;
                cp_async4(td + (cc*TSZ + i)*4, inb ? (ip + (size_t)iy*W + ix) : ip, inb);
            }
        }
        cp_commit();
    };

    auto transform = [&](int ci, int buf) {
        float* tb = tile + buf * CHUNK*TSZ;
        for (int i = tid; i < CHUNK*TSZ; i += 256) {
            int cc = i / TSZ, e = i % TSZ;
            int cin = ci*CHUNK + cc;
            bool isA = cin < csplit;
            const float2* prm = isA ? prmA : prmB;
            if (!prm) continue;
            int rl = isA ? reluA : reluB;
            int r = e / TPW, c = e % TPW;
            int iy = gy - pad + r, ix = gx - pad + c;
            bool inb = (c < TW+2) && iy >= 0 && iy < H && ix >= 0 && ix < W;
            float2 p = __ldg(&prm[isA ? cin : (cin - csplit)]);
            float v = inb ? (tb[i] * p.x + p.y) : 0.f;
            if (rl) v = fmaxf(v, 0.f);
            tb[i] = v;
        }
    };

    auto compute = [&](int buf) {
        const float* tb0 = tile + buf * CHUNK*TSZ + ty * TPW + tx;
        const float* wsb = ws + buf * WCH;
#pragma unroll
        for (int cc = 0; cc < CHUNK; ++cc) {
            const float* tb = tb0 + cc * TSZ;
            const u64* wrow = (const u64*)(wsb + cc * 9 * COUT) + group * C2G;
#pragma unroll
            for (int ky = 0; ky < 3; ky++) {
#pragma unroll
                for (int kx = 0; kx < 3; kx++) {
                    u64 va = pack2(tb[ky*TPW + kx]);
                    u64 vb = pack2(tb[ky*TPW + kx + 16]);
                    if constexpr (C2G >= 2) {
                        const ulonglong2* w4 = (const ulonglong2*)(wrow + (ky*3+kx) * C2);
#pragma unroll
                        for (int p2 = 0; p2 < C2G/2; p2++) {
                            ulonglong2 w = w4[p2];
                            accA[2*p2  ] = ffma2(va, w.x, accA[2*p2  ]);
                            accB[2*p2  ] = ffma2(vb, w.x, accB[2*p2  ]);
                            accA[2*p2+1] = ffma2(va, w.y, accA[2*p2+1]);
                            accB[2*p2+1] = ffma2(vb, w.y, accB[2*p2+1]);
                        }
                    } else {
                        u64 w = wrow[(ky*3+kx) * C2];
                        accA[0] = ffma2(va, w, accA[0]);
                        accB[0] = ffma2(vb, w, accB[0]);
                    }
                }
            }
        }
    };

    prefetch(0, 0);
    for (int ci = 0; ci < NCH; ++ci) {
        int cur = ci & 1;
        if (ci + 1 < NCH) {
            prefetch(ci + 1, 1 - cur);
            cp_wait<1>();
        } else {
            cp_wait<0>();
        }
        __syncthreads();
        if (needT) { transform(ci, cur); __syncthreads(); }
        compute(cur);
        __syncthreads();
    }

    float* ob = out + (size_t)blockIdx.z * COUT * HO * WO;
    float* so = statsOut + blockIdx.z * 2 * COUT;
    const bool vA = (oy < HO) && (ox0 < WO);
    const bool vB = (oy < HO) && (ox1 < WO);
    const size_t row = (size_t)oy * WO;
#pragma unroll
    for (int p = 0; p < C2G; p++) {
        int c0 = group * COUTG + 2*p;
        float a0, a1, b0, b1;
        unpack2(accA[p], a0, a1);
        unpack2(accB[p], b0, b1);
        if (vA) {
            ob[(size_t)(c0  ) * HO * WO + row + ox0] = a0;
            ob[(size_t)(c0+1) * HO * WO + row + ox0] = a1;
        }
        if (vB) {
            ob[(size_t)(c0  ) * HO * WO + row + ox1] = b0;
            ob[(size_t)(c0+1) * HO * WO + row + ox1] = b1;
        }
        float s0 = (vA ? a0 : 0.f) + (vB ? b0 : 0.f);
        float q0 = (vA ? a0*a0 : 0.f) + (vB ? b0*b0 : 0.f);
        float s1 = (vA ? a1 : 0.f) + (vB ? b1 : 0.f);
        float q1 = (vA ? a1*a1 : 0.f) + (vB ? b1*b1 : 0.f);
#pragma unroll
        for (int o = 16; o; o >>= 1) {
            s0 += __shfl_down_sync(0xFFFFFFFFu, s0, o);
            q0 += __shfl_down_sync(0xFFFFFFFFu, q0, o);
            s1 += __shfl_down_sync(0xFFFFFFFFu, s1, o);
            q1 += __shfl_down_sync(0xFFFFFFFFu, q1, o);
        }
        if ((tid & 31) == 0) {
            atomicAdd(&sstat[2*c0  ], s0);
            atomicAdd(&sstat[2*c0+1], q0);
            atomicAdd(&sstat[2*c0+2], s1);
            atomicAdd(&sstat[2*c0+3], q1);
        }
    }
    __syncthreads();
    if (tid < 2*COUT) atomicAdd(&so[tid], sstat[tid]);
}

// ---------------- LSTM elementwise ----------------
__global__ void lstm_kernel(const float* __restrict__ prev_c, const float2* __restrict__ prm,
                            float* __restrict__ out_c, float* __restrict__ out_h)
{
    int idx = blockIdx.x * 256 + threadIdx.x;   // over 32*HW
    int c = idx >> 18;                          // HW = 2^18
    const int CHW = 32 * HW;

    float g[4];
#pragma unroll
    for (int gi = 0; gi < 4; gi++) {
        float2 p = prm[gi*32 + c];
        g[gi] = g_graw[(size_t)gi * CHW + idx] * p.x + p.y;
    }
    float f  = sigmoidf_(g[0]);
    float it = sigmoidf_(g[1]);
    float ct = tanhf(g[2]);
    float ot = sigmoidf_(g[3]);
    float nc = prev_c[idx] * f + it * ct;
    out_c[idx] = nc;
    out_h[idx] = tanhf(nc) * ot;
}

// ---------------- patch gather + per-channel dot ----------------
__global__ void gather_kernel(const int* __restrict__ holes,
                              const float* __restrict__ woil, const float* __restrict__ boil,
                              const float* __restrict__ wwat, const float* __restrict__ bwat,
                              const float* __restrict__ wgas, const float* __restrict__ bgas,
                              const float2* __restrict__ prm,
                              float* __restrict__ res)
{
    int nidx = threadIdx.x;
    if (nidx >= 256) return;
    int hx = holes[2*nidx], hy = holes[2*nidx+1];
    const float* wv[3] = { woil, wwat, wgas };
    float bv[3] = { boil[0], bwat[0], bgas[0] };
    for (int c = 0; c < 3; c++) {
        float2 p = prm[c];
        float s = bv[c];
        for (int i = 0; i < 3; i++)
            for (int j = 0; j < 3; j++) {
                float v = g_r2raw[(size_t)c * HW2 + (size_t)(hx + 3 + i) * HOB + (hy + 3 + j)];
                s += wv[c][i*3+j] * (v * p.x + p.y);
            }
        res[nidx*3 + c] = s;
    }
}

// ---------------- launch ----------------
extern "C" void kernel_launch(void* const* d_in, const int* in_sizes, int n_in,
                              void* d_out, int out_size)
{
    const float* x      = (const float*)d_in[0];
    const float* prev_c = (const float*)d_in[1];
    const float* prev_h = (const float*)d_in[2];
    const int*   holes  = (const int*)d_in[3];
    const float* w_e1   = (const float*)d_in[4];
    const float* w_e2   = (const float*)d_in[5];
    const float* w_f    = (const float*)d_in[6];
    const float* w_i    = (const float*)d_in[7];
    const float* w_c    = (const float*)d_in[8];
    const float* w_o    = (const float*)d_in[9];
    const float* w_r1   = (const float*)d_in[10];
    const float* w_r2   = (const float*)d_in[11];
    const float* w_oil  = (const float*)d_in[12];
    const float* b_oil  = (const float*)d_in[13];
    const float* w_wat  = (const float*)d_in[14];
    const float* b_wat  = (const float*)d_in[15];
    const float* w_gas  = (const float*)d_in[16];
    const float* b_gas  = (const float*)d_in[17];
    float* out = (float*)d_out;

    float *t1raw, *t2raw, *graw, *r1raw, *r2raw;
    float *wt_e1, *wt_e2, *wt_g, *wt_r1, *wt_r2, *stats;
    float2 *params;
    cudaGetSymbolAddress((void**)&t1raw, g_t1raw);
    cudaGetSymbolAddress((void**)&t2raw, g_t2raw);
    cudaGetSymbolAddress((void**)&graw,  g_graw);
    cudaGetSymbolAddress((void**)&r1raw, g_r1raw);
    cudaGetSymbolAddress((void**)&r2raw, g_r2raw);
    cudaGetSymbolAddress((void**)&wt_e1, g_wt_e1);
    cudaGetSymbolAddress((void**)&wt_e2, g_wt_e2);
    cudaGetSymbolAddress((void**)&wt_g,  g_wt_g);
    cudaGetSymbolAddress((void**)&wt_r1, g_wt_r1);
    cudaGetSymbolAddress((void**)&wt_r2, g_wt_r2);
    cudaGetSymbolAddress((void**)&stats, g_stats);
    cudaGetSymbolAddress((void**)&params, g_params);

    constexpr int TSZ = 36 * 10;
    const int SM_E1 = (2*4*9*32  + 2*4*TSZ) * 4;    // 20736
    const int SM_R2 = (2*8*9*4   + 2*8*TSZ) * 4;    // 25344
    const int SM_MMA = (32*296 + 2*8*232) * 4;       // 52736 (both CIN=32 and CIN=64)
    cudaFuncSetAttribute((const void*)conv3x3_v8<4,32,4>,  cudaFuncAttributeMaxDynamicSharedMemorySize, SM_E1);
    cudaFuncSetAttribute((const void*)conv3x3_v8<32,4,8>,  cudaFuncAttributeMaxDynamicSharedMemorySize, SM_R2);
    cudaFuncSetAttribute((const void*)conv_mma<32>,        cudaFuncAttributeMaxDynamicSharedMemorySize, SM_MMA);
    cudaFuncSetAttribute((const void*)conv_mma<64>,        cudaFuncAttributeMaxDynamicSharedMemorySize, SM_MMA);

    dim3 thr(256);
    dim3 grid512(512/32, 512/8, 1);        // 16 x 64  (v8)
    dim3 gridM  (512/32, 512/4, 1);        // 16 x 128 (mma)
    dim3 gridGM (512/32, 512/4, 4);
    dim3 gridR2 ((HOB + 31)/32, (HOB + 7)/8, 1);   // 17 x 65

    // launch order: prep(1), e1(2), mp(3), e2_mma(4), mp(5), gates_mma(6 = profiled)
    prep_weights<<<(94464 + 255)/256, 256>>>(w_e1, w_e2, w_f, w_i, w_c, w_o, w_r1, w_r2);

    // e1: x (4ch, raw) -> t1raw (+stats)  [fp32 v8]
    conv3x3_v8<4,32,4><<<grid512, thr, SM_E1>>>(x, x, 4, nullptr, nullptr, 0, 0,
                                                wt_e1, t1raw, stats + 0, 512, 512, 1, 512, 512);
    make_params<<<1, 32>>>(stats + 0, params + 0, 32, 1.f / (float)HW);

    // e2: relu(BN(t1raw)) -> t2raw (+stats)  [tf32 mma]
    conv_mma<32><<<gridM, thr, SM_MMA>>>(t1raw, t1raw, 32, params + 0, params + 0, 1, 1,
                                         wt_e2, t2raw, stats + 64);
    make_params<<<1, 32>>>(stats + 64, params + 32, 32, 1.f / (float)HW);

    // gates: [prev_h (raw) ; BN(t2raw)] -> graw (+stats)  [tf32 mma, profiled launch]
    conv_mma<64><<<gridGM, thr, SM_MMA>>>(prev_h, t2raw, 32, nullptr, params + 32, 0, 0,
                                          wt_g, graw, stats + 128);
    make_params<<<1, 128>>>(stats + 128, params + 64, 128, 1.f / (float)HW);

    // LSTM -> out[0:32HW]=next_c, out[32HW:64HW]=next_h
    lstm_kernel<<<32*HW/256, 256>>>(prev_c, params + 64, out, out + 32*HW);

    // r1: next_h (raw) -> r1raw (+stats)  [tf32 mma]
    conv_mma<32><<<gridM, thr, SM_MMA>>>(out + 32*HW, out + 32*HW, 32, nullptr, nullptr, 0, 0,
                                         wt_r1, r1raw, stats + 384);
    make_params<<<1, 32>>>(stats + 384, params + 192, 32, 1.f / (float)HW);

    // r2: relu(BN(r1raw)) -> r2raw (3+1 ch @ 518x518, pad 4) (+stats)  [fp32 v8]
    conv3x3_v8<32,4,8><<<gridR2, thr, SM_R2>>>(r1raw, r1raw, 32, params + 192, params + 192, 1, 1,
                                               wt_r2, r2raw, stats + 448, 512, 512, 4, HOB, HOB);
    make_params<<<1, 32>>>(stats + 448, params + 224, 4, 1.f / (float)HW2);

    // gather + dot -> out tail
    gather_kernel<<<1, 256>>>(holes, w_oil, b_oil, w_wat, b_wat, w_gas, b_gas, params + 224, out + 64*HW);
}

// round 16
// speedup vs baseline: 2.5007x; 1.1345x over previous
#include <cuda_runtime.h>

#define HPX 512
#define WPX 512
#define HW  (HPX*WPX)           // 262144 = 2^18
#define HOB 518                 // r2 output side (512 + 2*4 - 2)
#define HW2 (HOB*HOB)           // 268324

typedef unsigned long long u64;

// ---------------- device scratch (no cudaMalloc allowed) ----------------
__device__ float g_t1raw[32*HW];
__device__ float g_t2raw[32*HW];
__device__ float g_graw [128*HW];
__device__ float g_r1raw[32*HW];
__device__ float g_r2raw[4*HW2];
__device__ __align__(16) float g_wt_e1[4*9*32];
// mma weights: [cin][k9][cl32], cl = (cout%8)*4 + cout/8 (B-fragment permuted), tf32-rounded
__device__ __align__(16) float g_wt_e2[32*9*32];
__device__ __align__(16) float g_wt_g [4*64*9*32];
__device__ __align__(16) float g_wt_r1[32*9*32];
__device__ __align__(16) float g_wt_r2[32*9*4];
__device__ float  g_stats[512];    // e1:[0,64) e2:[64,128) gates:[128,384) r1:[384,448) r2:[448,456)
__device__ float2 g_params[256];   // e1:0 e2:32 gates:64 r1:192 r2:224   (scale, bias)

// ---------------- f32x2 / cp.async helpers ----------------
__device__ __forceinline__ u64 pack2(float x) {
    unsigned u = __float_as_uint(x);
    u64 r;
    asm("mov.b64 %0, {%1, %2};" : "=l"(r) : "r"(u), "r"(u));
    return r;
}
__device__ __forceinline__ u64 ffma2(u64 a, u64 b, u64 c) {
    u64 d;
    asm("fma.rn.f32x2 %0, %1, %2, %3;" : "=l"(d) : "l"(a), "l"(b), "l"(c));
    return d;
}
__device__ __forceinline__ void unpack2(u64 v, float& lo, float& hi) {
    unsigned a, b;
    asm("mov.b64 {%0, %1}, %2;" : "=r"(a), "=r"(b) : "l"(v));
    lo = __uint_as_float(a); hi = __uint_as_float(b);
}
__device__ __forceinline__ float sigmoidf_(float x) { return 1.f / (1.f + expf(-x)); }

__device__ __forceinline__ void cp_async4(unsigned dst, const void* src, bool pred) {
    int bytes = pred ? 4 : 0;
    asm volatile("cp.async.ca.shared.global [%0], [%1], 4, %2;"
                 :: "r"(dst), "l"(src), "r"(bytes));
}
__device__ __forceinline__ void cp_async16(unsigned dst, const void* src) {
    asm volatile("cp.async.cg.shared.global [%0], [%1], 16;" :: "r"(dst), "l"(src));
}
__device__ __forceinline__ void cp_commit() {
    asm volatile("cp.async.commit_group;");
}
template<int N>
__device__ __forceinline__ void cp_wait() {
    asm volatile("cp.async.wait_group %0;" :: "n"(N));
}
__device__ __forceinline__ unsigned to_tf32(float v) {
    unsigned u;
    asm("cvt.rna.tf32.f32 %0, %1;" : "=r"(u) : "f"(v));
    return u;
}
__device__ __forceinline__ void mma_tf32(float* c, unsigned a0, unsigned a1, unsigned a2,
                                         unsigned a3, unsigned b0, unsigned b1) {
    asm volatile("mma.sync.aligned.m16n8k8.row.col.f32.tf32.tf32.f32 "
                 "{%0,%1,%2,%3}, {%4,%5,%6,%7}, {%8,%9}, {%0,%1,%2,%3};"
                 : "+f"(c[0]), "+f"(c[1]), "+f"(c[2]), "+f"(c[3])
                 : "r"(a0), "r"(a1), "r"(a2), "r"(a3), "r"(b0), "r"(b1));
}

// ------ weight prep (+ stats zeroing); mma weights tf32-rounded + cout-permuted ------
__global__ void prep_weights(const float* __restrict__ we1, const float* __restrict__ we2,
                             const float* __restrict__ wf,  const float* __restrict__ wi,
                             const float* __restrict__ wc,  const float* __restrict__ wo,
                             const float* __restrict__ wr1, const float* __restrict__ wr2)
{
    int idx = blockIdx.x * 256 + threadIdx.x;
    if (idx < 512) g_stats[idx] = 0.f;
    if (idx < 1152) {
        int cout = idx % 32, t = idx / 32, k = t % 9, cin = t / 9;
        g_wt_e1[idx] = we1[cout*4*9 + cin*9 + k];
        return;
    }
    idx -= 1152;
    if (idx < 9216) {
        int cl = idx % 32, t = idx / 32, k = t % 9, cin = t / 9;
        int cout = 8*(cl & 3) + (cl >> 2);
        g_wt_e2[idx] = __uint_as_float(to_tf32(we2[cout*32*9 + cin*9 + k]));
        return;
    }
    idx -= 9216;
    if (idx < 4*18432) {
        int g = idx / 18432, d = idx % 18432;
        int cl = d % 32, t = d / 32, k = t % 9, cin = t / 9;
        int cout = 8*(cl & 3) + (cl >> 2);
        const float* src = (g == 0) ? wf : (g == 1) ? wi : (g == 2) ? wc : wo;
        g_wt_g[idx] = __uint_as_float(to_tf32(src[cout*64*9 + cin*9 + k]));
        return;
    }
    idx -= 4*18432;
    if (idx < 9216) {
        int cl = idx % 32, t = idx / 32, k = t % 9, cin = t / 9;
        int cout = 8*(cl & 3) + (cl >> 2);
        g_wt_r1[idx] = __uint_as_float(to_tf32(wr1[cout*32*9 + cin*9 + k]));
        return;
    }
    idx -= 9216;
    if (idx < 1152) {
        int cout = idx % 4, t = idx / 4, k = t % 9, cin = t / 9;
        g_wt_r2[idx] = (cout < 3) ? wr2[cout*32*9 + cin*9 + k] : 0.f;
        return;
    }
}

// stats (sum, sumsq) -> params (scale, bias)
__global__ void make_params(const float* __restrict__ stats, float2* __restrict__ params,
                            int nch, float invn)
{
    int c = threadIdx.x;
    if (c >= nch) return;
    float m   = stats[2*c] * invn;
    float var = stats[2*c+1] * invn - m * m;
    float sc  = rsqrtf(var + 1e-5f);
    params[c] = make_float2(sc, -m * sc);
}

// ------- generic 3x3 conv via tf32 mma: 32x8 tile, 2 M-tiles/warp (B amortized) --------------
// Block: 32x8 output pixels x 32 couts; blockIdx.z = weight slice. 8 warps; warp (py, pxb)
// computes rows py and py+4 with shared B fragments. Weights staged 32 cins at a time
// (restage at g=4 for CIN=64). B fragments contiguous via cout permutation (LDS.128).
template<int CIN>
__global__ void __launch_bounds__(256, 3)
conv_mma(const float* __restrict__ inA, const float* __restrict__ inB, int csplit,
         const float2* __restrict__ prmA, const float2* __restrict__ prmB,
         int reluA, int reluB,
         const float* __restrict__ wt, float* __restrict__ out, float* __restrict__ statsOut)
{
    constexpr int PS = 360;     // tile plane stride floats (360 % 32 == 8 -> conflict-free A)
    constexpr int WS = 296;     // weight cin stride floats
    constexpr int TEL = 340;    // live elems per plane (34 x 10)
    constexpr int NG = CIN / 8;
    constexpr int NEL = 8 * TEL;             // 2720 elements per group
    constexpr int NSLOT = (NEL + 255) / 256; // 11
    constexpr int TB = 8 * PS;               // floats per tile buffer
    constexpr int WCIN = (CIN < 32) ? CIN : 32;
    extern __shared__ float smem[];
    float* wsh  = smem;                      // WCIN * WS
    float* tile = smem + WCIN*WS;            // 2 * TB
    __shared__ float2 spar[CIN];
    __shared__ float sstat[64];

    const int tid  = threadIdx.x;
    const int warp = tid >> 5, lane = tid & 31;
    const int gid  = lane >> 2, tig = lane & 3;
    if (tid < 64) sstat[tid] = 0.f;
    if (tid < CIN) {
        bool isA = tid < csplit;
        const float2* pr = isA ? prmA : prmB;
        spar[tid] = pr ? __ldg(&pr[isA ? tid : tid - csplit]) : make_float2(1.f, 0.f);
    }

    const int gx = blockIdx.x * 32, gy = blockIdx.y * 8;
    const float* wsrc = wt + (size_t)blockIdx.z * (CIN*9*32);
    const unsigned wsh_s = (unsigned)__cvta_generic_to_shared(wsh);

    float acc[2][4][4];
#pragma unroll
    for (int m = 0; m < 2; m++)
#pragma unroll
        for (int j = 0; j < 4; j++)
#pragma unroll
            for (int e = 0; e < 4; e++) acc[m][j][e] = 0.f;

    auto stage_w = [&](int half) {
        const float* wc = wsrc + half * 32 * 288;
        for (int i = tid; i < WCIN*72; i += 256) {
            int cin = i / 72, off = i % 72;
            cp_async16(wsh_s + (cin*WS + off*4)*4, wc + cin*288 + off*4);
        }
        cp_commit();
    };
    stage_w(0);

    // ---- precompute per-slot state (loop-invariant across groups) ----
    const int nslot = (tid < (NEL & 255)) ? NSLOT : NSLOT - 1;
    int so_[NSLOT];     // smem offset within a tile buffer
    int go_[NSLOT];     // global offset pl*HW + iy*512 + ix, or -1 if out of bounds
#pragma unroll
    for (int j = 0; j < NSLOT; j++) {
        int i = tid + j*256;
        if (j < nslot) {
            int pl = i / TEL, rem = i % TEL;
            int r = rem / 34, c = rem % 34;
            int iy = gy - 1 + r, ix = gx - 1 + c;
            so_[j] = pl*PS + r*34 + c;
            bool ib = iy >= 0 && iy < 512 && ix >= 0 && ix < 512;
            go_[j] = ib ? (pl*HW + iy*512 + ix) : -1;
        }
    }

    float vreg[NSLOT];
    auto loadg = [&](int g) {
        int cin0 = g*8;
        bool isA = cin0 < csplit;
        const float* bp = isA ? (inA + (size_t)cin0 * HW)
                              : (inB + (size_t)(cin0 - csplit) * HW);
#pragma unroll
        for (int j = 0; j < NSLOT; j++)
            if (j < nslot) vreg[j] = (go_[j] >= 0) ? __ldg(bp + go_[j]) : 0.f;
    };

    auto stores = [&](int g, int buf) {
        int cin0 = g*8;
        bool isA = cin0 < csplit;
        int rl = isA ? reluA : reluB;
        unsigned* tb = (unsigned*)(tile + buf * TB);
#pragma unroll
        for (int j = 0; j < NSLOT; j++) {
            if (j < nslot) {
                int g0 = go_[j];
                int pl = (g0 >= 0 ? g0 : 0) >> 18;
                float2 p = spar[cin0 + pl];
                float v = (g0 >= 0) ? (vreg[j] * p.x + p.y) : 0.f;
                if (rl) v = fmaxf(v, 0.f);
                tb[so_[j]] = to_tf32(v);
            }
        }
    };

    auto compute = [&](int gs, int buf) {     // gs = group slot within staged weights
        const unsigned* tb = (const unsigned*)(tile + buf * TB);
        const unsigned* wb = (const unsigned*)wsh + gs*8*WS;
        const int py = warp >> 1, pxb = (warp & 1) * 16;
#pragma unroll
        for (int ky = 0; ky < 3; ky++) {
#pragma unroll
            for (int kx = 0; kx < 3; kx++) {
                int ro0 = (py     + ky) * 34 + pxb + kx;
                int ro1 = (py + 4 + ky) * 34 + pxb + kx;
                unsigned a0 = tb[ tig    * PS + ro0 + gid    ];
                unsigned a1 = tb[ tig    * PS + ro0 + gid + 8];
                unsigned a2 = tb[(tig+4) * PS + ro0 + gid    ];
                unsigned a3 = tb[(tig+4) * PS + ro0 + gid + 8];
                unsigned c0 = tb[ tig    * PS + ro1 + gid    ];
                unsigned c1 = tb[ tig    * PS + ro1 + gid + 8];
                unsigned c2 = tb[(tig+4) * PS + ro1 + gid    ];
                unsigned c3 = tb[(tig+4) * PS + ro1 + gid + 8];
                uint4 b0v = *(const uint4*)(wb + tig    *WS + (ky*3+kx)*32 + gid*4);
                uint4 b4v = *(const uint4*)(wb + (tig+4)*WS + (ky*3+kx)*32 + gid*4);
                mma_tf32(acc[0][0], a0, a1, a2, a3, b0v.x, b4v.x);
                mma_tf32(acc[0][1], a0, a1, a2, a3, b0v.y, b4v.y);
                mma_tf32(acc[0][2], a0, a1, a2, a3, b0v.z, b4v.z);
                mma_tf32(acc[0][3], a0, a1, a2, a3, b0v.w, b4v.w);
                mma_tf32(acc[1][0], c0, c1, c2, c3, b0v.x, b4v.x);
                mma_tf32(acc[1][1], c0, c1, c2, c3, b0v.y, b4v.y);
                mma_tf32(acc[1][2], c0, c1, c2, c3, b0v.z, b4v.z);
                mma_tf32(acc[1][3], c0, c1, c2, c3, b0v.w, b4v.w);
            }
        }
    };

    loadg(0);
    cp_wait<0>();          // weights (half 0) landed
    __syncthreads();       // weights + spar visible
    stores(0, 0);
    for (int g = 0; g < NG; ++g) {
        __syncthreads();   // tile(g) visible; prior readers of the other buffer done
        if (CIN > 32 && g == 4) {
            stage_w(1);    // safe: compute(3) readers passed the barrier above
            if (g + 1 < NG) loadg(g + 1);
            cp_wait<0>();
            __syncthreads();
        } else {
            if (g + 1 < NG) loadg(g + 1);
        }
        compute((CIN > 32) ? (g & 3) : g, g & 1);
        if (g + 1 < NG) stores(g + 1, (g + 1) & 1);
    }

    // ---- epilogue: store + fused stats (all pixels valid: 512 divides exactly) ----
    float* ob = out + (size_t)blockIdx.z * 32 * HW;
    const int py = warp >> 1, pxb = (warp & 1) * 16;
#pragma unroll
    for (int j = 0; j < 4; j++) {
        int n0 = 8*j + 2*tig;
        float s0 = 0.f, q0 = 0.f, s1 = 0.f, q1 = 0.f;
#pragma unroll
        for (int m = 0; m < 2; m++) {
            const int oy = gy + py + 4*m;
            const size_t row = (size_t)oy * 512 + gx + pxb;
            float v0 = acc[m][j][0], v1 = acc[m][j][1], v2 = acc[m][j][2], v3 = acc[m][j][3];
            ob[(size_t)(n0  ) * HW + row + gid    ] = v0;
            ob[(size_t)(n0+1) * HW + row + gid    ] = v1;
            ob[(size_t)(n0  ) * HW + row + gid + 8] = v2;
            ob[(size_t)(n0+1) * HW + row + gid + 8] = v3;
            s0 += v0 + v2; q0 += v0*v0 + v2*v2;
            s1 += v1 + v3; q1 += v1*v1 + v3*v3;
        }
#pragma unroll
        for (int o = 16; o >= 4; o >>= 1) {
            s0 += __shfl_down_sync(0xFFFFFFFFu, s0, o);
            q0 += __shfl_down_sync(0xFFFFFFFFu, q0, o);
            s1 += __shfl_down_sync(0xFFFFFFFFu, s1, o);
            q1 += __shfl_down_sync(0xFFFFFFFFu, q1, o);
        }
        if (gid == 0) {
            atomicAdd(&sstat[2*n0    ], s0);
            atomicAdd(&sstat[2*n0 + 1], q0);
            atomicAdd(&sstat[2*n0 + 2], s1);
            atomicAdd(&sstat[2*n0 + 3], q1);
        }
    }
    __syncthreads();
    if (tid < 64) atomicAdd(&statsOut[blockIdx.z*64 + tid], sstat[tid]);
}

// ---------------- 3x3 conv v8 (e1, r2) --------------------------------------------------------
template<int CIN, int COUT, int CHUNK>
__global__ void __launch_bounds__(256, 4)
conv3x3_v8(const float* __restrict__ inA, const float* __restrict__ inB, int csplit,
           const float2* __restrict__ prmA, const float2* __restrict__ prmB,
           int reluA, int reluB,
           const float* __restrict__ wt, float* __restrict__ out, float* __restrict__ statsOut,
           int H, int W, int pad, int HO, int WO)
{
    constexpr int TW = 32, TPW = 36, TPH = 10;
    constexpr int TSZ = TPW * TPH;
    constexpr int NCH = CIN / CHUNK;
    constexpr int WCH = CHUNK * 9 * COUT;
    constexpr int COUTG = COUT / 2;
    constexpr int C2G = COUTG / 2;
    constexpr int C2  = COUT / 2;
    extern __shared__ float smem[];
    float* ws   = smem;
    float* tile = smem + 2*WCH;
    __shared__ float sstat[2*COUT];

    const int tid   = threadIdx.x;
    const int group = tid >> 7;
    const int tx    = tid & 15;
    const int ty    = (tid >> 4) & 7;
    if (tid < 2*COUT) sstat[tid] = 0.f;

    const int gx = blockIdx.x * TW, gy = blockIdx.y * 8;
    const int oy = gy + ty;
    const int ox0 = gx + tx, ox1 = ox0 + 16;
    const float* wsrc = wt + (size_t)blockIdx.z * (CIN*9*COUT);

    const unsigned ws_s   = (unsigned)__cvta_generic_to_shared(ws);
    const unsigned tile_s = (unsigned)__cvta_generic_to_shared(tile);
    const bool needT = (prmA != nullptr && csplit > 0) || (prmB != nullptr && csplit < CIN);

    u64 accA[C2G], accB[C2G];
#pragma unroll
    for (int p = 0; p < C2G; p++) { accA[p] = 0ull; accB[p] = 0ull; }

    auto prefetch = [&](int ci, int buf) {
        const float* wc = wsrc + (size_t)ci * WCH;
        unsigned wd = ws_s + buf * WCH * 4;
        for (int i = tid; i < WCH/4; i += 256)
            cp_async16(wd + i*16, wc + i*4);
        unsigned td = tile_s + buf * CHUNK*TSZ*4;
        for (int cc = 0; cc < CHUNK; ++cc) {
            int cin = ci*CHUNK + cc;
            bool isA = cin < csplit;
            const float* ip = isA ? (inA + (size_t)cin * H * W)
                                  : (inB + (size_t)(cin - csplit) * H * W);
            for (int i = tid; i < TSZ; i += 256) {
                int r = i / TPW, c = i % TPW;
                int iy = gy - pad + r, ix = gx - pad + c;
                bool inb = (c < TW+2) && iy >= 0 && iy < H && ix >= 0 && ix < W;
                cp_async4(td + (cc*TSZ + i)*4, inb ? (ip + (size_t)iy*W + ix) : ip, inb);
            }
        }
        cp_commit();
    };

    auto transform = [&](int ci, int buf) {
        float* tb = tile + buf * CHUNK*TSZ;
        for (int i = tid; i < CHUNK*TSZ; i += 256) {
            int cc = i / TSZ, e = i % TSZ;
            int cin = ci*CHUNK + cc;
            bool isA = cin < csplit;
            const float2* prm = isA ? prmA : prmB;
            if (!prm) continue;
            int rl = isA ? reluA : reluB;
            int r = e / TPW, c = e % TPW;
            int iy = gy - pad + r, ix = gx - pad + c;
            bool inb = (c < TW+2) && iy >= 0 && iy < H && ix >= 0 && ix < W;
            float2 p = __ldg(&prm[isA ? cin : (cin - csplit)]);
            float v = inb ? (tb[i] * p.x + p.y) : 0.f;
            if (rl) v = fmaxf(v, 0.f);
            tb[i] = v;
        }
    };

    auto compute = [&](int buf) {
        const float* tb0 = tile + buf * CHUNK*TSZ + ty * TPW + tx;
        const float* wsb = ws + buf * WCH;
#pragma unroll
        for (int cc = 0; cc < CHUNK; ++cc) {
            const float* tb = tb0 + cc * TSZ;
            const u64* wrow = (const u64*)(wsb + cc * 9 * COUT) + group * C2G;
#pragma unroll
            for (int ky = 0; ky < 3; ky++) {
#pragma unroll
                for (int kx = 0; kx < 3; kx++) {
                    u64 va = pack2(tb[ky*TPW + kx]);
                    u64 vb = pack2(tb[ky*TPW + kx + 16]);
                    if constexpr (C2G >= 2) {
                        const ulonglong2* w4 = (const ulonglong2*)(wrow + (ky*3+kx) * C2);
#pragma unroll
                        for (int p2 = 0; p2 < C2G/2; p2++) {
                            ulonglong2 w = w4[p2];
                            accA[2*p2  ] = ffma2(va, w.x, accA[2*p2  ]);
                            accB[2*p2  ] = ffma2(vb, w.x, accB[2*p2  ]);
                            accA[2*p2+1] = ffma2(va, w.y, accA[2*p2+1]);
                            accB[2*p2+1] = ffma2(vb, w.y, accB[2*p2+1]);
                        }
                    } else {
                        u64 w = wrow[(ky*3+kx) * C2];
                        accA[0] = ffma2(va, w, accA[0]);
                        accB[0] = ffma2(vb, w, accB[0]);
                    }
                }
            }
        }
    };

    prefetch(0, 0);
    for (int ci = 0; ci < NCH; ++ci) {
        int cur = ci & 1;
        if (ci + 1 < NCH) {
            prefetch(ci + 1, 1 - cur);
            cp_wait<1>();
        } else {
            cp_wait<0>();
        }
        __syncthreads();
        if (needT) { transform(ci, cur); __syncthreads(); }
        compute(cur);
        __syncthreads();
    }

    float* ob = out + (size_t)blockIdx.z * COUT * HO * WO;
    float* so = statsOut + blockIdx.z * 2 * COUT;
    const bool vA = (oy < HO) && (ox0 < WO);
    const bool vB = (oy < HO) && (ox1 < WO);
    const size_t row = (size_t)oy * WO;
#pragma unroll
    for (int p = 0; p < C2G; p++) {
        int c0 = group * COUTG + 2*p;
        float a0, a1, b0, b1;
        unpack2(accA[p], a0, a1);
        unpack2(accB[p], b0, b1);
        if (vA) {
            ob[(size_t)(c0  ) * HO * WO + row + ox0] = a0;
            ob[(size_t)(c0+1) * HO * WO + row + ox0] = a1;
        }
        if (vB) {
            ob[(size_t)(c0  ) * HO * WO + row + ox1] = b0;
            ob[(size_t)(c0+1) * HO * WO + row + ox1] = b1;
        }
        float s0 = (vA ? a0 : 0.f) + (vB ? b0 : 0.f);
        float q0 = (vA ? a0*a0 : 0.f) + (vB ? b0*b0 : 0.f);
        float s1 = (vA ? a1 : 0.f) + (vB ? b1 : 0.f);
        float q1 = (vA ? a1*a1 : 0.f) + (vB ? b1*b1 : 0.f);
#pragma unroll
        for (int o = 16; o; o >>= 1) {
            s0 += __shfl_down_sync(0xFFFFFFFFu, s0, o);
            q0 += __shfl_down_sync(0xFFFFFFFFu, q0, o);
            s1 += __shfl_down_sync(0xFFFFFFFFu, s1, o);
            q1 += __shfl_down_sync(0xFFFFFFFFu, q1, o);
        }
        if ((tid & 31) == 0) {
            atomicAdd(&sstat[2*c0  ], s0);
            atomicAdd(&sstat[2*c0+1], q0);
            atomicAdd(&sstat[2*c0+2], s1);
            atomicAdd(&sstat[2*c0+3], q1);
        }
    }
    __syncthreads();
    if (tid < 2*COUT) atomicAdd(&so[tid], sstat[tid]);
}

// ---------------- LSTM elementwise ----------------
__global__ void lstm_kernel(const float* __restrict__ prev_c, const float2* __restrict__ prm,
                            float* __restrict__ out_c, float* __restrict__ out_h)
{
    int idx = blockIdx.x * 256 + threadIdx.x;   // over 32*HW
    int c = idx >> 18;                          // HW = 2^18
    const int CHW = 32 * HW;

    float g[4];
#pragma unroll
    for (int gi = 0; gi < 4; gi++) {
        float2 p = prm[gi*32 + c];
        g[gi] = g_graw[(size_t)gi * CHW + idx] * p.x + p.y;
    }
    float f  = sigmoidf_(g[0]);
    float it = sigmoidf_(g[1]);
    float ct = tanhf(g[2]);
    float ot = sigmoidf_(g[3]);
    float nc = prev_c[idx] * f + it * ct;
    out_c[idx] = nc;
    out_h[idx] = tanhf(nc) * ot;
}

// ---------------- patch gather + per-channel dot ----------------
__global__ void gather_kernel(const int* __restrict__ holes,
                              const float* __restrict__ woil, const float* __restrict__ boil,
                              const float* __restrict__ wwat, const float* __restrict__ bwat,
                              const float* __restrict__ wgas, const float* __restrict__ bgas,
                              const float2* __restrict__ prm,
                              float* __restrict__ res)
{
    int nidx = threadIdx.x;
    if (nidx >= 256) return;
    int hx = holes[2*nidx], hy = holes[2*nidx+1];
    const float* wv[3] = { woil, wwat, wgas };
    float bv[3] = { boil[0], bwat[0], bgas[0] };
    for (int c = 0; c < 3; c++) {
        float2 p = prm[c];
        float s = bv[c];
        for (int i = 0; i < 3; i++)
            for (int j = 0; j < 3; j++) {
                float v = g_r2raw[(size_t)c * HW2 + (size_t)(hx + 3 + i) * HOB + (hy + 3 + j)];
                s += wv[c][i*3+j] * (v * p.x + p.y);
            }
        res[nidx*3 + c] = s;
    }
}

// ---------------- launch ----------------
extern "C" void kernel_launch(void* const* d_in, const int* in_sizes, int n_in,
                              void* d_out, int out_size)
{
    const float* x      = (const float*)d_in[0];
    const float* prev_c = (const float*)d_in[1];
    const float* prev_h = (const float*)d_in[2];
    const int*   holes  = (const int*)d_in[3];
    const float* w_e1   = (const float*)d_in[4];
    const float* w_e2   = (const float*)d_in[5];
    const float* w_f    = (const float*)d_in[6];
    const float* w_i    = (const float*)d_in[7];
    const float* w_c    = (const float*)d_in[8];
    const float* w_o    = (const float*)d_in[9];
    const float* w_r1   = (const float*)d_in[10];
    const float* w_r2   = (const float*)d_in[11];
    const float* w_oil  = (const float*)d_in[12];
    const float* b_oil  = (const float*)d_in[13];
    const float* w_wat  = (const float*)d_in[14];
    const float* b_wat  = (const float*)d_in[15];
    const float* w_gas  = (const float*)d_in[16];
    const float* b_gas  = (const float*)d_in[17];
    float* out = (float*)d_out;

    float *t1raw, *t2raw, *graw, *r1raw, *r2raw;
    float *wt_e1, *wt_e2, *wt_g, *wt_r1, *wt_r2, *stats;
    float2 *params;
    cudaGetSymbolAddress((void**)&t1raw, g_t1raw);
    cudaGetSymbolAddress((void**)&t2raw, g_t2raw);
    cudaGetSymbolAddress((void**)&graw,  g_graw);
    cudaGetSymbolAddress((void**)&r1raw, g_r1raw);
    cudaGetSymbolAddress((void**)&r2raw, g_r2raw);
    cudaGetSymbolAddress((void**)&wt_e1, g_wt_e1);
    cudaGetSymbolAddress((void**)&wt_e2, g_wt_e2);
    cudaGetSymbolAddress((void**)&wt_g,  g_wt_g);
    cudaGetSymbolAddress((void**)&wt_r1, g_wt_r1);
    cudaGetSymbolAddress((void**)&wt_r2, g_wt_r2);
    cudaGetSymbolAddress((void**)&stats, g_stats);
    cudaGetSymbolAddress((void**)&params, g_params);

    constexpr int TSZ = 36 * 10;
    const int SM_E1 = (2*4*9*32  + 2*4*TSZ) * 4;    // 20736
    const int SM_R2 = (2*8*9*4   + 2*8*TSZ) * 4;    // 25344
    const int SM_MMA = (32*296 + 2*8*360) * 4;       // 60928 (both CIN=32 and CIN=64)
    cudaFuncSetAttribute((const void*)conv3x3_v8<4,32,4>,  cudaFuncAttributeMaxDynamicSharedMemorySize, SM_E1);
    cudaFuncSetAttribute((const void*)conv3x3_v8<32,4,8>,  cudaFuncAttributeMaxDynamicSharedMemorySize, SM_R2);
    cudaFuncSetAttribute((const void*)conv_mma<32>,        cudaFuncAttributeMaxDynamicSharedMemorySize, SM_MMA);
    cudaFuncSetAttribute((const void*)conv_mma<64>,        cudaFuncAttributeMaxDynamicSharedMemorySize, SM_MMA);

    dim3 thr(256);
    dim3 grid512(512/32, 512/8, 1);        // 16 x 64  (v8)
    dim3 gridM  (512/32, 512/8, 1);        // 16 x 64  (mma, 32x8 tile)
    dim3 gridGM (512/32, 512/8, 4);
    dim3 gridR2 ((HOB + 31)/32, (HOB + 7)/8, 1);   // 17 x 65

    // launch order: prep(1), e1(2), mp(3), e2_mma(4), mp(5), gates_mma(6 = profiled)
    prep_weights<<<(94464 + 255)/256, 256>>>(w_e1, w_e2, w_f, w_i, w_c, w_o, w_r1, w_r2);

    // e1: x (4ch, raw) -> t1raw (+stats)  [fp32 v8]
    conv3x3_v8<4,32,4><<<grid512, thr, SM_E1>>>(x, x, 4, nullptr, nullptr, 0, 0,
                                                wt_e1, t1raw, stats + 0, 512, 512, 1, 512, 512);
    make_params<<<1, 32>>>(stats + 0, params + 0, 32, 1.f / (float)HW);

    // e2: relu(BN(t1raw)) -> t2raw (+stats)  [tf32 mma]
    conv_mma<32><<<gridM, thr, SM_MMA>>>(t1raw, t1raw, 32, params + 0, params + 0, 1, 1,
                                         wt_e2, t2raw, stats + 64);
    make_params<<<1, 32>>>(stats + 64, params + 32, 32, 1.f / (float)HW);

    // gates: [prev_h (raw) ; BN(t2raw)] -> graw (+stats)  [tf32 mma, profiled launch]
    conv_mma<64><<<gridGM, thr, SM_MMA>>>(prev_h, t2raw, 32, nullptr, params + 32, 0, 0,
                                          wt_g, graw, stats + 128);
    make_params<<<1, 128>>>(stats + 128, params + 64, 128, 1.f / (float)HW);

    // LSTM -> out[0:32HW]=next_c, out[32HW:64HW]=next_h
    lstm_kernel<<<32*HW/256, 256>>>(prev_c, params + 64, out, out + 32*HW);

    // r1: next_h (raw) -> r1raw (+stats)  [tf32 mma]
    conv_mma<32><<<gridM, thr, SM_MMA>>>(out + 32*HW, out + 32*HW, 32, nullptr, nullptr, 0, 0,
                                         wt_r1, r1raw, stats + 384);
    make_params<<<1, 32>>>(stats + 384, params + 192, 32, 1.f / (float)HW);

    // r2: relu(BN(r1raw)) -> r2raw (3+1 ch @ 518x518, pad 4) (+stats)  [fp32 v8]
    conv3x3_v8<32,4,8><<<gridR2, thr, SM_R2>>>(r1raw, r1raw, 32, params + 192, params + 192, 1, 1,
                                               wt_r2, r2raw, stats + 448, 512, 512, 4, HOB, HOB);
    make_params<<<1, 32>>>(stats + 448, params + 224, 4, 1.f / (float)HW2);

    // gather + dot -> out tail
    gather_kernel<<<1, 256>>>(holes, w_oil, b_oil, w_wat, b_wat, w_gas, b_gas, params + 224, out + 64*HW);
}

// round 17
// speedup vs baseline: 2.7637x; 1.1052x over previous
#include <cuda_runtime.h>

#define HPX 512
#define WPX 512
#define HW  (HPX*WPX)           // 262144 = 2^18
#define HOB 518                 // r2 output side (512 + 2*4 - 2)
#define HW2 (HOB*HOB)           // 268324

typedef unsigned long long u64;

// ---------------- device scratch (no cudaMalloc allowed) ----------------
__device__ float g_t1raw[32*HW];
__device__ float g_t2raw[32*HW];
__device__ float g_graw [128*HW];
__device__ float g_r1raw[32*HW];
__device__ float g_r2raw[4*HW2];
__device__ __align__(16) float g_wt_e1[4*9*32];
// mma weights: [cin][k9][cl32], cl = (cout%8)*4 + cout/8 (B-fragment permuted), tf32-rounded
__device__ __align__(16) float g_wt_e2[32*9*32];
__device__ __align__(16) float g_wt_g [4*64*9*32];
__device__ __align__(16) float g_wt_r1[32*9*32];
__device__ __align__(16) float g_wt_r2[32*9*4];
__device__ float  g_stats[512];    // e1:[0,64) e2:[64,128) gates:[128,384) r1:[384,448) r2:[448,456)
__device__ float2 g_params[256];   // e1:0 e2:32 gates:64 r1:192 r2:224   (scale, bias)

// ---------------- f32x2 / cp.async helpers ----------------
__device__ __forceinline__ u64 pack2(float x) {
    unsigned u = __float_as_uint(x);
    u64 r;
    asm("mov.b64 %0, {%1, %2};" : "=l"(r) : "r"(u), "r"(u));
    return r;
}
__device__ __forceinline__ u64 ffma2(u64 a, u64 b, u64 c) {
    u64 d;
    asm("fma.rn.f32x2 %0, %1, %2, %3;" : "=l"(d) : "l"(a), "l"(b), "l"(c));
    return d;
}
__device__ __forceinline__ void unpack2(u64 v, float& lo, float& hi) {
    unsigned a, b;
    asm("mov.b64 {%0, %1}, %2;" : "=r"(a), "=r"(b) : "l"(v));
    lo = __uint_as_float(a); hi = __uint_as_float(b);
}
__device__ __forceinline__ float sigmoidf_(float x) { return 1.f / (1.f + expf(-x)); }

__device__ __forceinline__ void cp_async4(unsigned dst, const void* src, bool pred) {
    int bytes = pred ? 4 : 0;
    asm volatile("cp.async.ca.shared.global [%0], [%1], 4, %2;"
                 :: "r"(dst), "l"(src), "r"(bytes));
}
__device__ __forceinline__ void cp_async16(unsigned dst, const void* src) {
    asm volatile("cp.async.cg.shared.global [%0], [%1], 16;" :: "r"(dst), "l"(src));
}
__device__ __forceinline__ void cp_commit() {
    asm volatile("cp.async.commit_group;");
}
template<int N>
__device__ __forceinline__ void cp_wait() {
    asm volatile("cp.async.wait_group %0;" :: "n"(N));
}
__device__ __forceinline__ unsigned to_tf32(float v) {
    unsigned u;
    asm("cvt.rna.tf32.f32 %0, %1;" : "=r"(u) : "f"(v));
    return u;
}
__device__ __forceinline__ void mma_tf32(float* c, unsigned a0, unsigned a1, unsigned a2,
                                         unsigned a3, unsigned b0, unsigned b1) {
    asm volatile("mma.sync.aligned.m16n8k8.row.col.f32.tf32.tf32.f32 "
                 "{%0,%1,%2,%3}, {%4,%5,%6,%7}, {%8,%9}, {%0,%1,%2,%3};"
                 : "+f"(c[0]), "+f"(c[1]), "+f"(c[2]), "+f"(c[3])
                 : "r"(a0), "r"(a1), "r"(a2), "r"(a3), "r"(b0), "r"(b1));
}

// ------ weight prep (+ stats zeroing); mma weights tf32-rounded + cout-permuted ------
__global__ void prep_weights(const float* __restrict__ we1, const float* __restrict__ we2,
                             const float* __restrict__ wf,  const float* __restrict__ wi,
                             const float* __restrict__ wc,  const float* __restrict__ wo,
                             const float* __restrict__ wr1, const float* __restrict__ wr2)
{
    int idx = blockIdx.x * 256 + threadIdx.x;
    if (idx < 512) g_stats[idx] = 0.f;
    if (idx < 1152) {
        int cout = idx % 32, t = idx / 32, k = t % 9, cin = t / 9;
        g_wt_e1[idx] = we1[cout*4*9 + cin*9 + k];
        return;
    }
    idx -= 1152;
    if (idx < 9216) {
        int cl = idx % 32, t = idx / 32, k = t % 9, cin = t / 9;
        int cout = 8*(cl & 3) + (cl >> 2);
        g_wt_e2[idx] = __uint_as_float(to_tf32(we2[cout*32*9 + cin*9 + k]));
        return;
    }
    idx -= 9216;
    if (idx < 4*18432) {
        int g = idx / 18432, d = idx % 18432;
        int cl = d % 32, t = d / 32, k = t % 9, cin = t / 9;
        int cout = 8*(cl & 3) + (cl >> 2);
        const float* src = (g == 0) ? wf : (g == 1) ? wi : (g == 2) ? wc : wo;
        g_wt_g[idx] = __uint_as_float(to_tf32(src[cout*64*9 + cin*9 + k]));
        return;
    }
    idx -= 4*18432;
    if (idx < 9216) {
        int cl = idx % 32, t = idx / 32, k = t % 9, cin = t / 9;
        int cout = 8*(cl & 3) + (cl >> 2);
        g_wt_r1[idx] = __uint_as_float(to_tf32(wr1[cout*32*9 + cin*9 + k]));
        return;
    }
    idx -= 9216;
    if (idx < 1152) {
        int cout = idx % 4, t = idx / 4, k = t % 9, cin = t / 9;
        g_wt_r2[idx] = (cout < 3) ? wr2[cout*32*9 + cin*9 + k] : 0.f;
        return;
    }
}

// stats (sum, sumsq) -> params (scale, bias)
__global__ void make_params(const float* __restrict__ stats, float2* __restrict__ params,
                            int nch, float invn)
{
    int c = threadIdx.x;
    if (c >= nch) return;
    float m   = stats[2*c] * invn;
    float var = stats[2*c+1] * invn - m * m;
    float sc  = rsqrtf(var + 1e-5f);
    params[c] = make_float2(sc, -m * sc);
}

// ------- conv_mma: 32x8 tile, 2 M-tiles/warp, single 32-cout slice (e2, r1) ------------------
template<int CIN>
__global__ void __launch_bounds__(256, 3)
conv_mma(const float* __restrict__ inA, const float* __restrict__ inB, int csplit,
         const float2* __restrict__ prmA, const float2* __restrict__ prmB,
         int reluA, int reluB,
         const float* __restrict__ wt, float* __restrict__ out, float* __restrict__ statsOut)
{
    constexpr int PS = 360;     // tile plane stride floats (360 % 32 == 8 -> conflict-free A)
    constexpr int WS = 296;     // weight cin stride floats
    constexpr int TEL = 340;    // live elems per plane (34 x 10)
    constexpr int NG = CIN / 8;
    constexpr int NEL = 8 * TEL;
    constexpr int NSLOT = (NEL + 255) / 256; // 11
    constexpr int TB = 8 * PS;
    extern __shared__ float smem[];
    float* wsh  = smem;                      // CIN * WS
    float* tile = smem + CIN*WS;             // 2 * TB
    __shared__ float2 spar[CIN];
    __shared__ float sstat[64];

    const int tid  = threadIdx.x;
    const int warp = tid >> 5, lane = tid & 31;
    const int gid  = lane >> 2, tig = lane & 3;
    if (tid < 64) sstat[tid] = 0.f;
    if (tid < CIN) {
        bool isA = tid < csplit;
        const float2* pr = isA ? prmA : prmB;
        spar[tid] = pr ? __ldg(&pr[isA ? tid : tid - csplit]) : make_float2(1.f, 0.f);
    }

    const int gx = blockIdx.x * 32, gy = blockIdx.y * 8;
    const float* wsrc = wt;
    const unsigned wsh_s = (unsigned)__cvta_generic_to_shared(wsh);

    float acc[2][4][4];
#pragma unroll
    for (int m = 0; m < 2; m++)
#pragma unroll
        for (int j = 0; j < 4; j++)
#pragma unroll
            for (int e = 0; e < 4; e++) acc[m][j][e] = 0.f;

    for (int i = tid; i < CIN*72; i += 256) {
        int cin = i / 72, off = i % 72;
        cp_async16(wsh_s + (cin*WS + off*4)*4, wsrc + cin*288 + off*4);
    }
    cp_commit();

    const int nslot = (tid < (NEL & 255)) ? NSLOT : NSLOT - 1;
    int so_[NSLOT];
    int go_[NSLOT];
#pragma unroll
    for (int j = 0; j < NSLOT; j++) {
        int i = tid + j*256;
        if (j < nslot) {
            int pl = i / TEL, rem = i % TEL;
            int r = rem / 34, c = rem % 34;
            int iy = gy - 1 + r, ix = gx - 1 + c;
            so_[j] = pl*PS + r*34 + c;
            bool ib = iy >= 0 && iy < 512 && ix >= 0 && ix < 512;
            go_[j] = ib ? (pl*HW + iy*512 + ix) : -1;
        }
    }

    float vreg[NSLOT];
    auto loadg = [&](int g) {
        int cin0 = g*8;
        bool isA = cin0 < csplit;
        const float* bp = isA ? (inA + (size_t)cin0 * HW)
                              : (inB + (size_t)(cin0 - csplit) * HW);
#pragma unroll
        for (int j = 0; j < NSLOT; j++)
            if (j < nslot) vreg[j] = (go_[j] >= 0) ? __ldg(bp + go_[j]) : 0.f;
    };

    auto stores = [&](int g, int buf) {
        int cin0 = g*8;
        bool isA = cin0 < csplit;
        int rl = isA ? reluA : reluB;
        unsigned* tb = (unsigned*)(tile + buf * TB);
#pragma unroll
        for (int j = 0; j < NSLOT; j++) {
            if (j < nslot) {
                int g0 = go_[j];
                int pl = (g0 >= 0 ? g0 : 0) >> 18;
                float2 p = spar[cin0 + pl];
                float v = (g0 >= 0) ? (vreg[j] * p.x + p.y) : 0.f;
                if (rl) v = fmaxf(v, 0.f);
                tb[so_[j]] = to_tf32(v);
            }
        }
    };

    auto compute = [&](int gs, int buf) {
        const unsigned* tb = (const unsigned*)(tile + buf * TB);
        const unsigned* wb = (const unsigned*)wsh + gs*8*WS;
        const int py = warp >> 1, pxb = (warp & 1) * 16;
#pragma unroll
        for (int ky = 0; ky < 3; ky++) {
#pragma unroll
            for (int kx = 0; kx < 3; kx++) {
                int ro0 = (py     + ky) * 34 + pxb + kx;
                int ro1 = (py + 4 + ky) * 34 + pxb + kx;
                unsigned a0 = tb[ tig    * PS + ro0 + gid    ];
                unsigned a1 = tb[ tig    * PS + ro0 + gid + 8];
                unsigned a2 = tb[(tig+4) * PS + ro0 + gid    ];
                unsigned a3 = tb[(tig+4) * PS + ro0 + gid + 8];
                unsigned c0 = tb[ tig    * PS + ro1 + gid    ];
                unsigned c1 = tb[ tig    * PS + ro1 + gid + 8];
                unsigned c2 = tb[(tig+4) * PS + ro1 + gid    ];
                unsigned c3 = tb[(tig+4) * PS + ro1 + gid + 8];
                uint4 b0v = *(const uint4*)(wb + tig    *WS + (ky*3+kx)*32 + gid*4);
                uint4 b4v = *(const uint4*)(wb + (tig+4)*WS + (ky*3+kx)*32 + gid*4);
                mma_tf32(acc[0][0], a0, a1, a2, a3, b0v.x, b4v.x);
                mma_tf32(acc[0][1], a0, a1, a2, a3, b0v.y, b4v.y);
                mma_tf32(acc[0][2], a0, a1, a2, a3, b0v.z, b4v.z);
                mma_tf32(acc[0][3], a0, a1, a2, a3, b0v.w, b4v.w);
                mma_tf32(acc[1][0], c0, c1, c2, c3, b0v.x, b4v.x);
                mma_tf32(acc[1][1], c0, c1, c2, c3, b0v.y, b4v.y);
                mma_tf32(acc[1][2], c0, c1, c2, c3, b0v.z, b4v.z);
                mma_tf32(acc[1][3], c0, c1, c2, c3, b0v.w, b4v.w);
            }
        }
    };

    loadg(0);
    cp_wait<0>();
    __syncthreads();
    stores(0, 0);
    for (int g = 0; g < NG; ++g) {
        __syncthreads();
        if (g + 1 < NG) loadg(g + 1);
        compute(g, g & 1);
        if (g + 1 < NG) stores(g + 1, (g + 1) & 1);
    }

    float* ob = out;
    const int py = warp >> 1, pxb = (warp & 1) * 16;
#pragma unroll
    for (int j = 0; j < 4; j++) {
        int n0 = 8*j + 2*tig;
        float s0 = 0.f, q0 = 0.f, s1 = 0.f, q1 = 0.f;
#pragma unroll
        for (int m = 0; m < 2; m++) {
            const int oy = gy + py + 4*m;
            const size_t row = (size_t)oy * 512 + gx + pxb;
            float v0 = acc[m][j][0], v1 = acc[m][j][1], v2 = acc[m][j][2], v3 = acc[m][j][3];
            ob[(size_t)(n0  ) * HW + row + gid    ] = v0;
            ob[(size_t)(n0+1) * HW + row + gid    ] = v1;
            ob[(size_t)(n0  ) * HW + row + gid + 8] = v2;
            ob[(size_t)(n0+1) * HW + row + gid + 8] = v3;
            s0 += v0 + v2; q0 += v0*v0 + v2*v2;
            s1 += v1 + v3; q1 += v1*v1 + v3*v3;
        }
#pragma unroll
        for (int o = 16; o >= 4; o >>= 1) {
            s0 += __shfl_down_sync(0xFFFFFFFFu, s0, o);
            q0 += __shfl_down_sync(0xFFFFFFFFu, q0, o);
            s1 += __shfl_down_sync(0xFFFFFFFFu, s1, o);
            q1 += __shfl_down_sync(0xFFFFFFFFu, q1, o);
        }
        if (gid == 0) {
            atomicAdd(&sstat[2*n0    ], s0);
            atomicAdd(&sstat[2*n0 + 1], q0);
            atomicAdd(&sstat[2*n0 + 2], s1);
            atomicAdd(&sstat[2*n0 + 3], q1);
        }
    }
    __syncthreads();
    if (tid < 64) atomicAdd(&statsOut[tid], sstat[tid]);
}

// ------- conv_mma2: gates kernel — 2 gate slices per block share A fragments -----------------
// blockIdx.z in {0,1} -> gates (2z, 2z+1). Weights staged 16 cins x 2 gates at a time.
// Per k-step: 8 A-LDS + 4 B-LDS.128 for 16 MMAs (1.5 crossbar-cyc/MMA).
__global__ void __launch_bounds__(256, 2)
conv_mma2(const float* __restrict__ inA, const float* __restrict__ inB,
          const float2* __restrict__ prmB,
          const float* __restrict__ wt, float* __restrict__ out, float* __restrict__ statsOut)
{
    constexpr int CIN = 64, NG = 8;
    constexpr int PS = 360, WS = 296, TEL = 340;
    constexpr int NEL = 8 * TEL;
    constexpr int NSLOT = (NEL + 255) / 256; // 11
    constexpr int TB = 8 * PS;
    extern __shared__ float smem[];
    float* wsh  = smem;                      // 2 gates * 16 cins * WS
    float* tile = smem + 2*16*WS;            // 2 * TB
    __shared__ float2 spar[CIN];
    __shared__ float sstat[128];

    const int tid  = threadIdx.x;
    const int warp = tid >> 5, lane = tid & 31;
    const int gid  = lane >> 2, tig = lane & 3;
    if (tid < 128) sstat[tid] = 0.f;
    if (tid < CIN) {
        spar[tid] = (tid < 32) ? make_float2(1.f, 0.f) : __ldg(&prmB[tid - 32]);
    }

    const int gx = blockIdx.x * 32, gy = blockIdx.y * 8;
    const int zb = blockIdx.z;               // gate pair
    const float* wsrc = wt + (size_t)(2*zb) * (64*9*32);
    const unsigned wsh_s = (unsigned)__cvta_generic_to_shared(wsh);

    float acc[2][2][4][4];                   // [gate][m][j][e]
#pragma unroll
    for (int zz = 0; zz < 2; zz++)
#pragma unroll
        for (int m = 0; m < 2; m++)
#pragma unroll
            for (int j = 0; j < 4; j++)
#pragma unroll
                for (int e = 0; e < 4; e++) acc[zz][m][j][e] = 0.f;

    auto stage_w = [&](int s) {              // cins [16s, 16s+16) for both gates
        for (int i = tid; i < 2*16*72; i += 256) {
            int zz = i / (16*72), rem = i % (16*72);
            int cin = rem / 72, off = rem % 72;
            cp_async16(wsh_s + ((zz*16 + cin)*WS + off*4)*4,
                       wsrc + (size_t)zz*(64*9*32) + (16*s + cin)*288 + off*4);
        }
        cp_commit();
    };
    stage_w(0);

    const int nslot = (tid < (NEL & 255)) ? NSLOT : NSLOT - 1;
    int so_[NSLOT];
    int go_[NSLOT];
#pragma unroll
    for (int j = 0; j < NSLOT; j++) {
        int i = tid + j*256;
        if (j < nslot) {
            int pl = i / TEL, rem = i % TEL;
            int r = rem / 34, c = rem % 34;
            int iy = gy - 1 + r, ix = gx - 1 + c;
            so_[j] = pl*PS + r*34 + c;
            bool ib = iy >= 0 && iy < 512 && ix >= 0 && ix < 512;
            go_[j] = ib ? (pl*HW + iy*512 + ix) : -1;
        }
    }

    float vreg[NSLOT];
    auto loadg = [&](int g) {
        int cin0 = g*8;
        const float* bp = (cin0 < 32) ? (inA + (size_t)cin0 * HW)
                                      : (inB + (size_t)(cin0 - 32) * HW);
#pragma unroll
        for (int j = 0; j < NSLOT; j++)
            if (j < nslot) vreg[j] = (go_[j] >= 0) ? __ldg(bp + go_[j]) : 0.f;
    };

    auto stores = [&](int g, int buf) {
        int cin0 = g*8;
        unsigned* tb = (unsigned*)(tile + buf * TB);
#pragma unroll
        for (int j = 0; j < NSLOT; j++) {
            if (j < nslot) {
                int g0 = go_[j];
                int pl = (g0 >= 0 ? g0 : 0) >> 18;
                float2 p = spar[cin0 + pl];
                float v = (g0 >= 0) ? (vreg[j] * p.x + p.y) : 0.f;
                tb[so_[j]] = to_tf32(v);
            }
        }
    };

    auto compute = [&](int g, int buf) {
        const unsigned* tb = (const unsigned*)(tile + buf * TB);
        const int gl = (g & 1) * 8;          // local cin offset within stage
        const unsigned* wb0 = (const unsigned*)wsh + gl*WS;
        const unsigned* wb1 = (const unsigned*)wsh + (16 + gl)*WS;
        const int py = warp >> 1, pxb = (warp & 1) * 16;
#pragma unroll
        for (int ky = 0; ky < 3; ky++) {
#pragma unroll
            for (int kx = 0; kx < 3; kx++) {
                int ro0 = (py     + ky) * 34 + pxb + kx;
                int ro1 = (py + 4 + ky) * 34 + pxb + kx;
                unsigned a0 = tb[ tig    * PS + ro0 + gid    ];
                unsigned a1 = tb[ tig    * PS + ro0 + gid + 8];
                unsigned a2 = tb[(tig+4) * PS + ro0 + gid    ];
                unsigned a3 = tb[(tig+4) * PS + ro0 + gid + 8];
                unsigned c0 = tb[ tig    * PS + ro1 + gid    ];
                unsigned c1 = tb[ tig    * PS + ro1 + gid + 8];
                unsigned c2 = tb[(tig+4) * PS + ro1 + gid    ];
                unsigned c3 = tb[(tig+4) * PS + ro1 + gid + 8];
                uint4 p0 = *(const uint4*)(wb0 + tig    *WS + (ky*3+kx)*32 + gid*4);
                uint4 p4 = *(const uint4*)(wb0 + (tig+4)*WS + (ky*3+kx)*32 + gid*4);
                uint4 q0 = *(const uint4*)(wb1 + tig    *WS + (ky*3+kx)*32 + gid*4);
                uint4 q4 = *(const uint4*)(wb1 + (tig+4)*WS + (ky*3+kx)*32 + gid*4);
                mma_tf32(acc[0][0][0], a0, a1, a2, a3, p0.x, p4.x);
                mma_tf32(acc[0][0][1], a0, a1, a2, a3, p0.y, p4.y);
                mma_tf32(acc[0][0][2], a0, a1, a2, a3, p0.z, p4.z);
                mma_tf32(acc[0][0][3], a0, a1, a2, a3, p0.w, p4.w);
                mma_tf32(acc[0][1][0], c0, c1, c2, c3, p0.x, p4.x);
                mma_tf32(acc[0][1][1], c0, c1, c2, c3, p0.y, p4.y);
                mma_tf32(acc[0][1][2], c0, c1, c2, c3, p0.z, p4.z);
                mma_tf32(acc[0][1][3], c0, c1, c2, c3, p0.w, p4.w);
                mma_tf32(acc[1][0][0], a0, a1, a2, a3, q0.x, q4.x);
                mma_tf32(acc[1][0][1], a0, a1, a2, a3, q0.y, q4.y);
                mma_tf32(acc[1][0][2], a0, a1, a2, a3, q0.z, q4.z);
                mma_tf32(acc[1][0][3], a0, a1, a2, a3, q0.w, q4.w);
                mma_tf32(acc[1][1][0], c0, c1, c2, c3, q0.x, q4.x);
                mma_tf32(acc[1][1][1], c0, c1, c2, c3, q0.y, q4.y);
                mma_tf32(acc[1][1][2], c0, c1, c2, c3, q0.z, q4.z);
                mma_tf32(acc[1][1][3], c0, c1, c2, c3, q0.w, q4.w);
            }
        }
    };

    loadg(0);
    cp_wait<0>();
    __syncthreads();
    stores(0, 0);
    for (int g = 0; g < NG; ++g) {
        __syncthreads();   // tile(g) visible; prior readers of other buffer + wsh done
        if (g > 0 && (g & 1) == 0) {
            stage_w(g >> 1);
            if (g + 1 < NG) loadg(g + 1);
            cp_wait<0>();
            __syncthreads();
        } else {
            if (g + 1 < NG) loadg(g + 1);
        }
        compute(g, g & 1);
        if (g + 1 < NG) stores(g + 1, (g + 1) & 1);
    }

    // ---- epilogue: store + fused stats for both gates ----
    const int py = warp >> 1, pxb = (warp & 1) * 16;
#pragma unroll
    for (int zz = 0; zz < 2; zz++) {
        float* ob = out + (size_t)(2*zb + zz) * 32 * HW;
#pragma unroll
        for (int j = 0; j < 4; j++) {
            int n0 = 8*j + 2*tig;
            float s0 = 0.f, q0 = 0.f, s1 = 0.f, q1 = 0.f;
#pragma unroll
            for (int m = 0; m < 2; m++) {
                const int oy = gy + py + 4*m;
                const size_t row = (size_t)oy * 512 + gx + pxb;
                float v0 = acc[zz][m][j][0], v1 = acc[zz][m][j][1];
                float v2 = acc[zz][m][j][2], v3 = acc[zz][m][j][3];
                ob[(size_t)(n0  ) * HW + row + gid    ] = v0;
                ob[(size_t)(n0+1) * HW + row + gid    ] = v1;
                ob[(size_t)(n0  ) * HW + row + gid + 8] = v2;
                ob[(size_t)(n0+1) * HW + row + gid + 8] = v3;
                s0 += v0 + v2; q0 += v0*v0 + v2*v2;
                s1 += v1 + v3; q1 += v1*v1 + v3*v3;
            }
#pragma unroll
            for (int o = 16; o >= 4; o >>= 1) {
                s0 += __shfl_down_sync(0xFFFFFFFFu, s0, o);
                q0 += __shfl_down_sync(0xFFFFFFFFu, q0, o);
                s1 += __shfl_down_sync(0xFFFFFFFFu, s1, o);
                q1 += __shfl_down_sync(0xFFFFFFFFu, q1, o);
            }
            if (gid == 0) {
                atomicAdd(&sstat[zz*64 + 2*n0    ], s0);
                atomicAdd(&sstat[zz*64 + 2*n0 + 1], q0);
                atomicAdd(&sstat[zz*64 + 2*n0 + 2], s1);
                atomicAdd(&sstat[zz*64 + 2*n0 + 3], q1);
            }
        }
    }
    __syncthreads();
    if (tid < 128) {
        int zz = tid >> 6;
        atomicAdd(&statsOut[(2*zb + zz)*64 + (tid & 63)], sstat[tid]);
    }
}

// ---------------- 3x3 conv v8 (e1, r2) --------------------------------------------------------
template<int CIN, int COUT, int CHUNK>
__global__ void __launch_bounds__(256, 4)
conv3x3_v8(const float* __restrict__ inA, const float* __restrict__ inB, int csplit,
           const float2* __restrict__ prmA, const float2* __restrict__ prmB,
           int reluA, int reluB,
           const float* __restrict__ wt, float* __restrict__ out, float* __restrict__ statsOut,
           int H, int W, int pad, int HO, int WO)
{
    constexpr int TW = 32, TPW = 36, TPH = 10;
    constexpr int TSZ = TPW * TPH;
    constexpr int NCH = CIN / CHUNK;
    constexpr int WCH = CHUNK * 9 * COUT;
    constexpr int COUTG = COUT / 2;
    constexpr int C2G = COUTG / 2;
    constexpr int C2  = COUT / 2;
    extern __shared__ float smem[];
    float* ws   = smem;
    float* tile = smem + 2*WCH;
    __shared__ float sstat[2*COUT];

    const int tid   = threadIdx.x;
    const int group = tid >> 7;
    const int tx    = tid & 15;
    const int ty    = (tid >> 4) & 7;
    if (tid < 2*COUT) sstat[tid] = 0.f;

    const int gx = blockIdx.x * TW, gy = blockIdx.y * 8;
    const int oy = gy + ty;
    const int ox0 = gx + tx, ox1 = ox0 + 16;
    const float* wsrc = wt + (size_t)blockIdx.z * (CIN*9*COUT);

    const unsigned ws_s   = (unsigned)__cvta_generic_to_shared(ws);
    const unsigned tile_s = (unsigned)__cvta_generic_to_shared(tile);
    const bool needT = (prmA != nullptr && csplit > 0) || (prmB != nullptr && csplit < CIN);

    u64 accA[C2G], accB[C2G];
#pragma unroll
    for (int p = 0; p < C2G; p++) { accA[p] = 0ull; accB[p] = 0ull; }

    auto prefetch = [&](int ci, int buf) {
        const float* wc = wsrc + (size_t)ci * WCH;
        unsigned wd = ws_s + buf * WCH * 4;
        for (int i = tid; i < WCH/4; i += 256)
            cp_async16(wd + i*16, wc + i*4);
        unsigned td = tile_s + buf * CHUNK*TSZ*4;
        for (int cc = 0; cc < CHUNK; ++cc) {
            int cin = ci*CHUNK + cc;
            bool isA = cin < csplit;
            const float* ip = isA ? (inA + (size_t)cin * H * W)
                                  : (inB + (size_t)(cin - csplit) * H * W);
            for (int i = tid; i < TSZ; i += 256) {
                int r = i / TPW, c = i % TPW;
                int iy = gy - pad + r, ix = gx - pad + c;
                bool inb = (c < TW+2) && iy >= 0 && iy < H && ix >= 0 && ix < W;
                cp_async4(td + (cc*TSZ + i)*4, inb ? (ip + (size_t)iy*W + ix) : ip, inb);
            }
        }
        cp_commit();
    };

    auto transform = [&](int ci, int buf) {
        float* tb = tile + buf * CHUNK*TSZ;
        for (int i = tid; i < CHUNK*TSZ; i += 256) {
            int cc = i / TSZ, e = i % TSZ;
            int cin = ci*CHUNK + cc;
            bool isA = cin < csplit;
            const float2* prm = isA ? prmA : prmB;
            if (!prm) continue;
            int rl = isA ? reluA : reluB;
            int r = e / TPW, c = e % TPW;
            int iy = gy - pad + r, ix = gx - pad + c;
            bool inb = (c < TW+2) && iy >= 0 && iy < H && ix >= 0 && ix < W;
            float2 p = __ldg(&prm[isA ? cin : (cin - csplit)]);
            float v = inb ? (tb[i] * p.x + p.y) : 0.f;
            if (rl) v = fmaxf(v, 0.f);
            tb[i] = v;
        }
    };

    auto compute = [&](int buf) {
        const float* tb0 = tile + buf * CHUNK*TSZ + ty * TPW + tx;
        const float* wsb = ws + buf * WCH;
#pragma unroll
        for (int cc = 0; cc < CHUNK; ++cc) {
            const float* tb = tb0 + cc * TSZ;
            const u64* wrow = (const u64*)(wsb + cc * 9 * COUT) + group * C2G;
#pragma unroll
            for (int ky = 0; ky < 3; ky++) {
#pragma unroll
                for (int kx = 0; kx < 3; kx++) {
                    u64 va = pack2(tb[ky*TPW + kx]);
                    u64 vb = pack2(tb[ky*TPW + kx + 16]);
                    if constexpr (C2G >= 2) {
                        const ulonglong2* w4 = (const ulonglong2*)(wrow + (ky*3+kx) * C2);
#pragma unroll
                        for (int p2 = 0; p2 < C2G/2; p2++) {
                            ulonglong2 w = w4[p2];
                            accA[2*p2  ] = ffma2(va, w.x, accA[2*p2  ]);
                            accB[2*p2  ] = ffma2(vb, w.x, accB[2*p2  ]);
                            accA[2*p2+1] = ffma2(va, w.y, accA[2*p2+1]);
                            accB[2*p2+1] = ffma2(vb, w.y, accB[2*p2+1]);
                        }
                    } else {
                        u64 w = wrow[(ky*3+kx) * C2];
                        accA[0] = ffma2(va, w, accA[0]);
                        accB[0] = ffma2(vb, w, accB[0]);
                    }
                }
            }
        }
    };

    prefetch(0, 0);
    for (int ci = 0; ci < NCH; ++ci) {
        int cur = ci & 1;
        if (ci + 1 < NCH) {
            prefetch(ci + 1, 1 - cur);
            cp_wait<1>();
        } else {
            cp_wait<0>();
        }
        __syncthreads();
        if (needT) { transform(ci, cur); __syncthreads(); }
        compute(cur);
        __syncthreads();
    }

    float* ob = out + (size_t)blockIdx.z * COUT * HO * WO;
    float* so = statsOut + blockIdx.z * 2 * COUT;
    const bool vA = (oy < HO) && (ox0 < WO);
    const bool vB = (oy < HO) && (ox1 < WO);
    const size_t row = (size_t)oy * WO;
#pragma unroll
    for (int p = 0; p < C2G; p++) {
        int c0 = group * COUTG + 2*p;
        float a0, a1, b0, b1;
        unpack2(accA[p], a0, a1);
        unpack2(accB[p], b0, b1);
        if (vA) {
            ob[(size_t)(c0  ) * HO * WO + row + ox0] = a0;
            ob[(size_t)(c0+1) * HO * WO + row + ox0] = a1;
        }
        if (vB) {
            ob[(size_t)(c0  ) * HO * WO + row + ox1] = b0;
            ob[(size_t)(c0+1) * HO * WO + row + ox1] = b1;
        }
        float s0 = (vA ? a0 : 0.f) + (vB ? b0 : 0.f);
        float q0 = (vA ? a0*a0 : 0.f) + (vB ? b0*b0 : 0.f);
        float s1 = (vA ? a1 : 0.f) + (vB ? b1 : 0.f);
        float q1 = (vA ? a1*a1 : 0.f) + (vB ? b1*b1 : 0.f);
#pragma unroll
        for (int o = 16; o; o >>= 1) {
            s0 += __shfl_down_sync(0xFFFFFFFFu, s0, o);
            q0 += __shfl_down_sync(0xFFFFFFFFu, q0, o);
            s1 += __shfl_down_sync(0xFFFFFFFFu, s1, o);
            q1 += __shfl_down_sync(0xFFFFFFFFu, q1, o);
        }
        if ((tid & 31) == 0) {
            atomicAdd(&sstat[2*c0  ], s0);
            atomicAdd(&sstat[2*c0+1], q0);
            atomicAdd(&sstat[2*c0+2], s1);
            atomicAdd(&sstat[2*c0+3], q1);
        }
    }
    __syncthreads();
    if (tid < 2*COUT) atomicAdd(&so[tid], sstat[tid]);
}

// ---------------- LSTM elementwise ----------------
__global__ void lstm_kernel(const float* __restrict__ prev_c, const float2* __restrict__ prm,
                            float* __restrict__ out_c, float* __restrict__ out_h)
{
    int idx = blockIdx.x * 256 + threadIdx.x;   // over 32*HW
    int c = idx >> 18;                          // HW = 2^18
    const int CHW = 32 * HW;

    float g[4];
#pragma unroll
    for (int gi = 0; gi < 4; gi++) {
        float2 p = prm[gi*32 + c];
        g[gi] = g_graw[(size_t)gi * CHW + idx] * p.x + p.y;
    }
    float f  = sigmoidf_(g[0]);
    float it = sigmoidf_(g[1]);
    float ct = tanhf(g[2]);
    float ot = sigmoidf_(g[3]);
    float nc = prev_c[idx] * f + it * ct;
    out_c[idx] = nc;
    out_h[idx] = tanhf(nc) * ot;
}

// ---------------- patch gather + per-channel dot ----------------
__global__ void gather_kernel(const int* __restrict__ holes,
                              const float* __restrict__ woil, const float* __restrict__ boil,
                              const float* __restrict__ wwat, const float* __restrict__ bwat,
                              const float* __restrict__ wgas, const float* __restrict__ bgas,
                              const float2* __restrict__ prm,
                              float* __restrict__ res)
{
    int nidx = threadIdx.x;
    if (nidx >= 256) return;
    int hx = holes[2*nidx], hy = holes[2*nidx+1];
    const float* wv[3] = { woil, wwat, wgas };
    float bv[3] = { boil[0], bwat[0], bgas[0] };
    for (int c = 0; c < 3; c++) {
        float2 p = prm[c];
        float s = bv[c];
        for (int i = 0; i < 3; i++)
            for (int j = 0; j < 3; j++) {
                float v = g_r2raw[(size_t)c * HW2 + (size_t)(hx + 3 + i) * HOB + (hy + 3 + j)];
                s += wv[c][i*3+j] * (v * p.x + p.y);
            }
        res[nidx*3 + c] = s;
    }
}

// ---------------- launch ----------------
extern "C" void kernel_launch(void* const* d_in, const int* in_sizes, int n_in,
                              void* d_out, int out_size)
{
    const float* x      = (const float*)d_in[0];
    const float* prev_c = (const float*)d_in[1];
    const float* prev_h = (const float*)d_in[2];
    const int*   holes  = (const int*)d_in[3];
    const float* w_e1   = (const float*)d_in[4];
    const float* w_e2   = (const float*)d_in[5];
    const float* w_f    = (const float*)d_in[6];
    const float* w_i    = (const float*)d_in[7];
    const float* w_c    = (const float*)d_in[8];
    const float* w_o    = (const float*)d_in[9];
    const float* w_r1   = (const float*)d_in[10];
    const float* w_r2   = (const float*)d_in[11];
    const float* w_oil  = (const float*)d_in[12];
    const float* b_oil  = (const float*)d_in[13];
    const float* w_wat  = (const float*)d_in[14];
    const float* b_wat  = (const float*)d_in[15];
    const float* w_gas  = (const float*)d_in[16];
    const float* b_gas  = (const float*)d_in[17];
    float* out = (float*)d_out;

    float *t1raw, *t2raw, *graw, *r1raw, *r2raw;
    float *wt_e1, *wt_e2, *wt_g, *wt_r1, *wt_r2, *stats;
    float2 *params;
    cudaGetSymbolAddress((void**)&t1raw, g_t1raw);
    cudaGetSymbolAddress((void**)&t2raw, g_t2raw);
    cudaGetSymbolAddress((void**)&graw,  g_graw);
    cudaGetSymbolAddress((void**)&r1raw, g_r1raw);
    cudaGetSymbolAddress((void**)&r2raw, g_r2raw);
    cudaGetSymbolAddress((void**)&wt_e1, g_wt_e1);
    cudaGetSymbolAddress((void**)&wt_e2, g_wt_e2);
    cudaGetSymbolAddress((void**)&wt_g,  g_wt_g);
    cudaGetSymbolAddress((void**)&wt_r1, g_wt_r1);
    cudaGetSymbolAddress((void**)&wt_r2, g_wt_r2);
    cudaGetSymbolAddress((void**)&stats, g_stats);
    cudaGetSymbolAddress((void**)&params, g_params);

    constexpr int TSZ = 36 * 10;
    const int SM_E1 = (2*4*9*32  + 2*4*TSZ) * 4;    // 20736
    const int SM_R2 = (2*8*9*4   + 2*8*TSZ) * 4;    // 25344
    const int SM_M32 = (32*296 + 2*8*360) * 4;       // 60928
    const int SM_G2  = (2*16*296 + 2*8*360) * 4;     // 60928
    cudaFuncSetAttribute((const void*)conv3x3_v8<4,32,4>,  cudaFuncAttributeMaxDynamicSharedMemorySize, SM_E1);
    cudaFuncSetAttribute((const void*)conv3x3_v8<32,4,8>,  cudaFuncAttributeMaxDynamicSharedMemorySize, SM_R2);
    cudaFuncSetAttribute((const void*)conv_mma<32>,        cudaFuncAttributeMaxDynamicSharedMemorySize, SM_M32);
    cudaFuncSetAttribute((const void*)conv_mma2,           cudaFuncAttributeMaxDynamicSharedMemorySize, SM_G2);

    dim3 thr(256);
    dim3 grid512(512/32, 512/8, 1);        // 16 x 64  (v8)
    dim3 gridM  (512/32, 512/8, 1);        // 16 x 64  (mma, 32x8 tile)
    dim3 gridG2 (512/32, 512/8, 2);        // gate pairs
    dim3 gridR2 ((HOB + 31)/32, (HOB + 7)/8, 1);   // 17 x 65

    // launch order: prep(1), e1(2), mp(3), e2_mma(4), mp(5), gates_mma2(6 = profiled)
    prep_weights<<<(94464 + 255)/256, 256>>>(w_e1, w_e2, w_f, w_i, w_c, w_o, w_r1, w_r2);

    // e1: x (4ch, raw) -> t1raw (+stats)  [fp32 v8]
    conv3x3_v8<4,32,4><<<grid512, thr, SM_E1>>>(x, x, 4, nullptr, nullptr, 0, 0,
                                                wt_e1, t1raw, stats + 0, 512, 512, 1, 512, 512);
    make_params<<<1, 32>>>(stats + 0, params + 0, 32, 1.f / (float)HW);

    // e2: relu(BN(t1raw)) -> t2raw (+stats)  [tf32 mma]
    conv_mma<32><<<gridM, thr, SM_M32>>>(t1raw, t1raw, 32, params + 0, params + 0, 1, 1,
                                         wt_e2, t2raw, stats + 64);
    make_params<<<1, 32>>>(stats + 64, params + 32, 32, 1.f / (float)HW);

    // gates: [prev_h (raw) ; BN(t2raw)] -> graw (+stats)  [tf32 mma2, profiled launch]
    conv_mma2<<<gridG2, thr, SM_G2>>>(prev_h, t2raw, params + 32, wt_g, graw, stats + 128);
    make_params<<<1, 128>>>(stats + 128, params + 64, 128, 1.f / (float)HW);

    // LSTM -> out[0:32HW]=next_c, out[32HW:64HW]=next_h
    lstm_kernel<<<32*HW/256, 256>>>(prev_c, params + 64, out, out + 32*HW);

    // r1: next_h (raw) -> r1raw (+stats)  [tf32 mma]
    conv_mma<32><<<gridM, thr, SM_M32>>>(out + 32*HW, out + 32*HW, 32, nullptr, nullptr, 0, 0,
                                         wt_r1, r1raw, stats + 384);
    make_params<<<1, 32>>>(stats + 384, params + 192, 32, 1.f / (float)HW);

    // r2: relu(BN(r1raw)) -> r2raw (3+1 ch @ 518x518, pad 4) (+stats)  [fp32 v8]
    conv3x3_v8<32,4,8><<<gridR2, thr, SM_R2>>>(r1raw, r1raw, 32, params + 192, params + 192, 1, 1,
                                               wt_r2, r2raw, stats + 448, 512, 512, 4, HOB, HOB);
    make_params<<<1, 32>>>(stats + 448, params + 224, 4, 1.f / (float)HW2);

    // gather + dot -> out tail
    gather_kernel<<<1, 256>>>(holes, w_oil, b_oil, w_wat, b_wat, w_gas, b_gas, params + 224, out + 64*HW);
}